// round 5
// baseline (speedup 1.0000x reference)
#include <cuda_runtime.h>
#include <cstdint>
#include <math.h>

// Problem dims
#define BATCH 8
#define SQL   2048
#define SKL   2048
#define DIM   1024

#define NELEM ((size_t)BATCH * SQL * DIM)      // 16.8M floats = 64MB

// ---------------- device scratch (static) ----------------
__device__ float g_qh[NELEM],  g_ql[NELEM];
__device__ float g_kh[NELEM],  g_kl[NELEM];
__device__ float g_vh[NELEM],  g_vl[NELEM];
__device__ float g_Wqh[DIM*DIM], g_Wql[DIM*DIM];
__device__ float g_Wkh[DIM*DIM], g_Wkl[DIM*DIM];
__device__ float g_Wvh[DIM*DIM], g_Wvl[DIM*DIM];
__device__ float g_Qph[NELEM], g_Qpl[NELEM];
__device__ float g_Kph[NELEM], g_Kpl[NELEM];
__device__ float g_Vph[NELEM], g_Vpl[NELEM];     // [B*SK][DV]
__device__ float g_S[(size_t)BATCH * SQL * SKL]; // scores, then P (tf32-rounded)
__device__ float g_maskf[BATCH * SKL];
__device__ int   g_mask_mode;

// ---------------- small helpers ----------------
__device__ __forceinline__ uint32_t smem_u32(const void* p) {
    uint32_t a;
    asm("{ .reg .u64 t; cvta.to.shared.u64 t, %1; cvt.u32.u64 %0, t; }" : "=r"(a) : "l"(p));
    return a;
}
__device__ __forceinline__ float tf32_rna(float x) {
    uint32_t u;
    asm("cvt.rna.tf32.f32 %0, %1;" : "=r"(u) : "f"(x));
    return __uint_as_float(u);
}
__device__ __forceinline__ void cp16(uint32_t dst, const void* src) {
    asm volatile("cp.async.cg.shared.global [%0], [%1], 16;" :: "r"(dst), "l"(src) : "memory");
}
__device__ __forceinline__ void cp_commit() {
    asm volatile("cp.async.commit_group;" ::: "memory");
}
template<int N> __device__ __forceinline__ void cp_wait() {
    asm volatile("cp.async.wait_group %0;" :: "n"(N) : "memory");
}
// mma.sync m16n8k8 tf32 (base PTX)
__device__ __forceinline__ void mma8(float* c, const uint32_t* a, const uint32_t* b) {
    asm volatile(
        "mma.sync.aligned.m16n8k8.row.col.f32.tf32.tf32.f32 "
        "{%0,%1,%2,%3}, {%4,%5,%6,%7}, {%8,%9}, {%0,%1,%2,%3};"
        : "+f"(c[0]), "+f"(c[1]), "+f"(c[2]), "+f"(c[3])
        : "r"(a[0]), "r"(a[1]), "r"(a[2]), "r"(a[3]), "r"(b[0]), "r"(b[1]));
}
// ldmatrix x4 (b16 view of tf32 data): 4 regs per thread
__device__ __forceinline__ void ldsm4(uint32_t* r, uint32_t addr) {
    asm volatile("ldmatrix.sync.aligned.m8n8.x4.shared.b16 {%0,%1,%2,%3}, [%4];"
                 : "=r"(r[0]), "=r"(r[1]), "=r"(r[2]), "=r"(r[3]) : "r"(addr));
}
// scalar swizzled load (mode-3 B only)
__device__ __forceinline__ uint32_t sw_ld(const float* t, int r, int k) {
    return __float_as_uint(t[r * 32 + ((((k >> 2) ^ r) & 7) << 2) + (k & 3)]);
}

// ---------------- mask dtype sniffing (verified R1) ----------------
__global__ void detect_mask_kernel(const unsigned int* __restrict__ w)
{
    __shared__ unsigned int f;
    if (threadIdx.x == 0) f = 0u;
    __syncthreads();
    unsigned int loc = 0u;
    for (int i = threadIdx.x; i < 4096; i += 256) {
        unsigned int x = w[i];
        if (x == 0x3F803F80u || x == 0x00003F80u) loc |= 8u;
        if (x == 0x3F800000u)                     loc |= 4u;
        if (x > 1u)                               loc |= 2u;
    }
    atomicOr(&f, loc);
    __syncthreads();
    if (threadIdx.x == 0) {
        unsigned int ff = f;
        g_mask_mode = (ff & 8u) ? 3 : (ff & 4u) ? 2 : (ff & 2u) ? 1 : 0;
    }
}
__global__ void convert_mask_kernel(const void* __restrict__ m, int n)
{
    int i = blockIdx.x * blockDim.x + threadIdx.x;
    if (i >= n) return;
    int mode = g_mask_mode;
    float v;
    if (mode == 0)      v = (float)((const int*)m)[i];
    else if (mode == 1) v = (float)((const unsigned char*)m)[i];
    else if (mode == 2) v = ((const float*)m)[i];
    else {
        unsigned short h = ((const unsigned short*)m)[i];
        v = __uint_as_float(((unsigned int)h) << 16);
    }
    g_maskf[i] = v;
}

// ---------------- tf32 hi/lo splits ----------------
__global__ __launch_bounds__(256)
void split_kernel(const float4* __restrict__ src, float4* __restrict__ hi,
                  float4* __restrict__ lo, int n4)
{
    int i = blockIdx.x * blockDim.x + threadIdx.x;
    if (i >= n4) return;
    float4 x = src[i];
    float4 h, l;
    h.x = tf32_rna(x.x); l.x = x.x - h.x;
    h.y = tf32_rna(x.y); l.y = x.y - h.y;
    h.z = tf32_rna(x.z); l.z = x.z - h.z;
    h.w = tf32_rna(x.w); l.w = x.w - h.w;
    hi[i] = h; lo[i] = l;
}

// W [K=1024, N=1024] -> WT_hi/lo [N, K]
__global__ __launch_bounds__(256)
void transpose_split_kernel(const float* __restrict__ W,
                            float* __restrict__ Th, float* __restrict__ Tl)
{
    __shared__ float t[32][33];
    int n0 = blockIdx.x * 32, k0 = blockIdx.y * 32;
    int tx = threadIdx.x & 31, ty = threadIdx.x >> 5;
    for (int r = ty; r < 32; r += 8)
        t[r][tx] = W[(size_t)(k0 + r) * DIM + n0 + tx];
    __syncthreads();
    for (int r = ty; r < 32; r += 8) {
        float x = t[tx][r];
        float h = tf32_rna(x);
        size_t o = (size_t)(n0 + r) * DIM + k0 + tx;
        Th[o] = h; Tl[o] = x - h;
    }
}

// ---------------- mma.sync tf32 GEMM: 128x128 tile, Kc=32, 3-stage cp.async --------
// MODE 0: C = A@B^T + bias      -> split hi/lo write     (Q/K projection)
// MODE 1: C = tanh(A@B^T+bias)  -> split hi/lo write     (V projection)
// MODE 2: C = A@B^T + mask      -> f32 write             (QK^T)
// MODE 3: C = A@B  (B=[K][N])   -> f32 write             (P@V, 2-product)
#define STG0_FL 16384
#define STG3_FL (4096 + 2*32*136)

template<int MODE>
__global__ __launch_bounds__(256, 1)
void mma_gemm(const float* __restrict__ Ah, const float* __restrict__ Al,
              const float* __restrict__ Bh, const float* __restrict__ Bl,
              const float* __restrict__ aux,
              float* __restrict__ out0, float* __restrict__ out1,
              int ldA, int ldB, long long sAz, long long sBz,
              int nK, int ldO, long long sOz)
{
    constexpr bool SA = (MODE != 3);
    constexpr bool BK = (MODE == 3);
    constexpr int  STG = SA ? STG0_FL : STG3_FL;

    extern __shared__ float sm[];
    const uint32_t sb = smem_u32(sm);
    const int tid = threadIdx.x;
    const int lid = tid & 31, wid = tid >> 5;
    const int wm = wid >> 2, wn = wid & 3;      // 2 x 4 warp grid
    const int lx = lid & 3,  ly = lid >> 2;
    const int m0 = blockIdx.y * 128, n0 = blockIdx.x * 128, z = blockIdx.z;
    const int nst = nK / 32;

    const float* Agh = Ah + (size_t)z * sAz;
    const float* Agl = SA ? (Al + (size_t)z * sAz) : Ah;
    const float* Bgh = Bh + (size_t)z * sBz;
    const float* Bgl = Bl + (size_t)z * sBz;

    // ldmatrix per-thread row geometry (rows within the 128-row tile)
    const int lane8 = lid & 7;
    const int hi8   = (lid >> 3) & 1;
    const int cadd  = lid >> 4;                 // chunk offset 0/1
    int raM[4], ra7[4];                         // A fragment rows per mt
#pragma unroll
    for (int mt = 0; mt < 4; mt++) {
        int r = wm * 64 + mt * 16 + hi8 * 8 + lane8;
        raM[mt] = r * 128; ra7[mt] = r & 7;
    }
    int rbM[2], rb7[2];                         // B fragment rows per nt-pair
#pragma unroll
    for (int p = 0; p < 2; p++) {
        int r = wn * 32 + p * 16 + hi8 * 8 + lane8;
        rbM[p] = r * 128; rb7[p] = r & 7;
    }

    float acc[4][4][4];
#pragma unroll
    for (int a = 0; a < 4; a++)
#pragma unroll
        for (int b = 0; b < 4; b++)
#pragma unroll
            for (int c = 0; c < 4; c++) acc[a][b][c] = 0.f;

    // ---- producer: fills stage SLOT st (0..2) with k-chunk kt ----
    auto issue = [&](int st, int kt) {
        uint32_t base = sb + (uint32_t)st * STG * 4;
#pragma unroll
        for (int i = 0; i < 4; i++) {
            int q = i * 256 + tid; int r = q >> 3, c = q & 7;
            uint32_t d = (uint32_t)(r * 128 + ((c ^ (r & 7)) << 4));
            cp16(base + d, Agh + (size_t)(m0 + r) * ldA + kt + c * 4);
            if (SA) cp16(base + 4096 * 4 + d, Agl + (size_t)(m0 + r) * ldA + kt + c * 4);
        }
        uint32_t bb = base + (SA ? 8192u * 4 : 4096u * 4);
        if (!BK) {
#pragma unroll
            for (int i = 0; i < 4; i++) {
                int q = i * 256 + tid; int r = q >> 3, c = q & 7;
                uint32_t d = (uint32_t)(r * 128 + ((c ^ (r & 7)) << 4));
                cp16(bb + d,            Bgh + (size_t)(n0 + r) * ldB + kt + c * 4);
                cp16(bb + 4096 * 4 + d, Bgl + (size_t)(n0 + r) * ldB + kt + c * 4);
            }
        } else {
#pragma unroll
            for (int i = 0; i < 4; i++) {
                int q = i * 256 + tid; int r = q >> 5, c = q & 31;
                uint32_t d = (uint32_t)(r * 544 + c * 16);
                cp16(bb + d,            Bgh + (size_t)(kt + r) * ldB + n0 + c * 4);
                cp16(bb + 4352 * 4 + d, Bgl + (size_t)(kt + r) * ldB + n0 + c * 4);
            }
        }
        cp_commit();
    };

    issue(0, 0); issue(1, 32); issue(2, 64);

#pragma unroll 1
    for (int it = 0; it < nst; it++) {
        if (it + 2 < nst)      cp_wait<2>();
        else if (it + 1 < nst) cp_wait<1>();
        else                   cp_wait<0>();
        __syncthreads();
        const uint32_t sbase = sb + (uint32_t)(it % 3) * STG * 4;
        const uint32_t aAh = sbase;
        const uint32_t aAl = sbase + 4096 * 4;
        const uint32_t aBh = sbase + (SA ? 8192u : 4096u) * 4;
        const float*   S0  = sm + (it % 3) * STG;
        const float*   SBh3 = S0 + 4096;               // mode-3 B hi
        const float*   SBl3 = SBh3 + 4352;             // mode-3 B lo

#pragma unroll
        for (int ks = 0; ks < 4; ks++) {
            const int chunk = 2 * ks + cadd;
            uint32_t ah[4][4];
#pragma unroll
            for (int mt = 0; mt < 4; mt++)
                ldsm4(ah[mt], aAh + raM[mt] + (((chunk ^ ra7[mt]) & 7) << 4));

            uint32_t bh[4][2], bl[4][2];
            if (!BK) {
#pragma unroll
                for (int p = 0; p < 2; p++) {
                    uint32_t off = rbM[p] + (((chunk ^ rb7[p]) & 7) << 4);
                    uint32_t t[4];
                    ldsm4(t, aBh + off);
                    bh[2*p][0] = t[0]; bh[2*p+1][0] = t[1];
                    bh[2*p][1] = t[2]; bh[2*p+1][1] = t[3];
                    ldsm4(t, aBh + 4096 * 4 + off);
                    bl[2*p][0] = t[0]; bl[2*p+1][0] = t[1];
                    bl[2*p][1] = t[2]; bl[2*p+1][1] = t[3];
                }
            } else {
                const int k0 = ks * 8;
#pragma unroll
                for (int nt = 0; nt < 4; nt++) {
                    int cn = wn * 32 + nt * 8 + ly;
                    bh[nt][0] = __float_as_uint(SBh3[(k0 + lx) * 136 + cn]);
                    bh[nt][1] = __float_as_uint(SBh3[(k0 + 4 + lx) * 136 + cn]);
                    bl[nt][0] = __float_as_uint(SBl3[(k0 + lx) * 136 + cn]);
                    bl[nt][1] = __float_as_uint(SBl3[(k0 + 4 + lx) * 136 + cn]);
                }
            }
#pragma unroll
            for (int mt = 0; mt < 4; mt++)
#pragma unroll
                for (int nt = 0; nt < 4; nt++) {
                    mma8(acc[mt][nt], ah[mt], bh[nt]);
                    mma8(acc[mt][nt], ah[mt], bl[nt]);
                }
            if (SA) {
                uint32_t alr[4][4];
#pragma unroll
                for (int mt = 0; mt < 4; mt++)
                    ldsm4(alr[mt], aAl + raM[mt] + (((chunk ^ ra7[mt]) & 7) << 4));
#pragma unroll
                for (int mt = 0; mt < 4; mt++)
#pragma unroll
                    for (int nt = 0; nt < 4; nt++)
                        mma8(acc[mt][nt], alr[mt], bh[nt]);
            }
        }
        __syncthreads();
        if (it + 3 < nst) issue(it % 3, (it + 3) * 32);
    }

    // ---- epilogue ----
#pragma unroll
    for (int mt = 0; mt < 4; mt++) {
#pragma unroll
        for (int hf = 0; hf < 2; hf++) {
            const int gm = m0 + wm * 64 + mt * 16 + ly + hf * 8;
#pragma unroll
            for (int nt = 0; nt < 4; nt++) {
                const int col = n0 + wn * 32 + nt * 8 + 2 * lx;
                float c0 = acc[mt][nt][hf * 2 + 0];
                float c1 = acc[mt][nt][hf * 2 + 1];
                if (MODE == 0 || MODE == 1) {
                    float x0 = c0 + aux[col], x1 = c1 + aux[col + 1];
                    if (MODE == 1) { x0 = tanhf(x0); x1 = tanhf(x1); }
                    float h0 = tf32_rna(x0), h1 = tf32_rna(x1);
                    float2* p0 = (float2*)(out0 + (size_t)gm * ldO + col);
                    float2* p1 = (float2*)(out1 + (size_t)gm * ldO + col);
                    *p0 = make_float2(h0, h1);
                    *p1 = make_float2(x0 - h0, x1 - h1);
                } else if (MODE == 2) {
                    float x0 = c0 + aux[(size_t)z * SKL + col];
                    float x1 = c1 + aux[(size_t)z * SKL + col + 1];
                    *(float2*)(out0 + (size_t)z * sOz + (size_t)gm * ldO + col) =
                        make_float2(x0, x1);
                } else {
                    *(float2*)(out0 + (size_t)z * sOz + (size_t)gm * ldO + col) =
                        make_float2(c0, c1);
                }
            }
        }
    }
}

// ---------------- softmax (in place, writes tf32-rounded P) ----------------
__global__ __launch_bounds__(256)
void softmax_rows(float* __restrict__ S)
{
    float* row = S + (size_t)blockIdx.x * SKL;
    const int t = threadIdx.x;
    float v[8];
    float mx = -INFINITY;
#pragma unroll
    for (int i = 0; i < 8; i++) { v[i] = row[t + i * 256]; mx = fmaxf(mx, v[i]); }

    __shared__ float red[256];
    red[t] = mx; __syncthreads();
#pragma unroll
    for (int s = 128; s > 0; s >>= 1) {
        if (t < s) red[t] = fmaxf(red[t], red[t + s]);
        __syncthreads();
    }
    mx = red[0];
    __syncthreads();

    float sum = 0.f;
#pragma unroll
    for (int i = 0; i < 8; i++) { v[i] = __expf(v[i] - mx); sum += v[i]; }
    red[t] = sum; __syncthreads();
#pragma unroll
    for (int s = 128; s > 0; s >>= 1) {
        if (t < s) red[t] += red[t + s];
        __syncthreads();
    }
    const float inv = 1.0f / red[0];
#pragma unroll
    for (int i = 0; i < 8; i++) row[t + i * 256] = tf32_rna(v[i] * inv);
}

// ---------------- launch ----------------
extern "C" void kernel_launch(void* const* d_in, const int* in_sizes, int n_in,
                              void* d_out, int out_size)
{
    const float* q    = (const float*)d_in[0];
    const float* k    = (const float*)d_in[1];
    const float* v    = (const float*)d_in[2];
    const void*  mask = d_in[3];
    const float* Wq   = (const float*)d_in[4];
    const float* bq   = (const float*)d_in[5];
    const float* Wk   = (const float*)d_in[6];
    const float* bk   = (const float*)d_in[7];
    const float* Wv   = (const float*)d_in[8];
    const float* bvp  = (const float*)d_in[9];
    float* out        = (float*)d_out;

    float *qh, *ql, *kh, *kl, *vh, *vl, *Wqh, *Wql, *Wkh, *Wkl, *Wvh, *Wvl;
    float *Qph, *Qpl, *Kph, *Kpl, *Vph, *Vpl, *S, *maskf;
    cudaGetSymbolAddress((void**)&qh, g_qh);   cudaGetSymbolAddress((void**)&ql, g_ql);
    cudaGetSymbolAddress((void**)&kh, g_kh);   cudaGetSymbolAddress((void**)&kl, g_kl);
    cudaGetSymbolAddress((void**)&vh, g_vh);   cudaGetSymbolAddress((void**)&vl, g_vl);
    cudaGetSymbolAddress((void**)&Wqh, g_Wqh); cudaGetSymbolAddress((void**)&Wql, g_Wql);
    cudaGetSymbolAddress((void**)&Wkh, g_Wkh); cudaGetSymbolAddress((void**)&Wkl, g_Wkl);
    cudaGetSymbolAddress((void**)&Wvh, g_Wvh); cudaGetSymbolAddress((void**)&Wvl, g_Wvl);
    cudaGetSymbolAddress((void**)&Qph, g_Qph); cudaGetSymbolAddress((void**)&Qpl, g_Qpl);
    cudaGetSymbolAddress((void**)&Kph, g_Kph); cudaGetSymbolAddress((void**)&Kpl, g_Kpl);
    cudaGetSymbolAddress((void**)&Vph, g_Vph); cudaGetSymbolAddress((void**)&Vpl, g_Vpl);
    cudaGetSymbolAddress((void**)&S, g_S);     cudaGetSymbolAddress((void**)&maskf, g_maskf);

    // mask -> float
    detect_mask_kernel<<<1, 256>>>((const unsigned int*)mask);
    convert_mask_kernel<<<(BATCH * SKL + 255) / 256, 256>>>(mask, BATCH * SKL);

    // split inputs q,k,v into tf32 hi/lo
    {
        int n4 = (int)(NELEM / 4);
        int nb = (n4 + 255) / 256;
        split_kernel<<<nb, 256>>>((const float4*)q, (float4*)qh, (float4*)ql, n4);
        split_kernel<<<nb, 256>>>((const float4*)k, (float4*)kh, (float4*)kl, n4);
        split_kernel<<<nb, 256>>>((const float4*)v, (float4*)vh, (float4*)vl, n4);
    }
    // transpose + split weights -> [N][K]
    {
        dim3 g(DIM / 32, DIM / 32);
        transpose_split_kernel<<<g, 256>>>(Wq, Wqh, Wql);
        transpose_split_kernel<<<g, 256>>>(Wk, Wkh, Wkl);
        transpose_split_kernel<<<g, 256>>>(Wv, Wvh, Wvl);
    }

    const int SMEM0 = 3 * STG0_FL * 4;   // 196608 B
    const int SMEM3 = 3 * STG3_FL * 4;   // 153600 B
    cudaFuncSetAttribute(mma_gemm<0>, cudaFuncAttributeMaxDynamicSharedMemorySize, SMEM0);
    cudaFuncSetAttribute(mma_gemm<1>, cudaFuncAttributeMaxDynamicSharedMemorySize, SMEM0);
    cudaFuncSetAttribute(mma_gemm<2>, cudaFuncAttributeMaxDynamicSharedMemorySize, SMEM0);
    cudaFuncSetAttribute(mma_gemm<3>, cudaFuncAttributeMaxDynamicSharedMemorySize, SMEM3);

    // Projections: M = B*SQL = 16384 rows, N = 1024
    {
        dim3 grid(DIM / 128, (BATCH * SQL) / 128, 1);
        mma_gemm<0><<<grid, 256, SMEM0>>>(qh, ql, Wqh, Wql, bq, Qph, Qpl,
                                          DIM, DIM, 0, 0, DIM, DIM, 0);
        mma_gemm<0><<<grid, 256, SMEM0>>>(kh, kl, Wkh, Wkl, bk, Kph, Kpl,
                                          DIM, DIM, 0, 0, DIM, DIM, 0);
        mma_gemm<1><<<grid, 256, SMEM0>>>(vh, vl, Wvh, Wvl, bvp, Vph, Vpl,
                                          DIM, DIM, 0, 0, DIM, DIM, 0);
    }

    // S = Qp @ Kp^T + mask (batched)
    {
        dim3 grid(SKL / 128, SQL / 128, BATCH);
        mma_gemm<2><<<grid, 256, SMEM0>>>(Qph, Qpl, Kph, Kpl, maskf, S, nullptr,
                                          DIM, DIM, (long long)SQL * DIM,
                                          (long long)SKL * DIM, DIM, SKL,
                                          (long long)SQL * SKL);
    }

    // softmax rows (writes tf32-rounded P in place)
    softmax_rows<<<BATCH * SQL, 256>>>(S);

    // out = P @ Vp (batched, B stored [K=sk][N=dv])
    {
        dim3 grid(DIM / 128, SQL / 128, BATCH);
        mma_gemm<3><<<grid, 256, SMEM3>>>(S, nullptr, Vph, Vpl, nullptr, out, nullptr,
                                          SKL, DIM, (long long)SQL * SKL,
                                          (long long)SKL * DIM, SKL, DIM,
                                          (long long)SQL * DIM);
    }
}

// round 6
// speedup vs baseline: 1.5085x; 1.5085x over previous
#include <cuda_runtime.h>
#include <cuda_fp16.h>
#include <cstdint>
#include <math.h>

// Problem dims
#define BATCH 8
#define SQL   2048
#define SKL   2048
#define DIM   1024

#define NELEM ((size_t)BATCH * SQL * DIM)      // 16.8M elements

// ---------------- device scratch (static) ----------------
__device__ __half g_q0[NELEM], g_q1[NELEM];
__device__ __half g_k0[NELEM], g_k1[NELEM];
__device__ __half g_v0[NELEM], g_v1[NELEM];
__device__ __half g_Wq0[DIM*DIM], g_Wq1[DIM*DIM];   // transposed [N][K]
__device__ __half g_Wk0[DIM*DIM], g_Wk1[DIM*DIM];
__device__ __half g_Wv0[DIM*DIM], g_Wv1[DIM*DIM];
__device__ __half g_Qp0[NELEM], g_Qp1[NELEM];
__device__ __half g_Kp0[NELEM], g_Kp1[NELEM];
__device__ __half g_Vp0[NELEM], g_Vp1[NELEM];       // [B*SK][DV]
__device__ float  g_S[(size_t)BATCH * SQL * SKL];   // scores (f32)
__device__ __half g_P0[(size_t)BATCH * SQL * SKL];  // softmax P split
__device__ __half g_P1[(size_t)BATCH * SQL * SKL];
__device__ float  g_maskf[BATCH * SKL];
__device__ int    g_mask_mode;

// ---------------- small helpers ----------------
__device__ __forceinline__ uint32_t smem_u32(const void* p) {
    uint32_t a;
    asm("{ .reg .u64 t; cvta.to.shared.u64 t, %1; cvt.u32.u64 %0, t; }" : "=r"(a) : "l"(p));
    return a;
}
__device__ __forceinline__ void cp16(uint32_t dst, const void* src) {
    asm volatile("cp.async.cg.shared.global [%0], [%1], 16;" :: "r"(dst), "l"(src) : "memory");
}
__device__ __forceinline__ void cp_commit() {
    asm volatile("cp.async.commit_group;" ::: "memory");
}
template<int N> __device__ __forceinline__ void cp_wait() {
    asm volatile("cp.async.wait_group %0;" :: "n"(N) : "memory");
}
// mma.sync m16n8k16 f16 -> f32 accum
__device__ __forceinline__ void mma16(float* c, const uint32_t* a, const uint32_t* b) {
    asm volatile(
        "mma.sync.aligned.m16n8k16.row.col.f32.f16.f16.f32 "
        "{%0,%1,%2,%3}, {%4,%5,%6,%7}, {%8,%9}, {%0,%1,%2,%3};"
        : "+f"(c[0]), "+f"(c[1]), "+f"(c[2]), "+f"(c[3])
        : "r"(a[0]), "r"(a[1]), "r"(a[2]), "r"(a[3]), "r"(b[0]), "r"(b[1]));
}
__device__ __forceinline__ uint32_t lds32(const char* smem, int off) {
    return *(const uint32_t*)(smem + off);
}
__device__ __forceinline__ uint32_t lds16x2(const char* smem, int off_lo, int off_hi) {
    uint32_t lo = *(const uint16_t*)(smem + off_lo);
    uint32_t hi = *(const uint16_t*)(smem + off_hi);
    return lo | (hi << 16);
}

// ---------------- mask dtype sniffing (verified R1) ----------------
__global__ void detect_mask_kernel(const unsigned int* __restrict__ w)
{
    __shared__ unsigned int f;
    if (threadIdx.x == 0) f = 0u;
    __syncthreads();
    unsigned int loc = 0u;
    for (int i = threadIdx.x; i < 4096; i += 256) {
        unsigned int x = w[i];
        if (x == 0x3F803F80u || x == 0x00003F80u) loc |= 8u;
        if (x == 0x3F800000u)                     loc |= 4u;
        if (x > 1u)                               loc |= 2u;
    }
    atomicOr(&f, loc);
    __syncthreads();
    if (threadIdx.x == 0) {
        unsigned int ff = f;
        g_mask_mode = (ff & 8u) ? 3 : (ff & 4u) ? 2 : (ff & 2u) ? 1 : 0;
    }
}
__global__ void convert_mask_kernel(const void* __restrict__ m, int n)
{
    int i = blockIdx.x * blockDim.x + threadIdx.x;
    if (i >= n) return;
    int mode = g_mask_mode;
    float v;
    if (mode == 0)      v = (float)((const int*)m)[i];
    else if (mode == 1) v = (float)((const unsigned char*)m)[i];
    else if (mode == 2) v = ((const float*)m)[i];
    else {
        unsigned short h = ((const unsigned short*)m)[i];
        v = __uint_as_float(((unsigned int)h) << 16);
    }
    g_maskf[i] = v;
}

// ---------------- fp16 double-half splits ----------------
__global__ __launch_bounds__(256)
void split_kernel(const float4* __restrict__ src, __half2* __restrict__ h0,
                  __half2* __restrict__ h1, int n4)
{
    int i = blockIdx.x * blockDim.x + threadIdx.x;
    if (i >= n4) return;
    float4 x = src[i];
    __half a0 = __float2half_rn(x.x); __half b0 = __float2half_rn(x.x - __half2float(a0));
    __half a1 = __float2half_rn(x.y); __half b1 = __float2half_rn(x.y - __half2float(a1));
    __half a2 = __float2half_rn(x.z); __half b2 = __float2half_rn(x.z - __half2float(a2));
    __half a3 = __float2half_rn(x.w); __half b3 = __float2half_rn(x.w - __half2float(a3));
    h0[2*i]   = __halves2half2(a0, a1);
    h0[2*i+1] = __halves2half2(a2, a3);
    h1[2*i]   = __halves2half2(b0, b1);
    h1[2*i+1] = __halves2half2(b2, b3);
}

// W [K=1024, N=1024] -> WT_h0/h1 [N, K] fp16
__global__ __launch_bounds__(256)
void transpose_split_kernel(const float* __restrict__ W,
                            __half* __restrict__ T0, __half* __restrict__ T1)
{
    __shared__ float t[32][33];
    int n0 = blockIdx.x * 32, k0 = blockIdx.y * 32;
    int tx = threadIdx.x & 31, ty = threadIdx.x >> 5;
    for (int r = ty; r < 32; r += 8)
        t[r][tx] = W[(size_t)(k0 + r) * DIM + n0 + tx];
    __syncthreads();
    for (int r = ty; r < 32; r += 8) {
        float x = t[tx][r];
        __half h = __float2half_rn(x);
        size_t o = (size_t)(n0 + r) * DIM + k0 + tx;
        T0[o] = h; T1[o] = __float2half_rn(x - __half2float(h));
    }
}

// ------------- fp16 mma GEMM: 128x128 tile, Kc=32, 3-stage cp.async -------------
// All modes compute 3 products: A0*B0 + A0*B1 + A1*B0 (A,B fp16 split pairs).
// MODE 0: C = A@B^T + bias      -> fp16 split write      (Q/K projection)
// MODE 1: C = tanh(A@B^T+bias)  -> fp16 split write      (V projection)
// MODE 2: C = A@B^T + mask      -> f32 write             (QK^T)
// MODE 3: C = A@B  (B=[K][N])   -> f32 write             (P@V)
// SMEM per stage: A0,A1 tiles [128][40 halfs] pad (10240 B each);
//   modes 0-2: B0,B1 same as A (10240 each)  -> stage 40960 B
//   mode  3:   B0,B1 [32][136 halfs] (8704)  -> stage 37888 B
#define STG02 40960
#define STG3  37888

template<int MODE>
__global__ __launch_bounds__(256, 1)
void mma_gemm(const __half* __restrict__ Ah, const __half* __restrict__ Al,
              const __half* __restrict__ Bh, const __half* __restrict__ Bl,
              const float* __restrict__ aux,
              void* __restrict__ out0v, void* __restrict__ out1v,
              int ldA, int ldB, long long sAz, long long sBz,
              int nK, int ldO, long long sOz)
{
    constexpr bool BK  = (MODE == 3);
    constexpr int  STG = BK ? STG3 : STG02;

    extern __shared__ char sm[];
    const uint32_t sb = smem_u32(sm);
    const int tid = threadIdx.x;
    const int lid = tid & 31, wid = tid >> 5;
    const int wm = wid >> 2, wn = wid & 3;      // 2 x 4 warp grid, warp tile 64x32
    const int lx = lid & 3,  ly = lid >> 2;
    const int m0 = blockIdx.y * 128, n0 = blockIdx.x * 128, z = blockIdx.z;
    const int nst = nK / 32;

    const __half* Agh = Ah + (size_t)z * sAz;
    const __half* Agl = Al + (size_t)z * sAz;
    const __half* Bgh = Bh + (size_t)z * sBz;
    const __half* Bgl = Bl + (size_t)z * sBz;

    float acc[4][4][4];
#pragma unroll
    for (int a = 0; a < 4; a++)
#pragma unroll
        for (int b = 0; b < 4; b++)
#pragma unroll
            for (int c = 0; c < 4; c++) acc[a][b][c] = 0.f;

    // ---- producer: fill stage SLOT st with k-chunk kt (32 k) ----
    auto issue = [&](int st, int kt) {
        uint32_t base = sb + (uint32_t)st * STG;
        // A tiles: 128 rows x 4 chunks (16B = 8 halfs), row stride 80 B
#pragma unroll
        for (int i = 0; i < 2; i++) {
            int q = i * 256 + tid; int r = q >> 2, c = q & 3;
            uint32_t d = (uint32_t)(r * 80 + c * 16);
            cp16(base + d,         Agh + (size_t)(m0 + r) * ldA + kt + c * 8);
            cp16(base + 10240 + d, Agl + (size_t)(m0 + r) * ldA + kt + c * 8);
        }
        uint32_t bb = base + 20480;
        if (!BK) {
#pragma unroll
            for (int i = 0; i < 2; i++) {
                int q = i * 256 + tid; int r = q >> 2, c = q & 3;
                uint32_t d = (uint32_t)(r * 80 + c * 16);
                cp16(bb + d,         Bgh + (size_t)(n0 + r) * ldB + kt + c * 8);
                cp16(bb + 10240 + d, Bgl + (size_t)(n0 + r) * ldB + kt + c * 8);
            }
        } else {
            // B tiles: 32 k-rows x 16 chunks, row stride 272 B
#pragma unroll
            for (int i = 0; i < 2; i++) {
                int q = i * 256 + tid; int r = q >> 4, c = q & 15;
                uint32_t d = (uint32_t)(r * 272 + c * 16);
                cp16(bb + d,        Bgh + (size_t)(kt + r) * ldB + n0 + c * 8);
                cp16(bb + 8704 + d, Bgl + (size_t)(kt + r) * ldB + n0 + c * 8);
            }
        }
        cp_commit();
    };

    issue(0, 0); issue(1, 32); issue(2, 64);

    // per-thread A row byte bases
    int rowA[4];
#pragma unroll
    for (int mt = 0; mt < 4; mt++) rowA[mt] = (wm * 64 + mt * 16 + ly) * 80 + 4 * lx;
    int rowB[4];
#pragma unroll
    for (int nt = 0; nt < 4; nt++) {
        if (!BK) rowB[nt] = (wn * 32 + nt * 8 + ly) * 80 + 4 * lx;
        else     rowB[nt] = wn * 32 + nt * 8 + ly;   // column index
    }

#pragma unroll 1
    for (int it = 0; it < nst; it++) {
        if (it + 2 < nst)      cp_wait<2>();
        else if (it + 1 < nst) cp_wait<1>();
        else                   cp_wait<0>();
        __syncthreads();
        const char* S0 = sm + (it % 3) * STG;
        const char* A0t = S0;
        const char* A1t = S0 + 10240;
        const char* B0t = S0 + 20480;
        const char* B1t = S0 + (BK ? 20480 + 8704 : 30720);

#pragma unroll
        for (int ks = 0; ks < 2; ks++) {
            const int kb = ks * 32;                 // byte offset of k16 slice (16 halfs)
            uint32_t a0[4][4], a1[4][4];
#pragma unroll
            for (int mt = 0; mt < 4; mt++) {
                int o = rowA[mt] + kb;
                a0[mt][0] = lds32(A0t, o);        a0[mt][1] = lds32(A0t, o + 640);
                a0[mt][2] = lds32(A0t, o + 16);   a0[mt][3] = lds32(A0t, o + 656);
                a1[mt][0] = lds32(A1t, o);        a1[mt][1] = lds32(A1t, o + 640);
                a1[mt][2] = lds32(A1t, o + 16);   a1[mt][3] = lds32(A1t, o + 656);
            }
            uint32_t b0[4][2], b1[4][2];
#pragma unroll
            for (int nt = 0; nt < 4; nt++) {
                if (!BK) {
                    int o = rowB[nt] + kb;
                    b0[nt][0] = lds32(B0t, o); b0[nt][1] = lds32(B0t, o + 16);
                    b1[nt][0] = lds32(B1t, o); b1[nt][1] = lds32(B1t, o + 16);
                } else {
                    int krow = (kb >> 1) + 2 * lx;        // k index = ks*16 + 2lx
                    int base0 = krow * 272 + rowB[nt] * 2;
                    b0[nt][0] = lds16x2(B0t, base0,        base0 + 272);
                    b0[nt][1] = lds16x2(B0t, base0 + 2176, base0 + 2448);
                    b1[nt][0] = lds16x2(B1t, base0,        base0 + 272);
                    b1[nt][1] = lds16x2(B1t, base0 + 2176, base0 + 2448);
                }
            }
#pragma unroll
            for (int mt = 0; mt < 4; mt++)
#pragma unroll
                for (int nt = 0; nt < 4; nt++) {
                    mma16(acc[mt][nt], a0[mt], b0[nt]);
                    mma16(acc[mt][nt], a0[mt], b1[nt]);
                    mma16(acc[mt][nt], a1[mt], b0[nt]);
                }
        }
        __syncthreads();
        if (it + 3 < nst) issue(it % 3, (it + 3) * 32);
    }

    // ---- epilogue ----
#pragma unroll
    for (int mt = 0; mt < 4; mt++) {
#pragma unroll
        for (int hf = 0; hf < 2; hf++) {
            const int gm = m0 + wm * 64 + mt * 16 + ly + hf * 8;
#pragma unroll
            for (int nt = 0; nt < 4; nt++) {
                const int col = n0 + wn * 32 + nt * 8 + 2 * lx;
                float c0 = acc[mt][nt][hf * 2 + 0];
                float c1 = acc[mt][nt][hf * 2 + 1];
                if (MODE == 0 || MODE == 1) {
                    float x0 = c0 + aux[col], x1 = c1 + aux[col + 1];
                    if (MODE == 1) { x0 = tanhf(x0); x1 = tanhf(x1); }
                    __half h0 = __float2half_rn(x0), h1 = __float2half_rn(x1);
                    __half l0 = __float2half_rn(x0 - __half2float(h0));
                    __half l1 = __float2half_rn(x1 - __half2float(h1));
                    *(__half2*)((__half*)out0v + (size_t)gm * ldO + col) = __halves2half2(h0, h1);
                    *(__half2*)((__half*)out1v + (size_t)gm * ldO + col) = __halves2half2(l0, l1);
                } else if (MODE == 2) {
                    float x0 = c0 + aux[(size_t)z * SKL + col];
                    float x1 = c1 + aux[(size_t)z * SKL + col + 1];
                    *(float2*)((float*)out0v + (size_t)z * sOz + (size_t)gm * ldO + col) =
                        make_float2(x0, x1);
                } else {
                    *(float2*)((float*)out0v + (size_t)z * sOz + (size_t)gm * ldO + col) =
                        make_float2(c0, c1);
                }
            }
        }
    }
}

// ------------- softmax: read f32 S row, write fp16-split P -------------
__global__ __launch_bounds__(256)
void softmax_rows(const float* __restrict__ S, __half* __restrict__ P0,
                  __half* __restrict__ P1)
{
    const float* row = S + (size_t)blockIdx.x * SKL;
    __half* r0 = P0 + (size_t)blockIdx.x * SKL;
    __half* r1 = P1 + (size_t)blockIdx.x * SKL;
    const int t = threadIdx.x;
    float v[8];
    float mx = -INFINITY;
#pragma unroll
    for (int i = 0; i < 8; i++) { v[i] = row[t + i * 256]; mx = fmaxf(mx, v[i]); }

    __shared__ float red[256];
    red[t] = mx; __syncthreads();
#pragma unroll
    for (int s = 128; s > 0; s >>= 1) {
        if (t < s) red[t] = fmaxf(red[t], red[t + s]);
        __syncthreads();
    }
    mx = red[0];
    __syncthreads();

    float sum = 0.f;
#pragma unroll
    for (int i = 0; i < 8; i++) { v[i] = __expf(v[i] - mx); sum += v[i]; }
    red[t] = sum; __syncthreads();
#pragma unroll
    for (int s = 128; s > 0; s >>= 1) {
        if (t < s) red[t] += red[t + s];
        __syncthreads();
    }
    const float inv = 1.0f / red[0];
#pragma unroll
    for (int i = 0; i < 8; i++) {
        float p = v[i] * inv;
        __half h = __float2half_rn(p);
        r0[t + i * 256] = h;
        r1[t + i * 256] = __float2half_rn(p - __half2float(h));
    }
}

// ---------------- launch ----------------
extern "C" void kernel_launch(void* const* d_in, const int* in_sizes, int n_in,
                              void* d_out, int out_size)
{
    const float* q    = (const float*)d_in[0];
    const float* k    = (const float*)d_in[1];
    const float* v    = (const float*)d_in[2];
    const void*  mask = d_in[3];
    const float* Wq   = (const float*)d_in[4];
    const float* bq   = (const float*)d_in[5];
    const float* Wk   = (const float*)d_in[6];
    const float* bk   = (const float*)d_in[7];
    const float* Wv   = (const float*)d_in[8];
    const float* bvp  = (const float*)d_in[9];
    float* out        = (float*)d_out;

    __half *q0, *q1, *k0, *k1, *v0, *v1;
    __half *Wq0, *Wq1, *Wk0, *Wk1, *Wv0, *Wv1;
    __half *Qp0, *Qp1, *Kp0, *Kp1, *Vp0, *Vp1, *P0, *P1;
    float *S, *maskf;
    cudaGetSymbolAddress((void**)&q0, g_q0);   cudaGetSymbolAddress((void**)&q1, g_q1);
    cudaGetSymbolAddress((void**)&k0, g_k0);   cudaGetSymbolAddress((void**)&k1, g_k1);
    cudaGetSymbolAddress((void**)&v0, g_v0);   cudaGetSymbolAddress((void**)&v1, g_v1);
    cudaGetSymbolAddress((void**)&Wq0, g_Wq0); cudaGetSymbolAddress((void**)&Wq1, g_Wq1);
    cudaGetSymbolAddress((void**)&Wk0, g_Wk0); cudaGetSymbolAddress((void**)&Wk1, g_Wk1);
    cudaGetSymbolAddress((void**)&Wv0, g_Wv0); cudaGetSymbolAddress((void**)&Wv1, g_Wv1);
    cudaGetSymbolAddress((void**)&Qp0, g_Qp0); cudaGetSymbolAddress((void**)&Qp1, g_Qp1);
    cudaGetSymbolAddress((void**)&Kp0, g_Kp0); cudaGetSymbolAddress((void**)&Kp1, g_Kp1);
    cudaGetSymbolAddress((void**)&Vp0, g_Vp0); cudaGetSymbolAddress((void**)&Vp1, g_Vp1);
    cudaGetSymbolAddress((void**)&P0, g_P0);   cudaGetSymbolAddress((void**)&P1, g_P1);
    cudaGetSymbolAddress((void**)&S, g_S);     cudaGetSymbolAddress((void**)&maskf, g_maskf);

    // mask -> float
    detect_mask_kernel<<<1, 256>>>((const unsigned int*)mask);
    convert_mask_kernel<<<(BATCH * SKL + 255) / 256, 256>>>(mask, BATCH * SKL);

    // split inputs into fp16 pairs
    {
        int n4 = (int)(NELEM / 4);
        int nb = (n4 + 255) / 256;
        split_kernel<<<nb, 256>>>((const float4*)q, (__half2*)q0, (__half2*)q1, n4);
        split_kernel<<<nb, 256>>>((const float4*)k, (__half2*)k0, (__half2*)k1, n4);
        split_kernel<<<nb, 256>>>((const float4*)v, (__half2*)v0, (__half2*)v1, n4);
    }
    // transpose + split weights -> [N][K] fp16
    {
        dim3 g(DIM / 32, DIM / 32);
        transpose_split_kernel<<<g, 256>>>(Wq, Wq0, Wq1);
        transpose_split_kernel<<<g, 256>>>(Wk, Wk0, Wk1);
        transpose_split_kernel<<<g, 256>>>(Wv, Wv0, Wv1);
    }

    const int SMEM02 = 3 * STG02;   // 122880 B
    const int SMEM3  = 3 * STG3;    // 113664 B
    cudaFuncSetAttribute(mma_gemm<0>, cudaFuncAttributeMaxDynamicSharedMemorySize, SMEM02);
    cudaFuncSetAttribute(mma_gemm<1>, cudaFuncAttributeMaxDynamicSharedMemorySize, SMEM02);
    cudaFuncSetAttribute(mma_gemm<2>, cudaFuncAttributeMaxDynamicSharedMemorySize, SMEM02);
    cudaFuncSetAttribute(mma_gemm<3>, cudaFuncAttributeMaxDynamicSharedMemorySize, SMEM3);

    // Projections: M = B*SQL = 16384 rows, N = 1024
    {
        dim3 grid(DIM / 128, (BATCH * SQL) / 128, 1);
        mma_gemm<0><<<grid, 256, SMEM02>>>(q0, q1, Wq0, Wq1, bq, Qp0, Qp1,
                                           DIM, DIM, 0, 0, DIM, DIM, 0);
        mma_gemm<0><<<grid, 256, SMEM02>>>(k0, k1, Wk0, Wk1, bk, Kp0, Kp1,
                                           DIM, DIM, 0, 0, DIM, DIM, 0);
        mma_gemm<1><<<grid, 256, SMEM02>>>(v0, v1, Wv0, Wv1, bvp, Vp0, Vp1,
                                           DIM, DIM, 0, 0, DIM, DIM, 0);
    }

    // S = Qp @ Kp^T + mask (batched)
    {
        dim3 grid(SKL / 128, SQL / 128, BATCH);
        mma_gemm<2><<<grid, 256, SMEM02>>>(Qp0, Qp1, Kp0, Kp1, maskf, S, nullptr,
                                           DIM, DIM, (long long)SQL * DIM,
                                           (long long)SKL * DIM, DIM, SKL,
                                           (long long)SQL * SKL);
    }

    // softmax rows -> fp16 split P
    softmax_rows<<<BATCH * SQL, 256>>>(S, P0, P1);

    // out = P @ Vp (batched, B stored [K=sk][N=dv])
    {
        dim3 grid(DIM / 128, SQL / 128, BATCH);
        mma_gemm<3><<<grid, 256, SMEM3>>>(P0, P1, Vp0, Vp1, nullptr, out, nullptr,
                                          SKL, DIM, (long long)SQL * SKL,
                                          (long long)SKL * DIM, SKL, DIM,
                                          (long long)SQL * DIM);
    }
}

// round 7
// speedup vs baseline: 1.7067x; 1.1315x over previous
#include <cuda_runtime.h>
#include <cuda_fp16.h>
#include <cstdint>
#include <math.h>

// Problem dims
#define BATCH 8
#define SQL   2048
#define SKL   2048
#define DIM   1024

#define NELEM ((size_t)BATCH * SQL * DIM)      // 16.8M elements

// ---------------- device scratch (static) ----------------
__device__ __half g_q0[NELEM], g_q1[NELEM];
__device__ __half g_k0[NELEM], g_k1[NELEM];
__device__ __half g_v0[NELEM], g_v1[NELEM];
__device__ __half g_Wq0[DIM*DIM], g_Wq1[DIM*DIM];   // transposed [N][K]
__device__ __half g_Wk0[DIM*DIM], g_Wk1[DIM*DIM];
__device__ __half g_Wv0[DIM*DIM], g_Wv1[DIM*DIM];
__device__ __half g_Qp0[NELEM], g_Qp1[NELEM];
__device__ __half g_Kp0[NELEM], g_Kp1[NELEM];
__device__ __half g_Vp0[NELEM], g_Vp1[NELEM];       // [B*SK][DV]
__device__ float  g_S[(size_t)BATCH * SQL * SKL];   // scores (f32)
__device__ __half g_P0[(size_t)BATCH * SQL * SKL];  // softmax P split
__device__ __half g_P1[(size_t)BATCH * SQL * SKL];
__device__ float  g_maskf[BATCH * SKL];
__device__ int    g_mask_mode;

// ---------------- small helpers ----------------
__device__ __forceinline__ uint32_t smem_u32(const void* p) {
    uint32_t a;
    asm("{ .reg .u64 t; cvta.to.shared.u64 t, %1; cvt.u32.u64 %0, t; }" : "=r"(a) : "l"(p));
    return a;
}
__device__ __forceinline__ void cp16(uint32_t dst, const void* src) {
    asm volatile("cp.async.cg.shared.global [%0], [%1], 16;" :: "r"(dst), "l"(src) : "memory");
}
__device__ __forceinline__ void cp_commit() {
    asm volatile("cp.async.commit_group;" ::: "memory");
}
template<int N> __device__ __forceinline__ void cp_wait() {
    asm volatile("cp.async.wait_group %0;" :: "n"(N) : "memory");
}
// mma.sync m16n8k16 f16 -> f32 accum
__device__ __forceinline__ void mma16(float* c, const uint32_t* a, const uint32_t* b) {
    asm volatile(
        "mma.sync.aligned.m16n8k16.row.col.f32.f16.f16.f32 "
        "{%0,%1,%2,%3}, {%4,%5,%6,%7}, {%8,%9}, {%0,%1,%2,%3};"
        : "+f"(c[0]), "+f"(c[1]), "+f"(c[2]), "+f"(c[3])
        : "r"(a[0]), "r"(a[1]), "r"(a[2]), "r"(a[3]), "r"(b[0]), "r"(b[1]));
}
__device__ __forceinline__ uint32_t lds32(const char* smem, int off) {
    return *(const uint32_t*)(smem + off);
}
__device__ __forceinline__ uint32_t lds16x2(const char* smem, int off_lo, int off_hi) {
    uint32_t lo = *(const uint16_t*)(smem + off_lo);
    uint32_t hi = *(const uint16_t*)(smem + off_hi);
    return lo | (hi << 16);
}

// ---------------- mask dtype sniffing (verified R1) ----------------
__global__ void detect_mask_kernel(const unsigned int* __restrict__ w)
{
    __shared__ unsigned int f;
    if (threadIdx.x == 0) f = 0u;
    __syncthreads();
    unsigned int loc = 0u;
    for (int i = threadIdx.x; i < 4096; i += 256) {
        unsigned int x = w[i];
        if (x == 0x3F803F80u || x == 0x00003F80u) loc |= 8u;
        if (x == 0x3F800000u)                     loc |= 4u;
        if (x > 1u)                               loc |= 2u;
    }
    atomicOr(&f, loc);
    __syncthreads();
    if (threadIdx.x == 0) {
        unsigned int ff = f;
        g_mask_mode = (ff & 8u) ? 3 : (ff & 4u) ? 2 : (ff & 2u) ? 1 : 0;
    }
}
__global__ void convert_mask_kernel(const void* __restrict__ m, int n)
{
    int i = blockIdx.x * blockDim.x + threadIdx.x;
    if (i >= n) return;
    int mode = g_mask_mode;
    float v;
    if (mode == 0)      v = (float)((const int*)m)[i];
    else if (mode == 1) v = (float)((const unsigned char*)m)[i];
    else if (mode == 2) v = ((const float*)m)[i];
    else {
        unsigned short h = ((const unsigned short*)m)[i];
        v = __uint_as_float(((unsigned int)h) << 16);
    }
    g_maskf[i] = v;
}

// ---------------- fp16 double-half splits ----------------
__global__ __launch_bounds__(256)
void split_kernel(const float4* __restrict__ src, __half2* __restrict__ h0,
                  __half2* __restrict__ h1, int n4)
{
    int i = blockIdx.x * blockDim.x + threadIdx.x;
    if (i >= n4) return;
    float4 x = src[i];
    __half a0 = __float2half_rn(x.x); __half b0 = __float2half_rn(x.x - __half2float(a0));
    __half a1 = __float2half_rn(x.y); __half b1 = __float2half_rn(x.y - __half2float(a1));
    __half a2 = __float2half_rn(x.z); __half b2 = __float2half_rn(x.z - __half2float(a2));
    __half a3 = __float2half_rn(x.w); __half b3 = __float2half_rn(x.w - __half2float(a3));
    h0[2*i]   = __halves2half2(a0, a1);
    h0[2*i+1] = __halves2half2(a2, a3);
    h1[2*i]   = __halves2half2(b0, b1);
    h1[2*i+1] = __halves2half2(b2, b3);
}

// W [K=1024, N=1024] -> WT_h0/h1 [N, K] fp16
__global__ __launch_bounds__(256)
void transpose_split_kernel(const float* __restrict__ W,
                            __half* __restrict__ T0, __half* __restrict__ T1)
{
    __shared__ float t[32][33];
    int n0 = blockIdx.x * 32, k0 = blockIdx.y * 32;
    int tx = threadIdx.x & 31, ty = threadIdx.x >> 5;
    for (int r = ty; r < 32; r += 8)
        t[r][tx] = W[(size_t)(k0 + r) * DIM + n0 + tx];
    __syncthreads();
    for (int r = ty; r < 32; r += 8) {
        float x = t[tx][r];
        __half h = __float2half_rn(x);
        size_t o = (size_t)(n0 + r) * DIM + k0 + tx;
        T0[o] = h; T1[o] = __float2half_rn(x - __half2float(h));
    }
}

// ------------- fp16 mma GEMM: 128x128 tile, Kc=32, 2-stage cp.async, 2 CTAs/SM ----
// All modes compute 3 products: A0*B0 + A0*B1 + A1*B0 (A,B fp16 split pairs).
// MODE 0: C = A@B^T + bias      -> fp16 split write      (Q/K projection)
// MODE 1: C = tanh(A@B^T+bias)  -> fp16 split write      (V projection)
// MODE 2: C = A@B^T + mask      -> f32 write             (QK^T)
// MODE 3: C = A@B  (B=[K][N])   -> f32 write             (P@V)
#define STG02 40960
#define STG3  37888

template<int MODE>
__global__ __launch_bounds__(256, 2)
void mma_gemm(const __half* __restrict__ Ah, const __half* __restrict__ Al,
              const __half* __restrict__ Bh, const __half* __restrict__ Bl,
              const float* __restrict__ aux,
              void* __restrict__ out0v, void* __restrict__ out1v,
              int ldA, int ldB, long long sAz, long long sBz,
              int nK, int ldO, long long sOz)
{
    constexpr bool BK  = (MODE == 3);
    constexpr int  STG = BK ? STG3 : STG02;

    extern __shared__ char sm[];
    const uint32_t sb = smem_u32(sm);
    const int tid = threadIdx.x;
    const int lid = tid & 31, wid = tid >> 5;
    const int wm = wid >> 2, wn = wid & 3;      // 2 x 4 warp grid, warp tile 64x32
    const int lx = lid & 3,  ly = lid >> 2;
    const int m0 = blockIdx.y * 128, n0 = blockIdx.x * 128, z = blockIdx.z;
    const int nst = nK / 32;

    const __half* Agh = Ah + (size_t)z * sAz;
    const __half* Agl = Al + (size_t)z * sAz;
    const __half* Bgh = Bh + (size_t)z * sBz;
    const __half* Bgl = Bl + (size_t)z * sBz;

    float acc[4][4][4];
#pragma unroll
    for (int a = 0; a < 4; a++)
#pragma unroll
        for (int b = 0; b < 4; b++)
#pragma unroll
            for (int c = 0; c < 4; c++) acc[a][b][c] = 0.f;

    // ---- producer: fill stage SLOT st with k-chunk kt (32 k) ----
    auto issue = [&](int st, int kt) {
        uint32_t base = sb + (uint32_t)st * STG;
        // A tiles: 128 rows x 4 chunks (16B = 8 halfs), row stride 80 B
#pragma unroll
        for (int i = 0; i < 2; i++) {
            int q = i * 256 + tid; int r = q >> 2, c = q & 3;
            uint32_t d = (uint32_t)(r * 80 + c * 16);
            cp16(base + d,         Agh + (size_t)(m0 + r) * ldA + kt + c * 8);
            cp16(base + 10240 + d, Agl + (size_t)(m0 + r) * ldA + kt + c * 8);
        }
        uint32_t bb = base + 20480;
        if (!BK) {
#pragma unroll
            for (int i = 0; i < 2; i++) {
                int q = i * 256 + tid; int r = q >> 2, c = q & 3;
                uint32_t d = (uint32_t)(r * 80 + c * 16);
                cp16(bb + d,         Bgh + (size_t)(n0 + r) * ldB + kt + c * 8);
                cp16(bb + 10240 + d, Bgl + (size_t)(n0 + r) * ldB + kt + c * 8);
            }
        } else {
            // B tiles: 32 k-rows x 16 chunks, row stride 272 B
#pragma unroll
            for (int i = 0; i < 2; i++) {
                int q = i * 256 + tid; int r = q >> 4, c = q & 15;
                uint32_t d = (uint32_t)(r * 272 + c * 16);
                cp16(bb + d,        Bgh + (size_t)(kt + r) * ldB + n0 + c * 8);
                cp16(bb + 8704 + d, Bgl + (size_t)(kt + r) * ldB + n0 + c * 8);
            }
        }
        cp_commit();
    };

    issue(0, 0); issue(1, 32);

    // per-thread A row byte bases
    int rowA[4];
#pragma unroll
    for (int mt = 0; mt < 4; mt++) rowA[mt] = (wm * 64 + mt * 16 + ly) * 80 + 4 * lx;
    int rowB[4];
#pragma unroll
    for (int nt = 0; nt < 4; nt++) {
        if (!BK) rowB[nt] = (wn * 32 + nt * 8 + ly) * 80 + 4 * lx;
        else     rowB[nt] = wn * 32 + nt * 8 + ly;   // column index
    }

#pragma unroll 1
    for (int it = 0; it < nst; it++) {
        if (it + 1 < nst) cp_wait<1>();
        else              cp_wait<0>();
        __syncthreads();
        const char* S0 = sm + (it & 1) * STG;
        const char* A0t = S0;
        const char* A1t = S0 + 10240;
        const char* B0t = S0 + 20480;
        const char* B1t = S0 + (BK ? 20480 + 8704 : 30720);

#pragma unroll
        for (int ks = 0; ks < 2; ks++) {
            const int kb = ks * 32;                 // byte offset of k16 slice (16 halfs)
            uint32_t a0[4][4], a1[4][4];
#pragma unroll
            for (int mt = 0; mt < 4; mt++) {
                int o = rowA[mt] + kb;
                a0[mt][0] = lds32(A0t, o);        a0[mt][1] = lds32(A0t, o + 640);
                a0[mt][2] = lds32(A0t, o + 16);   a0[mt][3] = lds32(A0t, o + 656);
                a1[mt][0] = lds32(A1t, o);        a1[mt][1] = lds32(A1t, o + 640);
                a1[mt][2] = lds32(A1t, o + 16);   a1[mt][3] = lds32(A1t, o + 656);
            }
            uint32_t b0[4][2], b1[4][2];
#pragma unroll
            for (int nt = 0; nt < 4; nt++) {
                if (!BK) {
                    int o = rowB[nt] + kb;
                    b0[nt][0] = lds32(B0t, o); b0[nt][1] = lds32(B0t, o + 16);
                    b1[nt][0] = lds32(B1t, o); b1[nt][1] = lds32(B1t, o + 16);
                } else {
                    int krow = (kb >> 1) + 2 * lx;        // k index = ks*16 + 2lx
                    int base0 = krow * 272 + rowB[nt] * 2;
                    b0[nt][0] = lds16x2(B0t, base0,        base0 + 272);
                    b0[nt][1] = lds16x2(B0t, base0 + 2176, base0 + 2448);
                    b1[nt][0] = lds16x2(B1t, base0,        base0 + 272);
                    b1[nt][1] = lds16x2(B1t, base0 + 2176, base0 + 2448);
                }
            }
#pragma unroll
            for (int mt = 0; mt < 4; mt++)
#pragma unroll
                for (int nt = 0; nt < 4; nt++) {
                    mma16(acc[mt][nt], a0[mt], b0[nt]);
                    mma16(acc[mt][nt], a0[mt], b1[nt]);
                    mma16(acc[mt][nt], a1[mt], b0[nt]);
                }
        }
        __syncthreads();
        if (it + 2 < nst) issue(it & 1, (it + 2) * 32);
    }

    // ---- epilogue ----
#pragma unroll
    for (int mt = 0; mt < 4; mt++) {
#pragma unroll
        for (int hf = 0; hf < 2; hf++) {
            const int gm = m0 + wm * 64 + mt * 16 + ly + hf * 8;
#pragma unroll
            for (int nt = 0; nt < 4; nt++) {
                const int col = n0 + wn * 32 + nt * 8 + 2 * lx;
                float c0 = acc[mt][nt][hf * 2 + 0];
                float c1 = acc[mt][nt][hf * 2 + 1];
                if (MODE == 0 || MODE == 1) {
                    float x0 = c0 + aux[col], x1 = c1 + aux[col + 1];
                    if (MODE == 1) { x0 = tanhf(x0); x1 = tanhf(x1); }
                    __half h0 = __float2half_rn(x0), h1 = __float2half_rn(x1);
                    __half l0 = __float2half_rn(x0 - __half2float(h0));
                    __half l1 = __float2half_rn(x1 - __half2float(h1));
                    *(__half2*)((__half*)out0v + (size_t)gm * ldO + col) = __halves2half2(h0, h1);
                    *(__half2*)((__half*)out1v + (size_t)gm * ldO + col) = __halves2half2(l0, l1);
                } else if (MODE == 2) {
                    float x0 = c0 + aux[(size_t)z * SKL + col];
                    float x1 = c1 + aux[(size_t)z * SKL + col + 1];
                    *(float2*)((float*)out0v + (size_t)z * sOz + (size_t)gm * ldO + col) =
                        make_float2(x0, x1);
                } else {
                    *(float2*)((float*)out0v + (size_t)z * sOz + (size_t)gm * ldO + col) =
                        make_float2(c0, c1);
                }
            }
        }
    }
}

// ------------- softmax: read f32 S row, write fp16-split P -------------
__global__ __launch_bounds__(256)
void softmax_rows(const float* __restrict__ S, __half* __restrict__ P0,
                  __half* __restrict__ P1)
{
    const float* row = S + (size_t)blockIdx.x * SKL;
    __half* r0 = P0 + (size_t)blockIdx.x * SKL;
    __half* r1 = P1 + (size_t)blockIdx.x * SKL;
    const int t = threadIdx.x;
    float v[8];
    float mx = -INFINITY;
#pragma unroll
    for (int i = 0; i < 8; i++) { v[i] = row[t + i * 256]; mx = fmaxf(mx, v[i]); }

    __shared__ float red[256];
    red[t] = mx; __syncthreads();
#pragma unroll
    for (int s = 128; s > 0; s >>= 1) {
        if (t < s) red[t] = fmaxf(red[t], red[t + s]);
        __syncthreads();
    }
    mx = red[0];
    __syncthreads();

    float sum = 0.f;
#pragma unroll
    for (int i = 0; i < 8; i++) { v[i] = __expf(v[i] - mx); sum += v[i]; }
    red[t] = sum; __syncthreads();
#pragma unroll
    for (int s = 128; s > 0; s >>= 1) {
        if (t < s) red[t] += red[t + s];
        __syncthreads();
    }
    const float inv = 1.0f / red[0];
#pragma unroll
    for (int i = 0; i < 8; i++) {
        float p = v[i] * inv;
        __half h = __float2half_rn(p);
        r0[t + i * 256] = h;
        r1[t + i * 256] = __float2half_rn(p - __half2float(h));
    }
}

// ---------------- launch ----------------
extern "C" void kernel_launch(void* const* d_in, const int* in_sizes, int n_in,
                              void* d_out, int out_size)
{
    const float* q    = (const float*)d_in[0];
    const float* k    = (const float*)d_in[1];
    const float* v    = (const float*)d_in[2];
    const void*  mask = d_in[3];
    const float* Wq   = (const float*)d_in[4];
    const float* bq   = (const float*)d_in[5];
    const float* Wk   = (const float*)d_in[6];
    const float* bk   = (const float*)d_in[7];
    const float* Wv   = (const float*)d_in[8];
    const float* bvp  = (const float*)d_in[9];
    float* out        = (float*)d_out;

    __half *q0, *q1, *k0, *k1, *v0, *v1;
    __half *Wq0, *Wq1, *Wk0, *Wk1, *Wv0, *Wv1;
    __half *Qp0, *Qp1, *Kp0, *Kp1, *Vp0, *Vp1, *P0, *P1;
    float *S, *maskf;
    cudaGetSymbolAddress((void**)&q0, g_q0);   cudaGetSymbolAddress((void**)&q1, g_q1);
    cudaGetSymbolAddress((void**)&k0, g_k0);   cudaGetSymbolAddress((void**)&k1, g_k1);
    cudaGetSymbolAddress((void**)&v0, g_v0);   cudaGetSymbolAddress((void**)&v1, g_v1);
    cudaGetSymbolAddress((void**)&Wq0, g_Wq0); cudaGetSymbolAddress((void**)&Wq1, g_Wq1);
    cudaGetSymbolAddress((void**)&Wk0, g_Wk0); cudaGetSymbolAddress((void**)&Wk1, g_Wk1);
    cudaGetSymbolAddress((void**)&Wv0, g_Wv0); cudaGetSymbolAddress((void**)&Wv1, g_Wv1);
    cudaGetSymbolAddress((void**)&Qp0, g_Qp0); cudaGetSymbolAddress((void**)&Qp1, g_Qp1);
    cudaGetSymbolAddress((void**)&Kp0, g_Kp0); cudaGetSymbolAddress((void**)&Kp1, g_Kp1);
    cudaGetSymbolAddress((void**)&Vp0, g_Vp0); cudaGetSymbolAddress((void**)&Vp1, g_Vp1);
    cudaGetSymbolAddress((void**)&P0, g_P0);   cudaGetSymbolAddress((void**)&P1, g_P1);
    cudaGetSymbolAddress((void**)&S, g_S);     cudaGetSymbolAddress((void**)&maskf, g_maskf);

    // mask -> float
    detect_mask_kernel<<<1, 256>>>((const unsigned int*)mask);
    convert_mask_kernel<<<(BATCH * SKL + 255) / 256, 256>>>(mask, BATCH * SKL);

    // split inputs into fp16 pairs
    {
        int n4 = (int)(NELEM / 4);
        int nb = (n4 + 255) / 256;
        split_kernel<<<nb, 256>>>((const float4*)q, (__half2*)q0, (__half2*)q1, n4);
        split_kernel<<<nb, 256>>>((const float4*)k, (__half2*)k0, (__half2*)k1, n4);
        split_kernel<<<nb, 256>>>((const float4*)v, (__half2*)v0, (__half2*)v1, n4);
    }
    // transpose + split weights -> [N][K] fp16
    {
        dim3 g(DIM / 32, DIM / 32);
        transpose_split_kernel<<<g, 256>>>(Wq, Wq0, Wq1);
        transpose_split_kernel<<<g, 256>>>(Wk, Wk0, Wk1);
        transpose_split_kernel<<<g, 256>>>(Wv, Wv0, Wv1);
    }

    const int SMEM02 = 2 * STG02;   // 81920 B -> 2 CTAs/SM
    const int SMEM3  = 2 * STG3;    // 75776 B -> 2 CTAs/SM
    cudaFuncSetAttribute(mma_gemm<0>, cudaFuncAttributeMaxDynamicSharedMemorySize, SMEM02);
    cudaFuncSetAttribute(mma_gemm<1>, cudaFuncAttributeMaxDynamicSharedMemorySize, SMEM02);
    cudaFuncSetAttribute(mma_gemm<2>, cudaFuncAttributeMaxDynamicSharedMemorySize, SMEM02);
    cudaFuncSetAttribute(mma_gemm<3>, cudaFuncAttributeMaxDynamicSharedMemorySize, SMEM3);

    // Projections: M = B*SQL = 16384 rows, N = 1024
    {
        dim3 grid(DIM / 128, (BATCH * SQL) / 128, 1);
        mma_gemm<0><<<grid, 256, SMEM02>>>(q0, q1, Wq0, Wq1, bq, Qp0, Qp1,
                                           DIM, DIM, 0, 0, DIM, DIM, 0);
        mma_gemm<0><<<grid, 256, SMEM02>>>(k0, k1, Wk0, Wk1, bk, Kp0, Kp1,
                                           DIM, DIM, 0, 0, DIM, DIM, 0);
        mma_gemm<1><<<grid, 256, SMEM02>>>(v0, v1, Wv0, Wv1, bvp, Vp0, Vp1,
                                           DIM, DIM, 0, 0, DIM, DIM, 0);
    }

    // S = Qp @ Kp^T + mask (batched)
    {
        dim3 grid(SKL / 128, SQL / 128, BATCH);
        mma_gemm<2><<<grid, 256, SMEM02>>>(Qp0, Qp1, Kp0, Kp1, maskf, S, nullptr,
                                           DIM, DIM, (long long)SQL * DIM,
                                           (long long)SKL * DIM, DIM, SKL,
                                           (long long)SQL * SKL);
    }

    // softmax rows -> fp16 split P
    softmax_rows<<<BATCH * SQL, 256>>>(S, P0, P1);

    // out = P @ Vp (batched, B stored [K=sk][N=dv])
    {
        dim3 grid(DIM / 128, SQL / 128, BATCH);
        mma_gemm<3><<<grid, 256, SMEM3>>>(P0, P1, Vp0, Vp1, nullptr, out, nullptr,
                                          SKL, DIM, (long long)SQL * SKL,
                                          (long long)SKL * DIM, SKL, DIM,
                                          (long long)SQL * DIM);
    }
}

// round 8
// speedup vs baseline: 1.8756x; 1.0989x over previous
#include <cuda_runtime.h>
#include <cuda_fp16.h>
#include <cstdint>
#include <math.h>

// Problem dims
#define BATCH 8
#define SQL   2048
#define SKL   2048
#define DIM   1024

#define NELEM ((size_t)BATCH * SQL * DIM)      // 16.8M elements

// ---------------- device scratch (static) ----------------
__device__ __half g_q0[NELEM], g_q1[NELEM];
__device__ __half g_k0[NELEM], g_k1[NELEM];
__device__ __half g_v0[NELEM], g_v1[NELEM];
__device__ __half g_Wq0[DIM*DIM], g_Wq1[DIM*DIM];   // transposed [N][K]
__device__ __half g_Wk0[DIM*DIM], g_Wk1[DIM*DIM];
__device__ __half g_Wv0[DIM*DIM], g_Wv1[DIM*DIM];
__device__ __half g_Qp0[NELEM], g_Qp1[NELEM];
__device__ __half g_Kp0[NELEM], g_Kp1[NELEM];
__device__ __half g_Vp0[NELEM];                     // single fp16 V (PV uses 2 products)
__device__ float  g_S[(size_t)BATCH * SQL * SKL];   // scores (f32)
__device__ __half g_P0[(size_t)BATCH * SQL * SKL];  // softmax P split
__device__ __half g_P1[(size_t)BATCH * SQL * SKL];
__device__ float  g_maskf[BATCH * SKL];
__device__ int    g_mask_mode;

// ---------------- small helpers ----------------
__device__ __forceinline__ uint32_t smem_u32(const void* p) {
    uint32_t a;
    asm("{ .reg .u64 t; cvta.to.shared.u64 t, %1; cvt.u32.u64 %0, t; }" : "=r"(a) : "l"(p));
    return a;
}
__device__ __forceinline__ void cp16(uint32_t dst, const void* src) {
    asm volatile("cp.async.cg.shared.global [%0], [%1], 16;" :: "r"(dst), "l"(src) : "memory");
}
__device__ __forceinline__ void cp_commit() {
    asm volatile("cp.async.commit_group;" ::: "memory");
}
template<int N> __device__ __forceinline__ void cp_wait() {
    asm volatile("cp.async.wait_group %0;" :: "n"(N) : "memory");
}
// mma.sync m16n8k16 f16 -> f32 accum
__device__ __forceinline__ void mma16(float* c, const uint32_t* a, const uint32_t* b) {
    asm volatile(
        "mma.sync.aligned.m16n8k16.row.col.f32.f16.f16.f32 "
        "{%0,%1,%2,%3}, {%4,%5,%6,%7}, {%8,%9}, {%0,%1,%2,%3};"
        : "+f"(c[0]), "+f"(c[1]), "+f"(c[2]), "+f"(c[3])
        : "r"(a[0]), "r"(a[1]), "r"(a[2]), "r"(a[3]), "r"(b[0]), "r"(b[1]));
}
__device__ __forceinline__ uint32_t lds32(const char* smem, int off) {
    return *(const uint32_t*)(smem + off);
}
__device__ __forceinline__ uint32_t lds16x2(const char* smem, int off_lo, int off_hi) {
    uint32_t lo = *(const uint16_t*)(smem + off_lo);
    uint32_t hi = *(const uint16_t*)(smem + off_hi);
    return lo | (hi << 16);
}

// ---------------- mask dtype sniffing (verified R1) ----------------
__global__ void detect_mask_kernel(const unsigned int* __restrict__ w)
{
    __shared__ unsigned int f;
    if (threadIdx.x == 0) f = 0u;
    __syncthreads();
    unsigned int loc = 0u;
    for (int i = threadIdx.x; i < 4096; i += 256) {
        unsigned int x = w[i];
        if (x == 0x3F803F80u || x == 0x00003F80u) loc |= 8u;
        if (x == 0x3F800000u)                     loc |= 4u;
        if (x > 1u)                               loc |= 2u;
    }
    atomicOr(&f, loc);
    __syncthreads();
    if (threadIdx.x == 0) {
        unsigned int ff = f;
        g_mask_mode = (ff & 8u) ? 3 : (ff & 4u) ? 2 : (ff & 2u) ? 1 : 0;
    }
}
__global__ void convert_mask_kernel(const void* __restrict__ m, int n)
{
    int i = blockIdx.x * blockDim.x + threadIdx.x;
    if (i >= n) return;
    int mode = g_mask_mode;
    float v;
    if (mode == 0)      v = (float)((const int*)m)[i];
    else if (mode == 1) v = (float)((const unsigned char*)m)[i];
    else if (mode == 2) v = ((const float*)m)[i];
    else {
        unsigned short h = ((const unsigned short*)m)[i];
        v = __uint_as_float(((unsigned int)h) << 16);
    }
    g_maskf[i] = v;
}

// ---------------- fp16 double-half splits ----------------
__global__ __launch_bounds__(256)
void split_kernel(const float4* __restrict__ src, __half2* __restrict__ h0,
                  __half2* __restrict__ h1, int n4)
{
    int i = blockIdx.x * blockDim.x + threadIdx.x;
    if (i >= n4) return;
    float4 x = src[i];
    __half a0 = __float2half_rn(x.x); __half b0 = __float2half_rn(x.x - __half2float(a0));
    __half a1 = __float2half_rn(x.y); __half b1 = __float2half_rn(x.y - __half2float(a1));
    __half a2 = __float2half_rn(x.z); __half b2 = __float2half_rn(x.z - __half2float(a2));
    __half a3 = __float2half_rn(x.w); __half b3 = __float2half_rn(x.w - __half2float(a3));
    h0[2*i]   = __halves2half2(a0, a1);
    h0[2*i+1] = __halves2half2(a2, a3);
    h1[2*i]   = __halves2half2(b0, b1);
    h1[2*i+1] = __halves2half2(b2, b3);
}

// W [K=1024, N=1024] -> WT_h0/h1 [N, K] fp16
__global__ __launch_bounds__(256)
void transpose_split_kernel(const float* __restrict__ W,
                            __half* __restrict__ T0, __half* __restrict__ T1)
{
    __shared__ float t[32][33];
    int n0 = blockIdx.x * 32, k0 = blockIdx.y * 32;
    int tx = threadIdx.x & 31, ty = threadIdx.x >> 5;
    for (int r = ty; r < 32; r += 8)
        t[r][tx] = W[(size_t)(k0 + r) * DIM + n0 + tx];
    __syncthreads();
    for (int r = ty; r < 32; r += 8) {
        float x = t[tx][r];
        __half h = __float2half_rn(x);
        size_t o = (size_t)(n0 + r) * DIM + k0 + tx;
        T0[o] = h; T1[o] = __float2half_rn(x - __half2float(h));
    }
}

// ------------- fp16 mma GEMM: 128x128 tile, Kc=32, 2-stage cp.async, 2 CTAs/SM ----
// MODE 0: C = A@B^T + bias      -> fp16 split write      (Q/K projection, 3 products)
// MODE 1: C = tanh(A@B^T+bias)  -> SINGLE fp16 write     (V projection, 3 products)
// MODE 2: C = A@B^T + mask      -> f32 write             (QK^T, 3 products)
// MODE 3: C = (A0+A1)@B0        -> f32 write             (P@V, 2 products, B single)
#define STG02 40960
#define STG3  29184   // A0,A1 tiles (10240 each) + single B tile (8704)

template<int MODE>
__global__ __launch_bounds__(256, 2)
void mma_gemm(const __half* __restrict__ Ah, const __half* __restrict__ Al,
              const __half* __restrict__ Bh, const __half* __restrict__ Bl,
              const float* __restrict__ aux,
              void* __restrict__ out0v, void* __restrict__ out1v,
              int ldA, int ldB, long long sAz, long long sBz,
              int nK, int ldO, long long sOz)
{
    constexpr bool BK  = (MODE == 3);
    constexpr int  STG = BK ? STG3 : STG02;

    extern __shared__ char sm[];
    const uint32_t sb = smem_u32(sm);
    const int tid = threadIdx.x;
    const int lid = tid & 31, wid = tid >> 5;
    const int wm = wid >> 2, wn = wid & 3;      // 2 x 4 warp grid, warp tile 64x32
    const int lx = lid & 3,  ly = lid >> 2;
    const int m0 = blockIdx.y * 128, n0 = blockIdx.x * 128, z = blockIdx.z;
    const int nst = nK / 32;

    const __half* Agh = Ah + (size_t)z * sAz;
    const __half* Agl = Al + (size_t)z * sAz;
    const __half* Bgh = Bh + (size_t)z * sBz;
    const __half* Bgl = Bl + (size_t)z * sBz;

    float acc[4][4][4];
#pragma unroll
    for (int a = 0; a < 4; a++)
#pragma unroll
        for (int b = 0; b < 4; b++)
#pragma unroll
            for (int c = 0; c < 4; c++) acc[a][b][c] = 0.f;

    // ---- producer: fill stage SLOT st with k-chunk kt (32 k) ----
    auto issue = [&](int st, int kt) {
        uint32_t base = sb + (uint32_t)st * STG;
        // A tiles: 128 rows x 4 chunks (16B = 8 halfs), row stride 80 B
#pragma unroll
        for (int i = 0; i < 2; i++) {
            int q = i * 256 + tid; int r = q >> 2, c = q & 3;
            uint32_t d = (uint32_t)(r * 80 + c * 16);
            cp16(base + d,         Agh + (size_t)(m0 + r) * ldA + kt + c * 8);
            cp16(base + 10240 + d, Agl + (size_t)(m0 + r) * ldA + kt + c * 8);
        }
        uint32_t bb = base + 20480;
        if (!BK) {
#pragma unroll
            for (int i = 0; i < 2; i++) {
                int q = i * 256 + tid; int r = q >> 2, c = q & 3;
                uint32_t d = (uint32_t)(r * 80 + c * 16);
                cp16(bb + d,         Bgh + (size_t)(n0 + r) * ldB + kt + c * 8);
                cp16(bb + 10240 + d, Bgl + (size_t)(n0 + r) * ldB + kt + c * 8);
            }
        } else {
            // single B tile: 32 k-rows x 16 chunks, row stride 272 B
#pragma unroll
            for (int i = 0; i < 2; i++) {
                int q = i * 256 + tid; int r = q >> 4, c = q & 15;
                uint32_t d = (uint32_t)(r * 272 + c * 16);
                cp16(bb + d, Bgh + (size_t)(kt + r) * ldB + n0 + c * 8);
            }
        }
        cp_commit();
    };

    issue(0, 0); issue(1, 32);

    // per-thread A row byte bases
    int rowA[4];
#pragma unroll
    for (int mt = 0; mt < 4; mt++) rowA[mt] = (wm * 64 + mt * 16 + ly) * 80 + 4 * lx;
    int rowB[4];
#pragma unroll
    for (int nt = 0; nt < 4; nt++) {
        if (!BK) rowB[nt] = (wn * 32 + nt * 8 + ly) * 80 + 4 * lx;
        else     rowB[nt] = wn * 32 + nt * 8 + ly;   // column index
    }

#pragma unroll 1
    for (int it = 0; it < nst; it++) {
        if (it + 1 < nst) cp_wait<1>();
        else              cp_wait<0>();
        __syncthreads();
        const char* S0 = sm + (it & 1) * STG;
        const char* A0t = S0;
        const char* A1t = S0 + 10240;
        const char* B0t = S0 + 20480;
        const char* B1t = S0 + 30720;   // modes 0-2 only

#pragma unroll
        for (int ks = 0; ks < 2; ks++) {
            const int kb = ks * 32;                 // byte offset of k16 slice (16 halfs)
            uint32_t a0[4][4], a1[4][4];
#pragma unroll
            for (int mt = 0; mt < 4; mt++) {
                int o = rowA[mt] + kb;
                a0[mt][0] = lds32(A0t, o);        a0[mt][1] = lds32(A0t, o + 640);
                a0[mt][2] = lds32(A0t, o + 16);   a0[mt][3] = lds32(A0t, o + 656);
                a1[mt][0] = lds32(A1t, o);        a1[mt][1] = lds32(A1t, o + 640);
                a1[mt][2] = lds32(A1t, o + 16);   a1[mt][3] = lds32(A1t, o + 656);
            }
            uint32_t b0[4][2], b1[4][2];
#pragma unroll
            for (int nt = 0; nt < 4; nt++) {
                if (!BK) {
                    int o = rowB[nt] + kb;
                    b0[nt][0] = lds32(B0t, o); b0[nt][1] = lds32(B0t, o + 16);
                    b1[nt][0] = lds32(B1t, o); b1[nt][1] = lds32(B1t, o + 16);
                } else {
                    int krow = (kb >> 1) + 2 * lx;        // k index = ks*16 + 2lx
                    int base0 = krow * 272 + rowB[nt] * 2;
                    b0[nt][0] = lds16x2(B0t, base0,        base0 + 272);
                    b0[nt][1] = lds16x2(B0t, base0 + 2176, base0 + 2448);
                }
            }
            if (!BK) {
#pragma unroll
                for (int mt = 0; mt < 4; mt++)
#pragma unroll
                    for (int nt = 0; nt < 4; nt++) {
                        mma16(acc[mt][nt], a0[mt], b0[nt]);
                        mma16(acc[mt][nt], a0[mt], b1[nt]);
                        mma16(acc[mt][nt], a1[mt], b0[nt]);
                    }
            } else {
#pragma unroll
                for (int mt = 0; mt < 4; mt++)
#pragma unroll
                    for (int nt = 0; nt < 4; nt++) {
                        mma16(acc[mt][nt], a0[mt], b0[nt]);
                        mma16(acc[mt][nt], a1[mt], b0[nt]);
                    }
            }
        }
        __syncthreads();
        if (it + 2 < nst) issue(it & 1, (it + 2) * 32);
    }

    // ---- epilogue ----
#pragma unroll
    for (int mt = 0; mt < 4; mt++) {
#pragma unroll
        for (int hf = 0; hf < 2; hf++) {
            const int gm = m0 + wm * 64 + mt * 16 + ly + hf * 8;
#pragma unroll
            for (int nt = 0; nt < 4; nt++) {
                const int col = n0 + wn * 32 + nt * 8 + 2 * lx;
                float c0 = acc[mt][nt][hf * 2 + 0];
                float c1 = acc[mt][nt][hf * 2 + 1];
                if (MODE == 0) {
                    float x0 = c0 + aux[col], x1 = c1 + aux[col + 1];
                    __half h0 = __float2half_rn(x0), h1 = __float2half_rn(x1);
                    __half l0 = __float2half_rn(x0 - __half2float(h0));
                    __half l1 = __float2half_rn(x1 - __half2float(h1));
                    *(__half2*)((__half*)out0v + (size_t)gm * ldO + col) = __halves2half2(h0, h1);
                    *(__half2*)((__half*)out1v + (size_t)gm * ldO + col) = __halves2half2(l0, l1);
                } else if (MODE == 1) {
                    float x0 = tanhf(c0 + aux[col]), x1 = tanhf(c1 + aux[col + 1]);
                    *(__half2*)((__half*)out0v + (size_t)gm * ldO + col) =
                        __halves2half2(__float2half_rn(x0), __float2half_rn(x1));
                } else if (MODE == 2) {
                    float x0 = c0 + aux[(size_t)z * SKL + col];
                    float x1 = c1 + aux[(size_t)z * SKL + col + 1];
                    *(float2*)((float*)out0v + (size_t)z * sOz + (size_t)gm * ldO + col) =
                        make_float2(x0, x1);
                } else {
                    *(float2*)((float*)out0v + (size_t)z * sOz + (size_t)gm * ldO + col) =
                        make_float2(c0, c1);
                }
            }
        }
    }
}

// ------------- softmax: read f32 S row, write fp16-split P -------------
__global__ __launch_bounds__(256)
void softmax_rows(const float* __restrict__ S, __half* __restrict__ P0,
                  __half* __restrict__ P1)
{
    const float* row = S + (size_t)blockIdx.x * SKL;
    __half* r0 = P0 + (size_t)blockIdx.x * SKL;
    __half* r1 = P1 + (size_t)blockIdx.x * SKL;
    const int t = threadIdx.x;
    float v[8];
    float mx = -INFINITY;
#pragma unroll
    for (int i = 0; i < 8; i++) { v[i] = row[t + i * 256]; mx = fmaxf(mx, v[i]); }

    __shared__ float red[256];
    red[t] = mx; __syncthreads();
#pragma unroll
    for (int s = 128; s > 0; s >>= 1) {
        if (t < s) red[t] = fmaxf(red[t], red[t + s]);
        __syncthreads();
    }
    mx = red[0];
    __syncthreads();

    float sum = 0.f;
#pragma unroll
    for (int i = 0; i < 8; i++) { v[i] = __expf(v[i] - mx); sum += v[i]; }
    red[t] = sum; __syncthreads();
#pragma unroll
    for (int s = 128; s > 0; s >>= 1) {
        if (t < s) red[t] += red[t + s];
        __syncthreads();
    }
    const float inv = 1.0f / red[0];
#pragma unroll
    for (int i = 0; i < 8; i++) {
        float p = v[i] * inv;
        __half h = __float2half_rn(p);
        r0[t + i * 256] = h;
        r1[t + i * 256] = __float2half_rn(p - __half2float(h));
    }
}

// ---------------- launch ----------------
extern "C" void kernel_launch(void* const* d_in, const int* in_sizes, int n_in,
                              void* d_out, int out_size)
{
    const float* q    = (const float*)d_in[0];
    const float* k    = (const float*)d_in[1];
    const float* v    = (const float*)d_in[2];
    const void*  mask = d_in[3];
    const float* Wq   = (const float*)d_in[4];
    const float* bq   = (const float*)d_in[5];
    const float* Wk   = (const float*)d_in[6];
    const float* bk   = (const float*)d_in[7];
    const float* Wv   = (const float*)d_in[8];
    const float* bvp  = (const float*)d_in[9];
    float* out        = (float*)d_out;

    __half *q0, *q1, *k0, *k1, *v0, *v1;
    __half *Wq0, *Wq1, *Wk0, *Wk1, *Wv0, *Wv1;
    __half *Qp0, *Qp1, *Kp0, *Kp1, *Vp0, *P0, *P1;
    float *S, *maskf;
    cudaGetSymbolAddress((void**)&q0, g_q0);   cudaGetSymbolAddress((void**)&q1, g_q1);
    cudaGetSymbolAddress((void**)&k0, g_k0);   cudaGetSymbolAddress((void**)&k1, g_k1);
    cudaGetSymbolAddress((void**)&v0, g_v0);   cudaGetSymbolAddress((void**)&v1, g_v1);
    cudaGetSymbolAddress((void**)&Wq0, g_Wq0); cudaGetSymbolAddress((void**)&Wq1, g_Wq1);
    cudaGetSymbolAddress((void**)&Wk0, g_Wk0); cudaGetSymbolAddress((void**)&Wk1, g_Wk1);
    cudaGetSymbolAddress((void**)&Wv0, g_Wv0); cudaGetSymbolAddress((void**)&Wv1, g_Wv1);
    cudaGetSymbolAddress((void**)&Qp0, g_Qp0); cudaGetSymbolAddress((void**)&Qp1, g_Qp1);
    cudaGetSymbolAddress((void**)&Kp0, g_Kp0); cudaGetSymbolAddress((void**)&Kp1, g_Kp1);
    cudaGetSymbolAddress((void**)&Vp0, g_Vp0);
    cudaGetSymbolAddress((void**)&P0, g_P0);   cudaGetSymbolAddress((void**)&P1, g_P1);
    cudaGetSymbolAddress((void**)&S, g_S);     cudaGetSymbolAddress((void**)&maskf, g_maskf);

    // mask -> float
    detect_mask_kernel<<<1, 256>>>((const unsigned int*)mask);
    convert_mask_kernel<<<(BATCH * SKL + 255) / 256, 256>>>(mask, BATCH * SKL);

    // split inputs into fp16 pairs
    {
        int n4 = (int)(NELEM / 4);
        int nb = (n4 + 255) / 256;
        split_kernel<<<nb, 256>>>((const float4*)q, (__half2*)q0, (__half2*)q1, n4);
        split_kernel<<<nb, 256>>>((const float4*)k, (__half2*)k0, (__half2*)k1, n4);
        split_kernel<<<nb, 256>>>((const float4*)v, (__half2*)v0, (__half2*)v1, n4);
    }
    // transpose + split weights -> [N][K] fp16
    {
        dim3 g(DIM / 32, DIM / 32);
        transpose_split_kernel<<<g, 256>>>(Wq, Wq0, Wq1);
        transpose_split_kernel<<<g, 256>>>(Wk, Wk0, Wk1);
        transpose_split_kernel<<<g, 256>>>(Wv, Wv0, Wv1);
    }

    const int SMEM02 = 2 * STG02;   // 81920 B -> 2 CTAs/SM
    const int SMEM3  = 2 * STG3;    // 58368 B -> 2 CTAs/SM
    cudaFuncSetAttribute(mma_gemm<0>, cudaFuncAttributeMaxDynamicSharedMemorySize, SMEM02);
    cudaFuncSetAttribute(mma_gemm<1>, cudaFuncAttributeMaxDynamicSharedMemorySize, SMEM02);
    cudaFuncSetAttribute(mma_gemm<2>, cudaFuncAttributeMaxDynamicSharedMemorySize, SMEM02);
    cudaFuncSetAttribute(mma_gemm<3>, cudaFuncAttributeMaxDynamicSharedMemorySize, SMEM3);

    // Projections: M = B*SQL = 16384 rows, N = 1024
    {
        dim3 grid(DIM / 128, (BATCH * SQL) / 128, 1);
        mma_gemm<0><<<grid, 256, SMEM02>>>(q0, q1, Wq0, Wq1, bq, Qp0, Qp1,
                                           DIM, DIM, 0, 0, DIM, DIM, 0);
        mma_gemm<0><<<grid, 256, SMEM02>>>(k0, k1, Wk0, Wk1, bk, Kp0, Kp1,
                                           DIM, DIM, 0, 0, DIM, DIM, 0);
        mma_gemm<1><<<grid, 256, SMEM02>>>(v0, v1, Wv0, Wv1, bvp, Vp0, nullptr,
                                           DIM, DIM, 0, 0, DIM, DIM, 0);
    }

    // S = Qp @ Kp^T + mask (batched)
    {
        dim3 grid(SKL / 128, SQL / 128, BATCH);
        mma_gemm<2><<<grid, 256, SMEM02>>>(Qp0, Qp1, Kp0, Kp1, maskf, S, nullptr,
                                           DIM, DIM, (long long)SQL * DIM,
                                           (long long)SKL * DIM, DIM, SKL,
                                           (long long)SQL * SKL);
    }

    // softmax rows -> fp16 split P
    softmax_rows<<<BATCH * SQL, 256>>>(S, P0, P1);

    // out = (P0+P1) @ Vp0  (batched, B stored [K=sk][N=dv], single B)
    {
        dim3 grid(DIM / 128, SQL / 128, BATCH);
        mma_gemm<3><<<grid, 256, SMEM3>>>(P0, P1, Vp0, Vp0, nullptr, out, nullptr,
                                          SKL, DIM, (long long)SQL * SKL,
                                          (long long)SKL * DIM, SKL, DIM,
                                          (long long)SQL * DIM);
    }
}

// round 9
// speedup vs baseline: 2.0305x; 1.0826x over previous
#include <cuda_runtime.h>
#include <cuda_fp16.h>
#include <cstdint>
#include <math.h>

// Problem dims
#define BATCH 8
#define SQL   2048
#define SKL   2048
#define DIM   1024

#define NELEM ((size_t)BATCH * SQL * DIM)      // 16.8M elements

// ---------------- device scratch (static) ----------------
__device__ __half g_q0[NELEM], g_q1[NELEM];
__device__ __half g_k0[NELEM], g_k1[NELEM];
__device__ __half g_v0[NELEM], g_v1[NELEM];
__device__ __half g_Wq0[DIM*DIM], g_Wq1[DIM*DIM];   // transposed [N][K]
__device__ __half g_Wk0[DIM*DIM], g_Wk1[DIM*DIM];
__device__ __half g_Wv0[DIM*DIM], g_Wv1[DIM*DIM];
__device__ __half g_Qp0[NELEM], g_Qp1[NELEM];
__device__ __half g_Kp0[NELEM], g_Kp1[NELEM];
__device__ __half g_Vp0[NELEM];                     // single fp16 V
__device__ float  g_S[(size_t)BATCH * SQL * SKL];   // scores (f32)
__device__ __half g_P0[(size_t)BATCH * SQL * SKL];  // softmax P (single fp16)
__device__ float  g_maskf[BATCH * SKL];
__device__ int    g_mask_mode;

// ---------------- small helpers ----------------
__device__ __forceinline__ uint32_t smem_u32(const void* p) {
    uint32_t a;
    asm("{ .reg .u64 t; cvta.to.shared.u64 t, %1; cvt.u32.u64 %0, t; }" : "=r"(a) : "l"(p));
    return a;
}
__device__ __forceinline__ void cp16(uint32_t dst, const void* src) {
    asm volatile("cp.async.cg.shared.global [%0], [%1], 16;" :: "r"(dst), "l"(src) : "memory");
}
__device__ __forceinline__ void cp_commit() {
    asm volatile("cp.async.commit_group;" ::: "memory");
}
template<int N> __device__ __forceinline__ void cp_wait() {
    asm volatile("cp.async.wait_group %0;" :: "n"(N) : "memory");
}
// mma.sync m16n8k16 f16 -> f32 accum
__device__ __forceinline__ void mma16(float* c, const uint32_t* a, const uint32_t* b) {
    asm volatile(
        "mma.sync.aligned.m16n8k16.row.col.f32.f16.f16.f32 "
        "{%0,%1,%2,%3}, {%4,%5,%6,%7}, {%8,%9}, {%0,%1,%2,%3};"
        : "+f"(c[0]), "+f"(c[1]), "+f"(c[2]), "+f"(c[3])
        : "r"(a[0]), "r"(a[1]), "r"(a[2]), "r"(a[3]), "r"(b[0]), "r"(b[1]));
}
__device__ __forceinline__ uint32_t lds32(const char* smem, int off) {
    return *(const uint32_t*)(smem + off);
}
__device__ __forceinline__ uint32_t lds16x2(const char* smem, int off_lo, int off_hi) {
    uint32_t lo = *(const uint16_t*)(smem + off_lo);
    uint32_t hi = *(const uint16_t*)(smem + off_hi);
    return lo | (hi << 16);
}

// ---------------- mask dtype sniffing (verified R1) ----------------
__global__ void detect_mask_kernel(const unsigned int* __restrict__ w)
{
    __shared__ unsigned int f;
    if (threadIdx.x == 0) f = 0u;
    __syncthreads();
    unsigned int loc = 0u;
    for (int i = threadIdx.x; i < 4096; i += 256) {
        unsigned int x = w[i];
        if (x == 0x3F803F80u || x == 0x00003F80u) loc |= 8u;
        if (x == 0x3F800000u)                     loc |= 4u;
        if (x > 1u)                               loc |= 2u;
    }
    atomicOr(&f, loc);
    __syncthreads();
    if (threadIdx.x == 0) {
        unsigned int ff = f;
        g_mask_mode = (ff & 8u) ? 3 : (ff & 4u) ? 2 : (ff & 2u) ? 1 : 0;
    }
}
__global__ void convert_mask_kernel(const void* __restrict__ m, int n)
{
    int i = blockIdx.x * blockDim.x + threadIdx.x;
    if (i >= n) return;
    int mode = g_mask_mode;
    float v;
    if (mode == 0)      v = (float)((const int*)m)[i];
    else if (mode == 1) v = (float)((const unsigned char*)m)[i];
    else if (mode == 2) v = ((const float*)m)[i];
    else {
        unsigned short h = ((const unsigned short*)m)[i];
        v = __uint_as_float(((unsigned int)h) << 16);
    }
    g_maskf[i] = v;
}

// ---------------- fp16 double-half splits ----------------
__global__ __launch_bounds__(256)
void split_kernel(const float4* __restrict__ src, __half2* __restrict__ h0,
                  __half2* __restrict__ h1, int n4)
{
    int i = blockIdx.x * blockDim.x + threadIdx.x;
    if (i >= n4) return;
    float4 x = src[i];
    __half a0 = __float2half_rn(x.x); __half b0 = __float2half_rn(x.x - __half2float(a0));
    __half a1 = __float2half_rn(x.y); __half b1 = __float2half_rn(x.y - __half2float(a1));
    __half a2 = __float2half_rn(x.z); __half b2 = __float2half_rn(x.z - __half2float(a2));
    __half a3 = __float2half_rn(x.w); __half b3 = __float2half_rn(x.w - __half2float(a3));
    h0[2*i]   = __halves2half2(a0, a1);
    h0[2*i+1] = __halves2half2(a2, a3);
    h1[2*i]   = __halves2half2(b0, b1);
    h1[2*i+1] = __halves2half2(b2, b3);
}

// W [K=1024, N=1024] -> WT_h0/h1 [N, K] fp16
__global__ __launch_bounds__(256)
void transpose_split_kernel(const float* __restrict__ W,
                            __half* __restrict__ T0, __half* __restrict__ T1)
{
    __shared__ float t[32][33];
    int n0 = blockIdx.x * 32, k0 = blockIdx.y * 32;
    int tx = threadIdx.x & 31, ty = threadIdx.x >> 5;
    for (int r = ty; r < 32; r += 8)
        t[r][tx] = W[(size_t)(k0 + r) * DIM + n0 + tx];
    __syncthreads();
    for (int r = ty; r < 32; r += 8) {
        float x = t[tx][r];
        __half h = __float2half_rn(x);
        size_t o = (size_t)(n0 + r) * DIM + k0 + tx;
        T0[o] = h; T1[o] = __float2half_rn(x - __half2float(h));
    }
}

// ------------- fp16 mma GEMM: 128x128 tile, Kc=32, 2-stage cp.async, 2 CTAs/SM ----
// MODE 0: C = A@B^T + bias      -> fp16 split write      (Q/K projection, 3 products)
// MODE 1: C = tanh(A@B^T+bias)  -> SINGLE fp16 write     (V projection, 3 products)
// MODE 2: C = A@B^T + mask      -> f32 write             (QK^T, 3 products)
// MODE 3: C = A0@B0             -> f32 write             (P@V, SINGLE product)
#define STG02 40960
#define STG3  18944   // single A tile (10240) + single B tile (8704)

template<int MODE>
__global__ __launch_bounds__(256, 2)
void mma_gemm(const __half* __restrict__ Ah, const __half* __restrict__ Al,
              const __half* __restrict__ Bh, const __half* __restrict__ Bl,
              const float* __restrict__ aux,
              void* __restrict__ out0v, void* __restrict__ out1v,
              int ldA, int ldB, long long sAz, long long sBz,
              int nK, int ldO, long long sOz)
{
    constexpr bool BK  = (MODE == 3);   // B is [K][N]; single-product path
    constexpr int  STG = BK ? STG3 : STG02;

    extern __shared__ char sm[];
    const uint32_t sb = smem_u32(sm);
    const int tid = threadIdx.x;
    const int lid = tid & 31, wid = tid >> 5;
    const int wm = wid >> 2, wn = wid & 3;      // 2 x 4 warp grid, warp tile 64x32
    const int lx = lid & 3,  ly = lid >> 2;
    const int m0 = blockIdx.y * 128, n0 = blockIdx.x * 128, z = blockIdx.z;
    const int nst = nK / 32;

    const __half* Agh = Ah + (size_t)z * sAz;
    const __half* Agl = Al + (size_t)z * sAz;
    const __half* Bgh = Bh + (size_t)z * sBz;
    const __half* Bgl = Bl + (size_t)z * sBz;

    float acc[4][4][4];
#pragma unroll
    for (int a = 0; a < 4; a++)
#pragma unroll
        for (int b = 0; b < 4; b++)
#pragma unroll
            for (int c = 0; c < 4; c++) acc[a][b][c] = 0.f;

    // ---- producer: fill stage SLOT st with k-chunk kt (32 k) ----
    auto issue = [&](int st, int kt) {
        uint32_t base = sb + (uint32_t)st * STG;
        // A tile(s): 128 rows x 4 chunks (16B = 8 halfs), row stride 80 B
#pragma unroll
        for (int i = 0; i < 2; i++) {
            int q = i * 256 + tid; int r = q >> 2, c = q & 3;
            uint32_t d = (uint32_t)(r * 80 + c * 16);
            cp16(base + d, Agh + (size_t)(m0 + r) * ldA + kt + c * 8);
            if (!BK) cp16(base + 10240 + d, Agl + (size_t)(m0 + r) * ldA + kt + c * 8);
        }
        uint32_t bb = base + (BK ? 10240u : 20480u);
        if (!BK) {
#pragma unroll
            for (int i = 0; i < 2; i++) {
                int q = i * 256 + tid; int r = q >> 2, c = q & 3;
                uint32_t d = (uint32_t)(r * 80 + c * 16);
                cp16(bb + d,         Bgh + (size_t)(n0 + r) * ldB + kt + c * 8);
                cp16(bb + 10240 + d, Bgl + (size_t)(n0 + r) * ldB + kt + c * 8);
            }
        } else {
            // single B tile: 32 k-rows x 16 chunks, row stride 272 B
#pragma unroll
            for (int i = 0; i < 2; i++) {
                int q = i * 256 + tid; int r = q >> 4, c = q & 15;
                uint32_t d = (uint32_t)(r * 272 + c * 16);
                cp16(bb + d, Bgh + (size_t)(kt + r) * ldB + n0 + c * 8);
            }
        }
        cp_commit();
    };

    issue(0, 0); issue(1, 32);

    // per-thread A row byte bases
    int rowA[4];
#pragma unroll
    for (int mt = 0; mt < 4; mt++) rowA[mt] = (wm * 64 + mt * 16 + ly) * 80 + 4 * lx;
    int rowB[4];
#pragma unroll
    for (int nt = 0; nt < 4; nt++) {
        if (!BK) rowB[nt] = (wn * 32 + nt * 8 + ly) * 80 + 4 * lx;
        else     rowB[nt] = wn * 32 + nt * 8 + ly;   // column index
    }

#pragma unroll 1
    for (int it = 0; it < nst; it++) {
        if (it + 1 < nst) cp_wait<1>();
        else              cp_wait<0>();
        __syncthreads();
        const char* S0 = sm + (it & 1) * STG;
        const char* A0t = S0;
        const char* A1t = S0 + 10240;                  // modes 0-2 only
        const char* B0t = S0 + (BK ? 10240 : 20480);
        const char* B1t = S0 + 30720;                  // modes 0-2 only

#pragma unroll
        for (int ks = 0; ks < 2; ks++) {
            const int kb = ks * 32;                 // byte offset of k16 slice (16 halfs)
            uint32_t a0[4][4], a1[4][4];
#pragma unroll
            for (int mt = 0; mt < 4; mt++) {
                int o = rowA[mt] + kb;
                a0[mt][0] = lds32(A0t, o);        a0[mt][1] = lds32(A0t, o + 640);
                a0[mt][2] = lds32(A0t, o + 16);   a0[mt][3] = lds32(A0t, o + 656);
                if (!BK) {
                    a1[mt][0] = lds32(A1t, o);        a1[mt][1] = lds32(A1t, o + 640);
                    a1[mt][2] = lds32(A1t, o + 16);   a1[mt][3] = lds32(A1t, o + 656);
                }
            }
            uint32_t b0[4][2], b1[4][2];
#pragma unroll
            for (int nt = 0; nt < 4; nt++) {
                if (!BK) {
                    int o = rowB[nt] + kb;
                    b0[nt][0] = lds32(B0t, o); b0[nt][1] = lds32(B0t, o + 16);
                    b1[nt][0] = lds32(B1t, o); b1[nt][1] = lds32(B1t, o + 16);
                } else {
                    int krow = (kb >> 1) + 2 * lx;        // k index = ks*16 + 2lx
                    int base0 = krow * 272 + rowB[nt] * 2;
                    b0[nt][0] = lds16x2(B0t, base0,        base0 + 272);
                    b0[nt][1] = lds16x2(B0t, base0 + 2176, base0 + 2448);
                }
            }
            if (!BK) {
#pragma unroll
                for (int mt = 0; mt < 4; mt++)
#pragma unroll
                    for (int nt = 0; nt < 4; nt++) {
                        mma16(acc[mt][nt], a0[mt], b0[nt]);
                        mma16(acc[mt][nt], a0[mt], b1[nt]);
                        mma16(acc[mt][nt], a1[mt], b0[nt]);
                    }
            } else {
#pragma unroll
                for (int mt = 0; mt < 4; mt++)
#pragma unroll
                    for (int nt = 0; nt < 4; nt++)
                        mma16(acc[mt][nt], a0[mt], b0[nt]);
            }
        }
        __syncthreads();
        if (it + 2 < nst) issue(it & 1, (it + 2) * 32);
    }

    // ---- epilogue ----
#pragma unroll
    for (int mt = 0; mt < 4; mt++) {
#pragma unroll
        for (int hf = 0; hf < 2; hf++) {
            const int gm = m0 + wm * 64 + mt * 16 + ly + hf * 8;
#pragma unroll
            for (int nt = 0; nt < 4; nt++) {
                const int col = n0 + wn * 32 + nt * 8 + 2 * lx;
                float c0 = acc[mt][nt][hf * 2 + 0];
                float c1 = acc[mt][nt][hf * 2 + 1];
                if (MODE == 0) {
                    float x0 = c0 + aux[col], x1 = c1 + aux[col + 1];
                    __half h0 = __float2half_rn(x0), h1 = __float2half_rn(x1);
                    __half l0 = __float2half_rn(x0 - __half2float(h0));
                    __half l1 = __float2half_rn(x1 - __half2float(h1));
                    *(__half2*)((__half*)out0v + (size_t)gm * ldO + col) = __halves2half2(h0, h1);
                    *(__half2*)((__half*)out1v + (size_t)gm * ldO + col) = __halves2half2(l0, l1);
                } else if (MODE == 1) {
                    float x0 = tanhf(c0 + aux[col]), x1 = tanhf(c1 + aux[col + 1]);
                    *(__half2*)((__half*)out0v + (size_t)gm * ldO + col) =
                        __halves2half2(__float2half_rn(x0), __float2half_rn(x1));
                } else if (MODE == 2) {
                    float x0 = c0 + aux[(size_t)z * SKL + col];
                    float x1 = c1 + aux[(size_t)z * SKL + col + 1];
                    *(float2*)((float*)out0v + (size_t)z * sOz + (size_t)gm * ldO + col) =
                        make_float2(x0, x1);
                } else {
                    *(float2*)((float*)out0v + (size_t)z * sOz + (size_t)gm * ldO + col) =
                        make_float2(c0, c1);
                }
            }
        }
    }
}

// ------------- softmax: read f32 S row, write single fp16 P -------------
__global__ __launch_bounds__(256)
void softmax_rows(const float* __restrict__ S, __half* __restrict__ P0)
{
    const float* row = S + (size_t)blockIdx.x * SKL;
    __half* r0 = P0 + (size_t)blockIdx.x * SKL;
    const int t = threadIdx.x;
    float v[8];
    float mx = -INFINITY;
#pragma unroll
    for (int i = 0; i < 8; i++) { v[i] = row[t + i * 256]; mx = fmaxf(mx, v[i]); }

    __shared__ float red[256];
    red[t] = mx; __syncthreads();
#pragma unroll
    for (int s = 128; s > 0; s >>= 1) {
        if (t < s) red[t] = fmaxf(red[t], red[t + s]);
        __syncthreads();
    }
    mx = red[0];
    __syncthreads();

    float sum = 0.f;
#pragma unroll
    for (int i = 0; i < 8; i++) { v[i] = __expf(v[i] - mx); sum += v[i]; }
    red[t] = sum; __syncthreads();
#pragma unroll
    for (int s = 128; s > 0; s >>= 1) {
        if (t < s) red[t] += red[t + s];
        __syncthreads();
    }
    const float inv = 1.0f / red[0];
#pragma unroll
    for (int i = 0; i < 8; i++)
        r0[t + i * 256] = __float2half_rn(v[i] * inv);
}

// ---------------- launch ----------------
extern "C" void kernel_launch(void* const* d_in, const int* in_sizes, int n_in,
                              void* d_out, int out_size)
{
    const float* q    = (const float*)d_in[0];
    const float* k    = (const float*)d_in[1];
    const float* v    = (const float*)d_in[2];
    const void*  mask = d_in[3];
    const float* Wq   = (const float*)d_in[4];
    const float* bq   = (const float*)d_in[5];
    const float* Wk   = (const float*)d_in[6];
    const float* bk   = (const float*)d_in[7];
    const float* Wv   = (const float*)d_in[8];
    const float* bvp  = (const float*)d_in[9];
    float* out        = (float*)d_out;

    __half *q0, *q1, *k0, *k1, *v0, *v1;
    __half *Wq0, *Wq1, *Wk0, *Wk1, *Wv0, *Wv1;
    __half *Qp0, *Qp1, *Kp0, *Kp1, *Vp0, *P0;
    float *S, *maskf;
    cudaGetSymbolAddress((void**)&q0, g_q0);   cudaGetSymbolAddress((void**)&q1, g_q1);
    cudaGetSymbolAddress((void**)&k0, g_k0);   cudaGetSymbolAddress((void**)&k1, g_k1);
    cudaGetSymbolAddress((void**)&v0, g_v0);   cudaGetSymbolAddress((void**)&v1, g_v1);
    cudaGetSymbolAddress((void**)&Wq0, g_Wq0); cudaGetSymbolAddress((void**)&Wq1, g_Wq1);
    cudaGetSymbolAddress((void**)&Wk0, g_Wk0); cudaGetSymbolAddress((void**)&Wk1, g_Wk1);
    cudaGetSymbolAddress((void**)&Wv0, g_Wv0); cudaGetSymbolAddress((void**)&Wv1, g_Wv1);
    cudaGetSymbolAddress((void**)&Qp0, g_Qp0); cudaGetSymbolAddress((void**)&Qp1, g_Qp1);
    cudaGetSymbolAddress((void**)&Kp0, g_Kp0); cudaGetSymbolAddress((void**)&Kp1, g_Kp1);
    cudaGetSymbolAddress((void**)&Vp0, g_Vp0);
    cudaGetSymbolAddress((void**)&P0, g_P0);
    cudaGetSymbolAddress((void**)&S, g_S);     cudaGetSymbolAddress((void**)&maskf, g_maskf);

    // mask -> float
    detect_mask_kernel<<<1, 256>>>((const unsigned int*)mask);
    convert_mask_kernel<<<(BATCH * SKL + 255) / 256, 256>>>(mask, BATCH * SKL);

    // split inputs into fp16 pairs
    {
        int n4 = (int)(NELEM / 4);
        int nb = (n4 + 255) / 256;
        split_kernel<<<nb, 256>>>((const float4*)q, (__half2*)q0, (__half2*)q1, n4);
        split_kernel<<<nb, 256>>>((const float4*)k, (__half2*)k0, (__half2*)k1, n4);
        split_kernel<<<nb, 256>>>((const float4*)v, (__half2*)v0, (__half2*)v1, n4);
    }
    // transpose + split weights -> [N][K] fp16
    {
        dim3 g(DIM / 32, DIM / 32);
        transpose_split_kernel<<<g, 256>>>(Wq, Wq0, Wq1);
        transpose_split_kernel<<<g, 256>>>(Wk, Wk0, Wk1);
        transpose_split_kernel<<<g, 256>>>(Wv, Wv0, Wv1);
    }

    const int SMEM02 = 2 * STG02;   // 81920 B -> 2 CTAs/SM
    const int SMEM3  = 2 * STG3;    // 37888 B -> 2 CTAs/SM
    cudaFuncSetAttribute(mma_gemm<0>, cudaFuncAttributeMaxDynamicSharedMemorySize, SMEM02);
    cudaFuncSetAttribute(mma_gemm<1>, cudaFuncAttributeMaxDynamicSharedMemorySize, SMEM02);
    cudaFuncSetAttribute(mma_gemm<2>, cudaFuncAttributeMaxDynamicSharedMemorySize, SMEM02);
    cudaFuncSetAttribute(mma_gemm<3>, cudaFuncAttributeMaxDynamicSharedMemorySize, SMEM3);

    // Projections: M = B*SQL = 16384 rows, N = 1024
    {
        dim3 grid(DIM / 128, (BATCH * SQL) / 128, 1);
        mma_gemm<0><<<grid, 256, SMEM02>>>(q0, q1, Wq0, Wq1, bq, Qp0, Qp1,
                                           DIM, DIM, 0, 0, DIM, DIM, 0);
        mma_gemm<0><<<grid, 256, SMEM02>>>(k0, k1, Wk0, Wk1, bk, Kp0, Kp1,
                                           DIM, DIM, 0, 0, DIM, DIM, 0);
        mma_gemm<1><<<grid, 256, SMEM02>>>(v0, v1, Wv0, Wv1, bvp, Vp0, nullptr,
                                           DIM, DIM, 0, 0, DIM, DIM, 0);
    }

    // S = Qp @ Kp^T + mask (batched)
    {
        dim3 grid(SKL / 128, SQL / 128, BATCH);
        mma_gemm<2><<<grid, 256, SMEM02>>>(Qp0, Qp1, Kp0, Kp1, maskf, S, nullptr,
                                           DIM, DIM, (long long)SQL * DIM,
                                           (long long)SKL * DIM, DIM, SKL,
                                           (long long)SQL * SKL);
    }

    // softmax rows -> single fp16 P
    softmax_rows<<<BATCH * SQL, 256>>>(S, P0);

    // out = P0 @ Vp0  (batched, single product)
    {
        dim3 grid(DIM / 128, SQL / 128, BATCH);
        mma_gemm<3><<<grid, 256, SMEM3>>>(P0, P0, Vp0, Vp0, nullptr, out, nullptr,
                                          SKL, DIM, (long long)SQL * SKL,
                                          (long long)SKL * DIM, SKL, DIM,
                                          (long long)SQL * DIM);
    }
}

// round 10
// speedup vs baseline: 2.1378x; 1.0528x over previous
#include <cuda_runtime.h>
#include <cuda_fp16.h>
#include <cstdint>
#include <math.h>

// Problem dims
#define BATCH 8
#define SQL   2048
#define SKL   2048
#define DIM   1024

#define NELEM ((size_t)BATCH * SQL * DIM)      // 16.8M elements

// ---------------- device scratch (static) ----------------
__device__ __half g_q0[NELEM], g_q1[NELEM];
__device__ __half g_k0[NELEM], g_k1[NELEM];
__device__ __half g_v0[NELEM];                      // V input single fp16
__device__ __half g_Wq0[DIM*DIM], g_Wq1[DIM*DIM];   // transposed [N][K]
__device__ __half g_Wk0[DIM*DIM], g_Wk1[DIM*DIM];
__device__ __half g_Wv0[DIM*DIM], g_Wv1[DIM*DIM];
__device__ __half g_Qp0[NELEM], g_Qp1[NELEM];
__device__ __half g_Kp0[NELEM], g_Kp1[NELEM];
__device__ __half g_Vp0[NELEM];                     // single fp16 V
__device__ float  g_S[(size_t)BATCH * SQL * SKL];   // scores (f32)
__device__ __half g_P0[(size_t)BATCH * SQL * SKL];  // softmax P (single fp16)
__device__ float  g_maskf[BATCH * SKL];
__device__ int    g_mask_mode;

// ---------------- small helpers ----------------
__device__ __forceinline__ uint32_t smem_u32(const void* p) {
    uint32_t a;
    asm("{ .reg .u64 t; cvta.to.shared.u64 t, %1; cvt.u32.u64 %0, t; }" : "=r"(a) : "l"(p));
    return a;
}
__device__ __forceinline__ void cp16(uint32_t dst, const void* src) {
    asm volatile("cp.async.cg.shared.global [%0], [%1], 16;" :: "r"(dst), "l"(src) : "memory");
}
__device__ __forceinline__ void cp_commit() {
    asm volatile("cp.async.commit_group;" ::: "memory");
}
template<int N> __device__ __forceinline__ void cp_wait() {
    asm volatile("cp.async.wait_group %0;" :: "n"(N) : "memory");
}
// mma.sync m16n8k16 f16 -> f32 accum
__device__ __forceinline__ void mma16(float* c, const uint32_t* a, const uint32_t* b) {
    asm volatile(
        "mma.sync.aligned.m16n8k16.row.col.f32.f16.f16.f32 "
        "{%0,%1,%2,%3}, {%4,%5,%6,%7}, {%8,%9}, {%0,%1,%2,%3};"
        : "+f"(c[0]), "+f"(c[1]), "+f"(c[2]), "+f"(c[3])
        : "r"(a[0]), "r"(a[1]), "r"(a[2]), "r"(a[3]), "r"(b[0]), "r"(b[1]));
}
__device__ __forceinline__ uint32_t lds32(const char* smem, int off) {
    return *(const uint32_t*)(smem + off);
}
__device__ __forceinline__ uint32_t lds16x2(const char* smem, int off_lo, int off_hi) {
    uint32_t lo = *(const uint16_t*)(smem + off_lo);
    uint32_t hi = *(const uint16_t*)(smem + off_hi);
    return lo | (hi << 16);
}

// ---------------- mask dtype sniffing (verified R1) ----------------
__global__ void detect_mask_kernel(const unsigned int* __restrict__ w)
{
    __shared__ unsigned int f;
    if (threadIdx.x == 0) f = 0u;
    __syncthreads();
    unsigned int loc = 0u;
    for (int i = threadIdx.x; i < 4096; i += 256) {
        unsigned int x = w[i];
        if (x == 0x3F803F80u || x == 0x00003F80u) loc |= 8u;
        if (x == 0x3F800000u)                     loc |= 4u;
        if (x > 1u)                               loc |= 2u;
    }
    atomicOr(&f, loc);
    __syncthreads();
    if (threadIdx.x == 0) {
        unsigned int ff = f;
        g_mask_mode = (ff & 8u) ? 3 : (ff & 4u) ? 2 : (ff & 2u) ? 1 : 0;
    }
}
__global__ void convert_mask_kernel(const void* __restrict__ m, int n)
{
    int i = blockIdx.x * blockDim.x + threadIdx.x;
    if (i >= n) return;
    int mode = g_mask_mode;
    float v;
    if (mode == 0)      v = (float)((const int*)m)[i];
    else if (mode == 1) v = (float)((const unsigned char*)m)[i];
    else if (mode == 2) v = ((const float*)m)[i];
    else {
        unsigned short h = ((const unsigned short*)m)[i];
        v = __uint_as_float(((unsigned int)h) << 16);
    }
    g_maskf[i] = v;
}

// ---------------- fp16 double-half split ----------------
__global__ __launch_bounds__(256)
void split_kernel(const float4* __restrict__ src, __half2* __restrict__ h0,
                  __half2* __restrict__ h1, int n4)
{
    int i = blockIdx.x * blockDim.x + threadIdx.x;
    if (i >= n4) return;
    float4 x = src[i];
    __half a0 = __float2half_rn(x.x); __half b0 = __float2half_rn(x.x - __half2float(a0));
    __half a1 = __float2half_rn(x.y); __half b1 = __float2half_rn(x.y - __half2float(a1));
    __half a2 = __float2half_rn(x.z); __half b2 = __float2half_rn(x.z - __half2float(a2));
    __half a3 = __float2half_rn(x.w); __half b3 = __float2half_rn(x.w - __half2float(a3));
    h0[2*i]   = __halves2half2(a0, a1);
    h0[2*i+1] = __halves2half2(a2, a3);
    h1[2*i]   = __halves2half2(b0, b1);
    h1[2*i+1] = __halves2half2(b2, b3);
}

// single fp16 convert (for V input)
__global__ __launch_bounds__(256)
void convert_half_kernel(const float4* __restrict__ src, __half2* __restrict__ h0, int n4)
{
    int i = blockIdx.x * blockDim.x + threadIdx.x;
    if (i >= n4) return;
    float4 x = src[i];
    h0[2*i]   = __halves2half2(__float2half_rn(x.x), __float2half_rn(x.y));
    h0[2*i+1] = __halves2half2(__float2half_rn(x.z), __float2half_rn(x.w));
}

// W [K=1024, N=1024] -> WT_h0/h1 [N, K] fp16
__global__ __launch_bounds__(256)
void transpose_split_kernel(const float* __restrict__ W,
                            __half* __restrict__ T0, __half* __restrict__ T1)
{
    __shared__ float t[32][33];
    int n0 = blockIdx.x * 32, k0 = blockIdx.y * 32;
    int tx = threadIdx.x & 31, ty = threadIdx.x >> 5;
    for (int r = ty; r < 32; r += 8)
        t[r][tx] = W[(size_t)(k0 + r) * DIM + n0 + tx];
    __syncthreads();
    for (int r = ty; r < 32; r += 8) {
        float x = t[tx][r];
        __half h = __float2half_rn(x);
        size_t o = (size_t)(n0 + r) * DIM + k0 + tx;
        T0[o] = h; T1[o] = __float2half_rn(x - __half2float(h));
    }
}

// ------------- fp16 mma GEMM: 128x128 tile, Kc=32, 2-stage cp.async, 2 CTAs/SM ----
// MODE 0: C = A@B^T + bias      -> fp16 split write   (Q/K proj, A split, B split, 3 prod)
// MODE 1: C = tanh(A@B^T+bias)  -> fp16 write         (V proj, A single, B split, 2 prod)
// MODE 2: C = A@B^T + mask      -> f32 write          (QK^T, A split, B split, 3 prod)
// MODE 3: C = A0@B0 (B=[K][N])  -> f32 write          (P@V, single product)
template<int MODE>
__global__ __launch_bounds__(256, 2)
void mma_gemm(const __half* __restrict__ Ah, const __half* __restrict__ Al,
              const __half* __restrict__ Bh, const __half* __restrict__ Bl,
              const float* __restrict__ aux,
              void* __restrict__ out0v, void* __restrict__ out1v,
              int ldA, int ldB, long long sAz, long long sBz,
              int nK, int ldO, long long sOz)
{
    constexpr bool BK     = (MODE == 3);                 // B is [K][N]
    constexpr bool SPLITA = (MODE == 0 || MODE == 2);
    constexpr bool SPLITB = !BK;
    constexpr int  OFF_B0 = SPLITA ? 20480 : 10240;
    constexpr int  STG    = BK ? (10240 + 8704) : (OFF_B0 + 20480);

    extern __shared__ char sm[];
    const uint32_t sb = smem_u32(sm);
    const int tid = threadIdx.x;
    const int lid = tid & 31, wid = tid >> 5;
    const int wm = wid >> 2, wn = wid & 3;      // 2 x 4 warp grid, warp tile 64x32
    const int lx = lid & 3,  ly = lid >> 2;
    const int m0 = blockIdx.y * 128, n0 = blockIdx.x * 128, z = blockIdx.z;
    const int nst = nK / 32;

    const __half* Agh = Ah + (size_t)z * sAz;
    const __half* Agl = Al + (size_t)z * sAz;
    const __half* Bgh = Bh + (size_t)z * sBz;
    const __half* Bgl = Bl + (size_t)z * sBz;

    float acc[4][4][4];
#pragma unroll
    for (int a = 0; a < 4; a++)
#pragma unroll
        for (int b = 0; b < 4; b++)
#pragma unroll
            for (int c = 0; c < 4; c++) acc[a][b][c] = 0.f;

    // ---- producer: fill stage SLOT st with k-chunk kt (32 k) ----
    auto issue = [&](int st, int kt) {
        uint32_t base = sb + (uint32_t)st * STG;
        // A tile(s): 128 rows x 4 chunks (16B = 8 halfs), row stride 80 B
#pragma unroll
        for (int i = 0; i < 2; i++) {
            int q = i * 256 + tid; int r = q >> 2, c = q & 3;
            uint32_t d = (uint32_t)(r * 80 + c * 16);
            cp16(base + d, Agh + (size_t)(m0 + r) * ldA + kt + c * 8);
            if (SPLITA) cp16(base + 10240 + d, Agl + (size_t)(m0 + r) * ldA + kt + c * 8);
        }
        uint32_t bb = base + OFF_B0;
        if (SPLITB) {
#pragma unroll
            for (int i = 0; i < 2; i++) {
                int q = i * 256 + tid; int r = q >> 2, c = q & 3;
                uint32_t d = (uint32_t)(r * 80 + c * 16);
                cp16(bb + d,         Bgh + (size_t)(n0 + r) * ldB + kt + c * 8);
                cp16(bb + 10240 + d, Bgl + (size_t)(n0 + r) * ldB + kt + c * 8);
            }
        } else {
            // single B tile: 32 k-rows x 16 chunks, row stride 272 B
#pragma unroll
            for (int i = 0; i < 2; i++) {
                int q = i * 256 + tid; int r = q >> 4, c = q & 15;
                uint32_t d = (uint32_t)(r * 272 + c * 16);
                cp16(bb + d, Bgh + (size_t)(kt + r) * ldB + n0 + c * 8);
            }
        }
        cp_commit();
    };

    issue(0, 0); issue(1, 32);

    // per-thread A row byte bases
    int rowA[4];
#pragma unroll
    for (int mt = 0; mt < 4; mt++) rowA[mt] = (wm * 64 + mt * 16 + ly) * 80 + 4 * lx;
    int rowB[4];
#pragma unroll
    for (int nt = 0; nt < 4; nt++) {
        if (SPLITB) rowB[nt] = (wn * 32 + nt * 8 + ly) * 80 + 4 * lx;
        else        rowB[nt] = wn * 32 + nt * 8 + ly;   // column index
    }

#pragma unroll 1
    for (int it = 0; it < nst; it++) {
        if (it + 1 < nst) cp_wait<1>();
        else              cp_wait<0>();
        __syncthreads();
        const char* S0 = sm + (it & 1) * STG;
        const char* A0t = S0;
        const char* A1t = S0 + 10240;                  // SPLITA only
        const char* B0t = S0 + OFF_B0;
        const char* B1t = S0 + OFF_B0 + 10240;         // SPLITB only

#pragma unroll
        for (int ks = 0; ks < 2; ks++) {
            const int kb = ks * 32;                 // byte offset of k16 slice (16 halfs)
            uint32_t a0[4][4], a1[4][4];
#pragma unroll
            for (int mt = 0; mt < 4; mt++) {
                int o = rowA[mt] + kb;
                a0[mt][0] = lds32(A0t, o);        a0[mt][1] = lds32(A0t, o + 640);
                a0[mt][2] = lds32(A0t, o + 16);   a0[mt][3] = lds32(A0t, o + 656);
                if (SPLITA) {
                    a1[mt][0] = lds32(A1t, o);        a1[mt][1] = lds32(A1t, o + 640);
                    a1[mt][2] = lds32(A1t, o + 16);   a1[mt][3] = lds32(A1t, o + 656);
                }
            }
            uint32_t b0[4][2], b1[4][2];
#pragma unroll
            for (int nt = 0; nt < 4; nt++) {
                if (SPLITB) {
                    int o = rowB[nt] + kb;
                    b0[nt][0] = lds32(B0t, o); b0[nt][1] = lds32(B0t, o + 16);
                    b1[nt][0] = lds32(B1t, o); b1[nt][1] = lds32(B1t, o + 16);
                } else {
                    int krow = (kb >> 1) + 2 * lx;        // k index = ks*16 + 2lx
                    int base0 = krow * 272 + rowB[nt] * 2;
                    b0[nt][0] = lds16x2(B0t, base0,        base0 + 272);
                    b0[nt][1] = lds16x2(B0t, base0 + 2176, base0 + 2448);
                }
            }
#pragma unroll
            for (int mt = 0; mt < 4; mt++)
#pragma unroll
                for (int nt = 0; nt < 4; nt++) {
                    mma16(acc[mt][nt], a0[mt], b0[nt]);
                    if (SPLITB) mma16(acc[mt][nt], a0[mt], b1[nt]);
                    if (SPLITA) mma16(acc[mt][nt], a1[mt], b0[nt]);
                }
        }
        __syncthreads();
        if (it + 2 < nst) issue(it & 1, (it + 2) * 32);
    }

    // ---- epilogue ----
#pragma unroll
    for (int mt = 0; mt < 4; mt++) {
#pragma unroll
        for (int hf = 0; hf < 2; hf++) {
            const int gm = m0 + wm * 64 + mt * 16 + ly + hf * 8;
#pragma unroll
            for (int nt = 0; nt < 4; nt++) {
                const int col = n0 + wn * 32 + nt * 8 + 2 * lx;
                float c0 = acc[mt][nt][hf * 2 + 0];
                float c1 = acc[mt][nt][hf * 2 + 1];
                if (MODE == 0) {
                    float x0 = c0 + aux[col], x1 = c1 + aux[col + 1];
                    __half h0 = __float2half_rn(x0), h1 = __float2half_rn(x1);
                    __half l0 = __float2half_rn(x0 - __half2float(h0));
                    __half l1 = __float2half_rn(x1 - __half2float(h1));
                    *(__half2*)((__half*)out0v + (size_t)gm * ldO + col) = __halves2half2(h0, h1);
                    *(__half2*)((__half*)out1v + (size_t)gm * ldO + col) = __halves2half2(l0, l1);
                } else if (MODE == 1) {
                    float x0 = tanhf(c0 + aux[col]), x1 = tanhf(c1 + aux[col + 1]);
                    *(__half2*)((__half*)out0v + (size_t)gm * ldO + col) =
                        __halves2half2(__float2half_rn(x0), __float2half_rn(x1));
                } else if (MODE == 2) {
                    float x0 = c0 + aux[(size_t)z * SKL + col];
                    float x1 = c1 + aux[(size_t)z * SKL + col + 1];
                    *(float2*)((float*)out0v + (size_t)z * sOz + (size_t)gm * ldO + col) =
                        make_float2(x0, x1);
                } else {
                    *(float2*)((float*)out0v + (size_t)z * sOz + (size_t)gm * ldO + col) =
                        make_float2(c0, c1);
                }
            }
        }
    }
}

// ------------- softmax: read f32 S row, write single fp16 P -------------
__global__ __launch_bounds__(256)
void softmax_rows(const float* __restrict__ S, __half* __restrict__ P0)
{
    const float* row = S + (size_t)blockIdx.x * SKL;
    __half* r0 = P0 + (size_t)blockIdx.x * SKL;
    const int t = threadIdx.x;
    float v[8];
    float mx = -INFINITY;
#pragma unroll
    for (int i = 0; i < 8; i++) { v[i] = row[t + i * 256]; mx = fmaxf(mx, v[i]); }

    __shared__ float red[256];
    red[t] = mx; __syncthreads();
#pragma unroll
    for (int s = 128; s > 0; s >>= 1) {
        if (t < s) red[t] = fmaxf(red[t], red[t + s]);
        __syncthreads();
    }
    mx = red[0];
    __syncthreads();

    float sum = 0.f;
#pragma unroll
    for (int i = 0; i < 8; i++) { v[i] = __expf(v[i] - mx); sum += v[i]; }
    red[t] = sum; __syncthreads();
#pragma unroll
    for (int s = 128; s > 0; s >>= 1) {
        if (t < s) red[t] += red[t + s];
        __syncthreads();
    }
    const float inv = 1.0f / red[0];
#pragma unroll
    for (int i = 0; i < 8; i++)
        r0[t + i * 256] = __float2half_rn(v[i] * inv);
}

// ---------------- launch ----------------
extern "C" void kernel_launch(void* const* d_in, const int* in_sizes, int n_in,
                              void* d_out, int out_size)
{
    const float* q    = (const float*)d_in[0];
    const float* k    = (const float*)d_in[1];
    const float* v    = (const float*)d_in[2];
    const void*  mask = d_in[3];
    const float* Wq   = (const float*)d_in[4];
    const float* bq   = (const float*)d_in[5];
    const float* Wk   = (const float*)d_in[6];
    const float* bk   = (const float*)d_in[7];
    const float* Wv   = (const float*)d_in[8];
    const float* bvp  = (const float*)d_in[9];
    float* out        = (float*)d_out;

    __half *q0, *q1, *k0, *k1, *v0;
    __half *Wq0, *Wq1, *Wk0, *Wk1, *Wv0, *Wv1;
    __half *Qp0, *Qp1, *Kp0, *Kp1, *Vp0, *P0;
    float *S, *maskf;
    cudaGetSymbolAddress((void**)&q0, g_q0);   cudaGetSymbolAddress((void**)&q1, g_q1);
    cudaGetSymbolAddress((void**)&k0, g_k0);   cudaGetSymbolAddress((void**)&k1, g_k1);
    cudaGetSymbolAddress((void**)&v0, g_v0);
    cudaGetSymbolAddress((void**)&Wq0, g_Wq0); cudaGetSymbolAddress((void**)&Wq1, g_Wq1);
    cudaGetSymbolAddress((void**)&Wk0, g_Wk0); cudaGetSymbolAddress((void**)&Wk1, g_Wk1);
    cudaGetSymbolAddress((void**)&Wv0, g_Wv0); cudaGetSymbolAddress((void**)&Wv1, g_Wv1);
    cudaGetSymbolAddress((void**)&Qp0, g_Qp0); cudaGetSymbolAddress((void**)&Qp1, g_Qp1);
    cudaGetSymbolAddress((void**)&Kp0, g_Kp0); cudaGetSymbolAddress((void**)&Kp1, g_Kp1);
    cudaGetSymbolAddress((void**)&Vp0, g_Vp0);
    cudaGetSymbolAddress((void**)&P0, g_P0);
    cudaGetSymbolAddress((void**)&S, g_S);     cudaGetSymbolAddress((void**)&maskf, g_maskf);

    // mask -> float
    detect_mask_kernel<<<1, 256>>>((const unsigned int*)mask);
    convert_mask_kernel<<<(BATCH * SKL + 255) / 256, 256>>>(mask, BATCH * SKL);

    // split q,k into fp16 pairs; convert v to single fp16
    {
        int n4 = (int)(NELEM / 4);
        int nb = (n4 + 255) / 256;
        split_kernel<<<nb, 256>>>((const float4*)q, (__half2*)q0, (__half2*)q1, n4);
        split_kernel<<<nb, 256>>>((const float4*)k, (__half2*)k0, (__half2*)k1, n4);
        convert_half_kernel<<<nb, 256>>>((const float4*)v, (__half2*)v0, n4);
    }
    // transpose + split weights -> [N][K] fp16
    {
        dim3 g(DIM / 32, DIM / 32);
        transpose_split_kernel<<<g, 256>>>(Wq, Wq0, Wq1);
        transpose_split_kernel<<<g, 256>>>(Wk, Wk0, Wk1);
        transpose_split_kernel<<<g, 256>>>(Wv, Wv0, Wv1);
    }

    const int SMEM02 = 2 * 40960;   // modes 0,2: 81920 B -> 2 CTAs/SM
    const int SMEM1  = 2 * 30720;   // mode 1:   61440 B -> 2 CTAs/SM
    const int SMEM3  = 2 * 18944;   // mode 3:   37888 B -> 2 CTAs/SM
    cudaFuncSetAttribute(mma_gemm<0>, cudaFuncAttributeMaxDynamicSharedMemorySize, SMEM02);
    cudaFuncSetAttribute(mma_gemm<1>, cudaFuncAttributeMaxDynamicSharedMemorySize, SMEM1);
    cudaFuncSetAttribute(mma_gemm<2>, cudaFuncAttributeMaxDynamicSharedMemorySize, SMEM02);
    cudaFuncSetAttribute(mma_gemm<3>, cudaFuncAttributeMaxDynamicSharedMemorySize, SMEM3);

    // Projections: M = B*SQL = 16384 rows, N = 1024
    {
        dim3 grid(DIM / 128, (BATCH * SQL) / 128, 1);
        mma_gemm<0><<<grid, 256, SMEM02>>>(q0, q1, Wq0, Wq1, bq, Qp0, Qp1,
                                           DIM, DIM, 0, 0, DIM, DIM, 0);
        mma_gemm<0><<<grid, 256, SMEM02>>>(k0, k1, Wk0, Wk1, bk, Kp0, Kp1,
                                           DIM, DIM, 0, 0, DIM, DIM, 0);
        // V projection: A single (v0), B split, 2 products
        mma_gemm<1><<<grid, 256, SMEM1>>>(v0, v0, Wv0, Wv1, bvp, Vp0, nullptr,
                                          DIM, DIM, 0, 0, DIM, DIM, 0);
    }

    // S = Qp @ Kp^T + mask (batched)
    {
        dim3 grid(SKL / 128, SQL / 128, BATCH);
        mma_gemm<2><<<grid, 256, SMEM02>>>(Qp0, Qp1, Kp0, Kp1, maskf, S, nullptr,
                                           DIM, DIM, (long long)SQL * DIM,
                                           (long long)SKL * DIM, DIM, SKL,
                                           (long long)SQL * SKL);
    }

    // softmax rows -> single fp16 P
    softmax_rows<<<BATCH * SQL, 256>>>(S, P0);

    // out = P0 @ Vp0  (batched, single product)
    {
        dim3 grid(DIM / 128, SQL / 128, BATCH);
        mma_gemm<3><<<grid, 256, SMEM3>>>(P0, P0, Vp0, Vp0, nullptr, out, nullptr,
                                          SKL, DIM, (long long)SQL * SKL,
                                          (long long)SKL * DIM, SKL, DIM,
                                          (long long)SQL * DIM);
    }
}

// round 11
// speedup vs baseline: 2.1456x; 1.0037x over previous
#include <cuda_runtime.h>
#include <cuda_fp16.h>
#include <cstdint>
#include <math.h>

// Problem dims
#define BATCH 8
#define SQL   2048
#define SKL   2048
#define DIM   1024

#define NELEM ((size_t)BATCH * SQL * DIM)      // 16.8M elements

// ---------------- device scratch (static) ----------------
__device__ __half g_q0[NELEM], g_q1[NELEM];
__device__ __half g_k0[NELEM], g_k1[NELEM];
__device__ __half g_v0[NELEM];                      // V input single fp16
__device__ __half g_Wq0[DIM*DIM], g_Wq1[DIM*DIM];   // transposed [N][K]
__device__ __half g_Wk0[DIM*DIM], g_Wk1[DIM*DIM];
__device__ __half g_Wv0[DIM*DIM], g_Wv1[DIM*DIM];
__device__ __half g_Qp0[NELEM], g_Qp1[NELEM];
__device__ __half g_Kp0[NELEM], g_Kp1[NELEM];
__device__ __half g_Vp0[NELEM];                     // single fp16 V
__device__ float  g_S[(size_t)BATCH * SQL * SKL];   // scores (f32)
__device__ __half g_P0[(size_t)BATCH * SQL * SKL];  // softmax P (single fp16)
__device__ float  g_maskf[BATCH * SKL];
__device__ int    g_mask_mode;

// ---------------- small helpers ----------------
__device__ __forceinline__ uint32_t smem_u32(const void* p) {
    uint32_t a;
    asm("{ .reg .u64 t; cvta.to.shared.u64 t, %1; cvt.u32.u64 %0, t; }" : "=r"(a) : "l"(p));
    return a;
}
__device__ __forceinline__ void cp16(uint32_t dst, const void* src) {
    asm volatile("cp.async.cg.shared.global [%0], [%1], 16;" :: "r"(dst), "l"(src) : "memory");
}
__device__ __forceinline__ void cp_commit() {
    asm volatile("cp.async.commit_group;" ::: "memory");
}
template<int N> __device__ __forceinline__ void cp_wait() {
    asm volatile("cp.async.wait_group %0;" :: "n"(N) : "memory");
}
// mma.sync m16n8k16 f16 -> f32 accum
__device__ __forceinline__ void mma16(float* c, const uint32_t* a, const uint32_t* b) {
    asm volatile(
        "mma.sync.aligned.m16n8k16.row.col.f32.f16.f16.f32 "
        "{%0,%1,%2,%3}, {%4,%5,%6,%7}, {%8,%9}, {%0,%1,%2,%3};"
        : "+f"(c[0]), "+f"(c[1]), "+f"(c[2]), "+f"(c[3])
        : "r"(a[0]), "r"(a[1]), "r"(a[2]), "r"(a[3]), "r"(b[0]), "r"(b[1]));
}
__device__ __forceinline__ uint32_t lds32(const char* smem, int off) {
    return *(const uint32_t*)(smem + off);
}
__device__ __forceinline__ uint32_t lds16x2(const char* smem, int off_lo, int off_hi) {
    uint32_t lo = *(const uint16_t*)(smem + off_lo);
    uint32_t hi = *(const uint16_t*)(smem + off_hi);
    return lo | (hi << 16);
}

// ---------------- mask dtype sniffing (verified R1) ----------------
__global__ void detect_mask_kernel(const unsigned int* __restrict__ w)
{
    __shared__ unsigned int f;
    if (threadIdx.x == 0) f = 0u;
    __syncthreads();
    unsigned int loc = 0u;
    for (int i = threadIdx.x; i < 4096; i += 256) {
        unsigned int x = w[i];
        if (x == 0x3F803F80u || x == 0x00003F80u) loc |= 8u;
        if (x == 0x3F800000u)                     loc |= 4u;
        if (x > 1u)                               loc |= 2u;
    }
    atomicOr(&f, loc);
    __syncthreads();
    if (threadIdx.x == 0) {
        unsigned int ff = f;
        g_mask_mode = (ff & 8u) ? 3 : (ff & 4u) ? 2 : (ff & 2u) ? 1 : 0;
    }
}
__global__ void convert_mask_kernel(const void* __restrict__ m, int n)
{
    int i = blockIdx.x * blockDim.x + threadIdx.x;
    if (i >= n) return;
    int mode = g_mask_mode;
    float v;
    if (mode == 0)      v = (float)((const int*)m)[i];
    else if (mode == 1) v = (float)((const unsigned char*)m)[i];
    else if (mode == 2) v = ((const float*)m)[i];
    else {
        unsigned short h = ((const unsigned short*)m)[i];
        v = __uint_as_float(((unsigned int)h) << 16);
    }
    g_maskf[i] = v;
}

// ---------------- fp16 double-half split ----------------
__global__ __launch_bounds__(256)
void split_kernel(const float4* __restrict__ src, __half2* __restrict__ h0,
                  __half2* __restrict__ h1, int n4)
{
    int i = blockIdx.x * blockDim.x + threadIdx.x;
    if (i >= n4) return;
    float4 x = src[i];
    __half a0 = __float2half_rn(x.x); __half b0 = __float2half_rn(x.x - __half2float(a0));
    __half a1 = __float2half_rn(x.y); __half b1 = __float2half_rn(x.y - __half2float(a1));
    __half a2 = __float2half_rn(x.z); __half b2 = __float2half_rn(x.z - __half2float(a2));
    __half a3 = __float2half_rn(x.w); __half b3 = __float2half_rn(x.w - __half2float(a3));
    h0[2*i]   = __halves2half2(a0, a1);
    h0[2*i+1] = __halves2half2(a2, a3);
    h1[2*i]   = __halves2half2(b0, b1);
    h1[2*i+1] = __halves2half2(b2, b3);
}

// single fp16 convert (for V input)
__global__ __launch_bounds__(256)
void convert_half_kernel(const float4* __restrict__ src, __half2* __restrict__ h0, int n4)
{
    int i = blockIdx.x * blockDim.x + threadIdx.x;
    if (i >= n4) return;
    float4 x = src[i];
    h0[2*i]   = __halves2half2(__float2half_rn(x.x), __float2half_rn(x.y));
    h0[2*i+1] = __halves2half2(__float2half_rn(x.z), __float2half_rn(x.w));
}

// W [K=1024, N=1024] -> WT_h0/h1 [N, K] fp16
__global__ __launch_bounds__(256)
void transpose_split_kernel(const float* __restrict__ W,
                            __half* __restrict__ T0, __half* __restrict__ T1)
{
    __shared__ float t[32][33];
    int n0 = blockIdx.x * 32, k0 = blockIdx.y * 32;
    int tx = threadIdx.x & 31, ty = threadIdx.x >> 5;
    for (int r = ty; r < 32; r += 8)
        t[r][tx] = W[(size_t)(k0 + r) * DIM + n0 + tx];
    __syncthreads();
    for (int r = ty; r < 32; r += 8) {
        float x = t[tx][r];
        __half h = __float2half_rn(x);
        size_t o = (size_t)(n0 + r) * DIM + k0 + tx;
        T0[o] = h; T1[o] = __float2half_rn(x - __half2float(h));
    }
}

// ------------- fp16 mma GEMM: 128x128 tile, Kc=32, 2-stage cp.async, 2 CTAs/SM ----
// MODE 0: C = A@B^T + bias      -> fp16 split write   (Q&K proj MERGED via z, 3 prod)
// MODE 1: C = tanh(A@B^T+bias)  -> fp16 write         (V proj, A single, B split, 2 prod)
// MODE 2: C = A@B^T + mask      -> f32 write          (QK^T, A split, B split, 3 prod)
// MODE 3: C = A0@B0 (B=[K][N])  -> f32 write          (P@V, single product)
// All z-strides are runtime pointer/element offsets: z selects batch (modes 2/3)
// or selects the {Q,K} problem instance (mode 0).
template<int MODE>
__global__ __launch_bounds__(256, 2)
void mma_gemm(const __half* __restrict__ Ah, const __half* __restrict__ Al,
              const __half* __restrict__ Bh, const __half* __restrict__ Bl,
              const float* __restrict__ aux,
              void* __restrict__ out0v, void* __restrict__ out1v,
              int ldA, int ldB,
              long long sAz, long long sAlz, long long sBz, long long sBlz,
              long long sAuxz,
              int nK, int ldO, long long sOz, long long sO1z)
{
    constexpr bool BK     = (MODE == 3);                 // B is [K][N]
    constexpr bool SPLITA = (MODE == 0 || MODE == 2);
    constexpr bool SPLITB = !BK;
    constexpr int  OFF_B0 = SPLITA ? 20480 : 10240;
    constexpr int  STG    = BK ? (10240 + 8704) : (OFF_B0 + 20480);

    extern __shared__ char sm[];
    const uint32_t sb = smem_u32(sm);
    const int tid = threadIdx.x;
    const int lid = tid & 31, wid = tid >> 5;
    const int wm = wid >> 2, wn = wid & 3;      // 2 x 4 warp grid, warp tile 64x32
    const int lx = lid & 3,  ly = lid >> 2;
    const int m0 = blockIdx.y * 128, n0 = blockIdx.x * 128, z = blockIdx.z;
    const int nst = nK / 32;

    const __half* Agh = Ah + (size_t)z * sAz;
    const __half* Agl = Al + (size_t)z * sAlz;
    const __half* Bgh = Bh + (size_t)z * sBz;
    const __half* Bgl = Bl + (size_t)z * sBlz;
    const float*  auxz = aux + (size_t)z * sAuxz;

    float acc[4][4][4];
#pragma unroll
    for (int a = 0; a < 4; a++)
#pragma unroll
        for (int b = 0; b < 4; b++)
#pragma unroll
            for (int c = 0; c < 4; c++) acc[a][b][c] = 0.f;

    // ---- producer: fill stage SLOT st with k-chunk kt (32 k) ----
    auto issue = [&](int st, int kt) {
        uint32_t base = sb + (uint32_t)st * STG;
        // A tile(s): 128 rows x 4 chunks (16B = 8 halfs), row stride 80 B
#pragma unroll
        for (int i = 0; i < 2; i++) {
            int q = i * 256 + tid; int r = q >> 2, c = q & 3;
            uint32_t d = (uint32_t)(r * 80 + c * 16);
            cp16(base + d, Agh + (size_t)(m0 + r) * ldA + kt + c * 8);
            if (SPLITA) cp16(base + 10240 + d, Agl + (size_t)(m0 + r) * ldA + kt + c * 8);
        }
        uint32_t bb = base + OFF_B0;
        if (SPLITB) {
#pragma unroll
            for (int i = 0; i < 2; i++) {
                int q = i * 256 + tid; int r = q >> 2, c = q & 3;
                uint32_t d = (uint32_t)(r * 80 + c * 16);
                cp16(bb + d,         Bgh + (size_t)(n0 + r) * ldB + kt + c * 8);
                cp16(bb + 10240 + d, Bgl + (size_t)(n0 + r) * ldB + kt + c * 8);
            }
        } else {
            // single B tile: 32 k-rows x 16 chunks, row stride 272 B
#pragma unroll
            for (int i = 0; i < 2; i++) {
                int q = i * 256 + tid; int r = q >> 4, c = q & 15;
                uint32_t d = (uint32_t)(r * 272 + c * 16);
                cp16(bb + d, Bgh + (size_t)(kt + r) * ldB + n0 + c * 8);
            }
        }
        cp_commit();
    };

    issue(0, 0); issue(1, 32);

    // per-thread A row byte bases
    int rowA[4];
#pragma unroll
    for (int mt = 0; mt < 4; mt++) rowA[mt] = (wm * 64 + mt * 16 + ly) * 80 + 4 * lx;
    int rowB[4];
#pragma unroll
    for (int nt = 0; nt < 4; nt++) {
        if (SPLITB) rowB[nt] = (wn * 32 + nt * 8 + ly) * 80 + 4 * lx;
        else        rowB[nt] = wn * 32 + nt * 8 + ly;   // column index
    }

#pragma unroll 1
    for (int it = 0; it < nst; it++) {
        if (it + 1 < nst) cp_wait<1>();
        else              cp_wait<0>();
        __syncthreads();
        const char* S0 = sm + (it & 1) * STG;
        const char* A0t = S0;
        const char* A1t = S0 + 10240;                  // SPLITA only
        const char* B0t = S0 + OFF_B0;
        const char* B1t = S0 + OFF_B0 + 10240;         // SPLITB only

#pragma unroll
        for (int ks = 0; ks < 2; ks++) {
            const int kb = ks * 32;                 // byte offset of k16 slice (16 halfs)
            uint32_t a0[4][4], a1[4][4];
#pragma unroll
            for (int mt = 0; mt < 4; mt++) {
                int o = rowA[mt] + kb;
                a0[mt][0] = lds32(A0t, o);        a0[mt][1] = lds32(A0t, o + 640);
                a0[mt][2] = lds32(A0t, o + 16);   a0[mt][3] = lds32(A0t, o + 656);
                if (SPLITA) {
                    a1[mt][0] = lds32(A1t, o);        a1[mt][1] = lds32(A1t, o + 640);
                    a1[mt][2] = lds32(A1t, o + 16);   a1[mt][3] = lds32(A1t, o + 656);
                }
            }
            uint32_t b0[4][2], b1[4][2];
#pragma unroll
            for (int nt = 0; nt < 4; nt++) {
                if (SPLITB) {
                    int o = rowB[nt] + kb;
                    b0[nt][0] = lds32(B0t, o); b0[nt][1] = lds32(B0t, o + 16);
                    b1[nt][0] = lds32(B1t, o); b1[nt][1] = lds32(B1t, o + 16);
                } else {
                    int krow = (kb >> 1) + 2 * lx;        // k index = ks*16 + 2lx
                    int base0 = krow * 272 + rowB[nt] * 2;
                    b0[nt][0] = lds16x2(B0t, base0,        base0 + 272);
                    b0[nt][1] = lds16x2(B0t, base0 + 2176, base0 + 2448);
                }
            }
#pragma unroll
            for (int mt = 0; mt < 4; mt++)
#pragma unroll
                for (int nt = 0; nt < 4; nt++) {
                    mma16(acc[mt][nt], a0[mt], b0[nt]);
                    if (SPLITB) mma16(acc[mt][nt], a0[mt], b1[nt]);
                    if (SPLITA) mma16(acc[mt][nt], a1[mt], b0[nt]);
                }
        }
        __syncthreads();
        if (it + 2 < nst) issue(it & 1, (it + 2) * 32);
    }

    // ---- epilogue ----
#pragma unroll
    for (int mt = 0; mt < 4; mt++) {
#pragma unroll
        for (int hf = 0; hf < 2; hf++) {
            const int gm = m0 + wm * 64 + mt * 16 + ly + hf * 8;
#pragma unroll
            for (int nt = 0; nt < 4; nt++) {
                const int col = n0 + wn * 32 + nt * 8 + 2 * lx;
                float c0 = acc[mt][nt][hf * 2 + 0];
                float c1 = acc[mt][nt][hf * 2 + 1];
                if (MODE == 0) {
                    float x0 = c0 + auxz[col], x1 = c1 + auxz[col + 1];
                    __half h0 = __float2half_rn(x0), h1 = __float2half_rn(x1);
                    __half l0 = __float2half_rn(x0 - __half2float(h0));
                    __half l1 = __float2half_rn(x1 - __half2float(h1));
                    *(__half2*)((__half*)out0v + (size_t)z * sOz + (size_t)gm * ldO + col) =
                        __halves2half2(h0, h1);
                    *(__half2*)((__half*)out1v + (size_t)z * sO1z + (size_t)gm * ldO + col) =
                        __halves2half2(l0, l1);
                } else if (MODE == 1) {
                    float x0 = tanhf(c0 + auxz[col]), x1 = tanhf(c1 + auxz[col + 1]);
                    *(__half2*)((__half*)out0v + (size_t)gm * ldO + col) =
                        __halves2half2(__float2half_rn(x0), __float2half_rn(x1));
                } else if (MODE == 2) {
                    float x0 = c0 + auxz[col];
                    float x1 = c1 + auxz[col + 1];
                    *(float2*)((float*)out0v + (size_t)z * sOz + (size_t)gm * ldO + col) =
                        make_float2(x0, x1);
                } else {
                    *(float2*)((float*)out0v + (size_t)z * sOz + (size_t)gm * ldO + col) =
                        make_float2(c0, c1);
                }
            }
        }
    }
}

// ------------- softmax: read f32 S row, write single fp16 P -------------
__global__ __launch_bounds__(256)
void softmax_rows(const float* __restrict__ S, __half* __restrict__ P0)
{
    const float* row = S + (size_t)blockIdx.x * SKL;
    __half* r0 = P0 + (size_t)blockIdx.x * SKL;
    const int t = threadIdx.x;
    float v[8];
    float mx = -INFINITY;
#pragma unroll
    for (int i = 0; i < 8; i++) { v[i] = row[t + i * 256]; mx = fmaxf(mx, v[i]); }

    __shared__ float red[256];
    red[t] = mx; __syncthreads();
#pragma unroll
    for (int s = 128; s > 0; s >>= 1) {
        if (t < s) red[t] = fmaxf(red[t], red[t + s]);
        __syncthreads();
    }
    mx = red[0];
    __syncthreads();

    float sum = 0.f;
#pragma unroll
    for (int i = 0; i < 8; i++) { v[i] = __expf(v[i] - mx); sum += v[i]; }
    red[t] = sum; __syncthreads();
#pragma unroll
    for (int s = 128; s > 0; s >>= 1) {
        if (t < s) red[t] += red[t + s];
        __syncthreads();
    }
    const float inv = 1.0f / red[0];
#pragma unroll
    for (int i = 0; i < 8; i++)
        r0[t + i * 256] = __float2half_rn(v[i] * inv);
}

// ---------------- launch ----------------
extern "C" void kernel_launch(void* const* d_in, const int* in_sizes, int n_in,
                              void* d_out, int out_size)
{
    const float* q    = (const float*)d_in[0];
    const float* k    = (const float*)d_in[1];
    const float* v    = (const float*)d_in[2];
    const void*  mask = d_in[3];
    const float* Wq   = (const float*)d_in[4];
    const float* bq   = (const float*)d_in[5];
    const float* Wk   = (const float*)d_in[6];
    const float* bk   = (const float*)d_in[7];
    const float* Wv   = (const float*)d_in[8];
    const float* bvp  = (const float*)d_in[9];
    float* out        = (float*)d_out;

    __half *q0, *q1, *k0, *k1, *v0;
    __half *Wq0, *Wq1, *Wk0, *Wk1, *Wv0, *Wv1;
    __half *Qp0, *Qp1, *Kp0, *Kp1, *Vp0, *P0;
    float *S, *maskf;
    cudaGetSymbolAddress((void**)&q0, g_q0);   cudaGetSymbolAddress((void**)&q1, g_q1);
    cudaGetSymbolAddress((void**)&k0, g_k0);   cudaGetSymbolAddress((void**)&k1, g_k1);
    cudaGetSymbolAddress((void**)&v0, g_v0);
    cudaGetSymbolAddress((void**)&Wq0, g_Wq0); cudaGetSymbolAddress((void**)&Wq1, g_Wq1);
    cudaGetSymbolAddress((void**)&Wk0, g_Wk0); cudaGetSymbolAddress((void**)&Wk1, g_Wk1);
    cudaGetSymbolAddress((void**)&Wv0, g_Wv0); cudaGetSymbolAddress((void**)&Wv1, g_Wv1);
    cudaGetSymbolAddress((void**)&Qp0, g_Qp0); cudaGetSymbolAddress((void**)&Qp1, g_Qp1);
    cudaGetSymbolAddress((void**)&Kp0, g_Kp0); cudaGetSymbolAddress((void**)&Kp1, g_Kp1);
    cudaGetSymbolAddress((void**)&Vp0, g_Vp0);
    cudaGetSymbolAddress((void**)&P0, g_P0);
    cudaGetSymbolAddress((void**)&S, g_S);     cudaGetSymbolAddress((void**)&maskf, g_maskf);

    // mask -> float
    detect_mask_kernel<<<1, 256>>>((const unsigned int*)mask);
    convert_mask_kernel<<<(BATCH * SKL + 255) / 256, 256>>>(mask, BATCH * SKL);

    // split q,k into fp16 pairs; convert v to single fp16
    {
        int n4 = (int)(NELEM / 4);
        int nb = (n4 + 255) / 256;
        split_kernel<<<nb, 256>>>((const float4*)q, (__half2*)q0, (__half2*)q1, n4);
        split_kernel<<<nb, 256>>>((const float4*)k, (__half2*)k0, (__half2*)k1, n4);
        convert_half_kernel<<<nb, 256>>>((const float4*)v, (__half2*)v0, n4);
    }
    // transpose + split weights -> [N][K] fp16
    {
        dim3 g(DIM / 32, DIM / 32);
        transpose_split_kernel<<<g, 256>>>(Wq, Wq0, Wq1);
        transpose_split_kernel<<<g, 256>>>(Wk, Wk0, Wk1);
        transpose_split_kernel<<<g, 256>>>(Wv, Wv0, Wv1);
    }

    const int SMEM02 = 2 * 40960;   // modes 0,2: 81920 B -> 2 CTAs/SM
    const int SMEM1  = 2 * 30720;   // mode 1:   61440 B -> 2 CTAs/SM
    const int SMEM3  = 2 * 18944;   // mode 3:   37888 B -> 2 CTAs/SM
    cudaFuncSetAttribute(mma_gemm<0>, cudaFuncAttributeMaxDynamicSharedMemorySize, SMEM02);
    cudaFuncSetAttribute(mma_gemm<1>, cudaFuncAttributeMaxDynamicSharedMemorySize, SMEM1);
    cudaFuncSetAttribute(mma_gemm<2>, cudaFuncAttributeMaxDynamicSharedMemorySize, SMEM02);
    cudaFuncSetAttribute(mma_gemm<3>, cudaFuncAttributeMaxDynamicSharedMemorySize, SMEM3);

    // Q & K projections MERGED: grid z=2 selects problem instance via pointer-diff strides
    {
        dim3 grid(DIM / 128, (BATCH * SQL) / 128, 2);
        long long sAz   = (long long)(k0  - q0);
        long long sAlz  = (long long)(k1  - q1);
        long long sBz   = (long long)(Wk0 - Wq0);
        long long sBlz  = (long long)(Wk1 - Wq1);
        long long sAuxz = (long long)(bk  - bq);
        long long sOz   = (long long)(Kp0 - Qp0);
        long long sO1z  = (long long)(Kp1 - Qp1);
        mma_gemm<0><<<grid, 256, SMEM02>>>(q0, q1, Wq0, Wq1, bq, Qp0, Qp1,
                                           DIM, DIM,
                                           sAz, sAlz, sBz, sBlz, sAuxz,
                                           DIM, DIM, sOz, sO1z);
    }
    // V projection: A single (v0), B split, 2 products
    {
        dim3 grid(DIM / 128, (BATCH * SQL) / 128, 1);
        mma_gemm<1><<<grid, 256, SMEM1>>>(v0, v0, Wv0, Wv1, bvp, Vp0, nullptr,
                                          DIM, DIM, 0, 0, 0, 0, 0,
                                          DIM, DIM, 0, 0);
    }

    // S = Qp @ Kp^T + mask (batched over z)
    {
        dim3 grid(SKL / 128, SQL / 128, BATCH);
        mma_gemm<2><<<grid, 256, SMEM02>>>(Qp0, Qp1, Kp0, Kp1, maskf, S, nullptr,
                                           DIM, DIM,
                                           (long long)SQL * DIM, (long long)SQL * DIM,
                                           (long long)SKL * DIM, (long long)SKL * DIM,
                                           SKL,
                                           DIM, SKL, (long long)SQL * SKL, 0);
    }

    // softmax rows -> single fp16 P
    softmax_rows<<<BATCH * SQL, 256>>>(S, P0);

    // out = P0 @ Vp0  (batched, single product)
    {
        dim3 grid(DIM / 128, SQL / 128, BATCH);
        mma_gemm<3><<<grid, 256, SMEM3>>>(P0, P0, Vp0, Vp0, nullptr, out, nullptr,
                                          SKL, DIM,
                                          (long long)SQL * SKL, (long long)SQL * SKL,
                                          (long long)SKL * DIM, (long long)SKL * DIM,
                                          0,
                                          SKL, DIM, (long long)SQL * DIM, 0);
    }
}

// round 12
// speedup vs baseline: 2.1799x; 1.0160x over previous
#include <cuda_runtime.h>
#include <cuda_fp16.h>
#include <cstdint>
#include <math.h>

// Problem dims
#define BATCH 8
#define SQL   2048
#define SKL   2048
#define DIM   1024

#define NELEM ((size_t)BATCH * SQL * DIM)      // 16.8M elements

// ---------------- device scratch (static) ----------------
__device__ __half g_q0[NELEM], g_q1[NELEM];
__device__ __half g_k0[NELEM], g_k1[NELEM];
__device__ __half g_v0[NELEM];                      // V input single fp16
__device__ __half g_Wq0[DIM*DIM], g_Wq1[DIM*DIM];   // transposed [N][K]
__device__ __half g_Wk0[DIM*DIM], g_Wk1[DIM*DIM];
__device__ __half g_Wv0[DIM*DIM], g_Wv1[DIM*DIM];
__device__ __half g_Qp0[NELEM], g_Qp1[NELEM];
__device__ __half g_Kp0[NELEM], g_Kp1[NELEM];
__device__ __half g_Vp0[NELEM];                     // single fp16 V
__device__ __half g_S16[(size_t)BATCH * SQL * SKL]; // tile-shifted scores (fp16)
__device__ float  g_Tmax[(size_t)BATCH * SQL * 16]; // per-row per-tile max (f32)
__device__ __half g_P0[(size_t)BATCH * SQL * SKL];  // softmax P (single fp16)
__device__ float  g_maskf[BATCH * SKL];
__device__ int    g_mask_mode;

// ---------------- small helpers ----------------
__device__ __forceinline__ uint32_t smem_u32(const void* p) {
    uint32_t a;
    asm("{ .reg .u64 t; cvta.to.shared.u64 t, %1; cvt.u32.u64 %0, t; }" : "=r"(a) : "l"(p));
    return a;
}
__device__ __forceinline__ void cp16(uint32_t dst, const void* src) {
    asm volatile("cp.async.cg.shared.global [%0], [%1], 16;" :: "r"(dst), "l"(src) : "memory");
}
__device__ __forceinline__ void cp_commit() {
    asm volatile("cp.async.commit_group;" ::: "memory");
}
template<int N> __device__ __forceinline__ void cp_wait() {
    asm volatile("cp.async.wait_group %0;" :: "n"(N) : "memory");
}
// mma.sync m16n8k16 f16 -> f32 accum
__device__ __forceinline__ void mma16(float* c, const uint32_t* a, const uint32_t* b) {
    asm volatile(
        "mma.sync.aligned.m16n8k16.row.col.f32.f16.f16.f32 "
        "{%0,%1,%2,%3}, {%4,%5,%6,%7}, {%8,%9}, {%0,%1,%2,%3};"
        : "+f"(c[0]), "+f"(c[1]), "+f"(c[2]), "+f"(c[3])
        : "r"(a[0]), "r"(a[1]), "r"(a[2]), "r"(a[3]), "r"(b[0]), "r"(b[1]));
}
__device__ __forceinline__ uint32_t lds32(const char* smem, int off) {
    return *(const uint32_t*)(smem + off);
}
__device__ __forceinline__ uint32_t lds16x2(const char* smem, int off_lo, int off_hi) {
    uint32_t lo = *(const uint16_t*)(smem + off_lo);
    uint32_t hi = *(const uint16_t*)(smem + off_hi);
    return lo | (hi << 16);
}
// float <-> monotonic unsigned encoding (for atomicMax on floats incl. negatives)
__device__ __forceinline__ unsigned f2o(float f) {
    unsigned u = __float_as_uint(f);
    return (u & 0x80000000u) ? ~u : (u | 0x80000000u);
}
__device__ __forceinline__ float o2f(unsigned u) {
    return (u & 0x80000000u) ? __uint_as_float(u & 0x7FFFFFFFu) : __uint_as_float(~u);
}

// ---------------- mask dtype sniffing (verified R1) ----------------
__global__ void detect_mask_kernel(const unsigned int* __restrict__ w)
{
    __shared__ unsigned int f;
    if (threadIdx.x == 0) f = 0u;
    __syncthreads();
    unsigned int loc = 0u;
    for (int i = threadIdx.x; i < 4096; i += 256) {
        unsigned int x = w[i];
        if (x == 0x3F803F80u || x == 0x00003F80u) loc |= 8u;
        if (x == 0x3F800000u)                     loc |= 4u;
        if (x > 1u)                               loc |= 2u;
    }
    atomicOr(&f, loc);
    __syncthreads();
    if (threadIdx.x == 0) {
        unsigned int ff = f;
        g_mask_mode = (ff & 8u) ? 3 : (ff & 4u) ? 2 : (ff & 2u) ? 1 : 0;
    }
}
__global__ void convert_mask_kernel(const void* __restrict__ m, int n)
{
    int i = blockIdx.x * blockDim.x + threadIdx.x;
    if (i >= n) return;
    int mode = g_mask_mode;
    float v;
    if (mode == 0)      v = (float)((const int*)m)[i];
    else if (mode == 1) v = (float)((const unsigned char*)m)[i];
    else if (mode == 2) v = ((const float*)m)[i];
    else {
        unsigned short h = ((const unsigned short*)m)[i];
        v = __uint_as_float(((unsigned int)h) << 16);
    }
    g_maskf[i] = v;
}

// ---------------- fp16 double-half split ----------------
__global__ __launch_bounds__(256)
void split_kernel(const float4* __restrict__ src, __half2* __restrict__ h0,
                  __half2* __restrict__ h1, int n4)
{
    int i = blockIdx.x * blockDim.x + threadIdx.x;
    if (i >= n4) return;
    float4 x = src[i];
    __half a0 = __float2half_rn(x.x); __half b0 = __float2half_rn(x.x - __half2float(a0));
    __half a1 = __float2half_rn(x.y); __half b1 = __float2half_rn(x.y - __half2float(a1));
    __half a2 = __float2half_rn(x.z); __half b2 = __float2half_rn(x.z - __half2float(a2));
    __half a3 = __float2half_rn(x.w); __half b3 = __float2half_rn(x.w - __half2float(a3));
    h0[2*i]   = __halves2half2(a0, a1);
    h0[2*i+1] = __halves2half2(a2, a3);
    h1[2*i]   = __halves2half2(b0, b1);
    h1[2*i+1] = __halves2half2(b2, b3);
}

// single fp16 convert (for V input)
__global__ __launch_bounds__(256)
void convert_half_kernel(const float4* __restrict__ src, __half2* __restrict__ h0, int n4)
{
    int i = blockIdx.x * blockDim.x + threadIdx.x;
    if (i >= n4) return;
    float4 x = src[i];
    h0[2*i]   = __halves2half2(__float2half_rn(x.x), __float2half_rn(x.y));
    h0[2*i+1] = __halves2half2(__float2half_rn(x.z), __float2half_rn(x.w));
}

// W [K=1024, N=1024] -> WT_h0/h1 [N, K] fp16
__global__ __launch_bounds__(256)
void transpose_split_kernel(const float* __restrict__ W,
                            __half* __restrict__ T0, __half* __restrict__ T1)
{
    __shared__ float t[32][33];
    int n0 = blockIdx.x * 32, k0 = blockIdx.y * 32;
    int tx = threadIdx.x & 31, ty = threadIdx.x >> 5;
    for (int r = ty; r < 32; r += 8)
        t[r][tx] = W[(size_t)(k0 + r) * DIM + n0 + tx];
    __syncthreads();
    for (int r = ty; r < 32; r += 8) {
        float x = t[tx][r];
        __half h = __float2half_rn(x);
        size_t o = (size_t)(n0 + r) * DIM + k0 + tx;
        T0[o] = h; T1[o] = __float2half_rn(x - __half2float(h));
    }
}

// ------------- fp16 mma GEMM: 128x128 tile, Kc=32, 2-stage cp.async, 2 CTAs/SM ----
// MODE 0: C = A@B^T + bias      -> fp16 split write   (Q&K proj MERGED via z, 3 prod)
// MODE 1: C = tanh(A@B^T+bias)  -> fp16 write         (V proj, A single, B split, 2 prod)
// MODE 2: C = A@B^T + mask      -> tile-shifted fp16 S + f32 tile max (QK^T, 3 prod)
// MODE 3: C = A0@B0 (B=[K][N])  -> f32 write          (P@V, single product)
template<int MODE>
__global__ __launch_bounds__(256, 2)
void mma_gemm(const __half* __restrict__ Ah, const __half* __restrict__ Al,
              const __half* __restrict__ Bh, const __half* __restrict__ Bl,
              const float* __restrict__ aux,
              void* __restrict__ out0v, void* __restrict__ out1v,
              int ldA, int ldB,
              long long sAz, long long sAlz, long long sBz, long long sBlz,
              long long sAuxz,
              int nK, int ldO, long long sOz, long long sO1z)
{
    constexpr bool BK     = (MODE == 3);                 // B is [K][N]
    constexpr bool SPLITA = (MODE == 0 || MODE == 2);
    constexpr bool SPLITB = !BK;
    constexpr int  OFF_B0 = SPLITA ? 20480 : 10240;
    constexpr int  STG    = BK ? (10240 + 8704) : (OFF_B0 + 20480);

    extern __shared__ char sm[];
    const uint32_t sb = smem_u32(sm);
    const int tid = threadIdx.x;
    const int lid = tid & 31, wid = tid >> 5;
    const int wm = wid >> 2, wn = wid & 3;      // 2 x 4 warp grid, warp tile 64x32
    const int lx = lid & 3,  ly = lid >> 2;
    const int m0 = blockIdx.y * 128, n0 = blockIdx.x * 128, z = blockIdx.z;
    const int nst = nK / 32;

    const __half* Agh = Ah + (size_t)z * sAz;
    const __half* Agl = Al + (size_t)z * sAlz;
    const __half* Bgh = Bh + (size_t)z * sBz;
    const __half* Bgl = Bl + (size_t)z * sBlz;
    const float*  auxz = aux + (size_t)z * sAuxz;

    float acc[4][4][4];
#pragma unroll
    for (int a = 0; a < 4; a++)
#pragma unroll
        for (int b = 0; b < 4; b++)
#pragma unroll
            for (int c = 0; c < 4; c++) acc[a][b][c] = 0.f;

    // ---- producer: fill stage SLOT st with k-chunk kt (32 k) ----
    auto issue = [&](int st, int kt) {
        uint32_t base = sb + (uint32_t)st * STG;
        // A tile(s): 128 rows x 4 chunks (16B = 8 halfs), row stride 80 B
#pragma unroll
        for (int i = 0; i < 2; i++) {
            int q = i * 256 + tid; int r = q >> 2, c = q & 3;
            uint32_t d = (uint32_t)(r * 80 + c * 16);
            cp16(base + d, Agh + (size_t)(m0 + r) * ldA + kt + c * 8);
            if (SPLITA) cp16(base + 10240 + d, Agl + (size_t)(m0 + r) * ldA + kt + c * 8);
        }
        uint32_t bb = base + OFF_B0;
        if (SPLITB) {
#pragma unroll
            for (int i = 0; i < 2; i++) {
                int q = i * 256 + tid; int r = q >> 2, c = q & 3;
                uint32_t d = (uint32_t)(r * 80 + c * 16);
                cp16(bb + d,         Bgh + (size_t)(n0 + r) * ldB + kt + c * 8);
                cp16(bb + 10240 + d, Bgl + (size_t)(n0 + r) * ldB + kt + c * 8);
            }
        } else {
            // single B tile: 32 k-rows x 16 chunks, row stride 272 B
#pragma unroll
            for (int i = 0; i < 2; i++) {
                int q = i * 256 + tid; int r = q >> 4, c = q & 15;
                uint32_t d = (uint32_t)(r * 272 + c * 16);
                cp16(bb + d, Bgh + (size_t)(kt + r) * ldB + n0 + c * 8);
            }
        }
        cp_commit();
    };

    issue(0, 0); issue(1, 32);

    // per-thread A row byte bases
    int rowA[4];
#pragma unroll
    for (int mt = 0; mt < 4; mt++) rowA[mt] = (wm * 64 + mt * 16 + ly) * 80 + 4 * lx;
    int rowB[4];
#pragma unroll
    for (int nt = 0; nt < 4; nt++) {
        if (SPLITB) rowB[nt] = (wn * 32 + nt * 8 + ly) * 80 + 4 * lx;
        else        rowB[nt] = wn * 32 + nt * 8 + ly;   // column index
    }

#pragma unroll 1
    for (int it = 0; it < nst; it++) {
        if (it + 1 < nst) cp_wait<1>();
        else              cp_wait<0>();
        __syncthreads();
        const char* S0 = sm + (it & 1) * STG;
        const char* A0t = S0;
        const char* A1t = S0 + 10240;                  // SPLITA only
        const char* B0t = S0 + OFF_B0;
        const char* B1t = S0 + OFF_B0 + 10240;         // SPLITB only

#pragma unroll
        for (int ks = 0; ks < 2; ks++) {
            const int kb = ks * 32;                 // byte offset of k16 slice (16 halfs)
            uint32_t a0[4][4], a1[4][4];
#pragma unroll
            for (int mt = 0; mt < 4; mt++) {
                int o = rowA[mt] + kb;
                a0[mt][0] = lds32(A0t, o);        a0[mt][1] = lds32(A0t, o + 640);
                a0[mt][2] = lds32(A0t, o + 16);   a0[mt][3] = lds32(A0t, o + 656);
                if (SPLITA) {
                    a1[mt][0] = lds32(A1t, o);        a1[mt][1] = lds32(A1t, o + 640);
                    a1[mt][2] = lds32(A1t, o + 16);   a1[mt][3] = lds32(A1t, o + 656);
                }
            }
            uint32_t b0[4][2], b1[4][2];
#pragma unroll
            for (int nt = 0; nt < 4; nt++) {
                if (SPLITB) {
                    int o = rowB[nt] + kb;
                    b0[nt][0] = lds32(B0t, o); b0[nt][1] = lds32(B0t, o + 16);
                    b1[nt][0] = lds32(B1t, o); b1[nt][1] = lds32(B1t, o + 16);
                } else {
                    int krow = (kb >> 1) + 2 * lx;        // k index = ks*16 + 2lx
                    int base0 = krow * 272 + rowB[nt] * 2;
                    b0[nt][0] = lds16x2(B0t, base0,        base0 + 272);
                    b0[nt][1] = lds16x2(B0t, base0 + 2176, base0 + 2448);
                }
            }
#pragma unroll
            for (int mt = 0; mt < 4; mt++)
#pragma unroll
                for (int nt = 0; nt < 4; nt++) {
                    mma16(acc[mt][nt], a0[mt], b0[nt]);
                    if (SPLITB) mma16(acc[mt][nt], a0[mt], b1[nt]);
                    if (SPLITA) mma16(acc[mt][nt], a1[mt], b0[nt]);
                }
        }
        __syncthreads();
        if (it + 2 < nst) issue(it & 1, (it + 2) * 32);
    }

    // ---- epilogue ----
    if (MODE == 2) {
        // per-row (within CTA) tile max via smem atomicMax, then shifted fp16 store
        __syncthreads();
        unsigned* rmax = (unsigned*)sm;
        if (tid < 128) rmax[tid] = 0u;     // f2o-encoded -inf lower bound
        __syncthreads();
#pragma unroll
        for (int mt = 0; mt < 4; mt++) {
#pragma unroll
            for (int hf = 0; hf < 2; hf++) {
                const int rl = wm * 64 + mt * 16 + ly + hf * 8;
                float mx = -INFINITY;
#pragma unroll
                for (int nt = 0; nt < 4; nt++) {
                    const int col = n0 + wn * 32 + nt * 8 + 2 * lx;
                    float x0 = acc[mt][nt][hf * 2 + 0] + auxz[col];
                    float x1 = acc[mt][nt][hf * 2 + 1] + auxz[col + 1];
                    mx = fmaxf(mx, fmaxf(x0, x1));
                }
                atomicMax(&rmax[rl], f2o(mx));
            }
        }
        __syncthreads();
        __half* S16o = (__half*)out0v;
        float*  Tmxo = (float*)out1v;
#pragma unroll
        for (int mt = 0; mt < 4; mt++) {
#pragma unroll
            for (int hf = 0; hf < 2; hf++) {
                const int rl = wm * 64 + mt * 16 + ly + hf * 8;
                const float m = o2f(rmax[rl]);
                const int gm = m0 + rl;
#pragma unroll
                for (int nt = 0; nt < 4; nt++) {
                    const int col = n0 + wn * 32 + nt * 8 + 2 * lx;
                    float x0 = acc[mt][nt][hf * 2 + 0] + auxz[col];
                    float x1 = acc[mt][nt][hf * 2 + 1] + auxz[col + 1];
                    *(__half2*)(S16o + (size_t)z * sOz + (size_t)gm * ldO + col) =
                        __floats2half2_rn(x0 - m, x1 - m);
                }
                if (wn == 0 && lx == 0)
                    Tmxo[((size_t)z * SQL + gm) * 16 + (n0 >> 7)] = m;
            }
        }
        return;
    }

#pragma unroll
    for (int mt = 0; mt < 4; mt++) {
#pragma unroll
        for (int hf = 0; hf < 2; hf++) {
            const int gm = m0 + wm * 64 + mt * 16 + ly + hf * 8;
#pragma unroll
            for (int nt = 0; nt < 4; nt++) {
                const int col = n0 + wn * 32 + nt * 8 + 2 * lx;
                float c0 = acc[mt][nt][hf * 2 + 0];
                float c1 = acc[mt][nt][hf * 2 + 1];
                if (MODE == 0) {
                    float x0 = c0 + auxz[col], x1 = c1 + auxz[col + 1];
                    __half h0 = __float2half_rn(x0), h1 = __float2half_rn(x1);
                    __half l0 = __float2half_rn(x0 - __half2float(h0));
                    __half l1 = __float2half_rn(x1 - __half2float(h1));
                    *(__half2*)((__half*)out0v + (size_t)z * sOz + (size_t)gm * ldO + col) =
                        __halves2half2(h0, h1);
                    *(__half2*)((__half*)out1v + (size_t)z * sO1z + (size_t)gm * ldO + col) =
                        __halves2half2(l0, l1);
                } else if (MODE == 1) {
                    float x0 = tanhf(c0 + auxz[col]), x1 = tanhf(c1 + auxz[col + 1]);
                    *(__half2*)((__half*)out0v + (size_t)gm * ldO + col) =
                        __halves2half2(__float2half_rn(x0), __float2half_rn(x1));
                } else {
                    *(float2*)((float*)out0v + (size_t)z * sOz + (size_t)gm * ldO + col) =
                        make_float2(c0, c1);
                }
            }
        }
    }
}

// ------------- softmax: read fp16 tile-shifted S + f32 tile max, write fp16 P -------------
__global__ __launch_bounds__(256)
void softmax_rows(const __half* __restrict__ S16, const float* __restrict__ Tmax,
                  __half* __restrict__ P0)
{
    const size_t row = blockIdx.x;
    const __half2* srow = (const __half2*)(S16 + row * SKL);
    __half2* prow = (__half2*)(P0 + row * SKL);
    const float* tmr = Tmax + row * 16;
    const int t = threadIdx.x;

    // global row max from the 16 tile maxes
    float m = -INFINITY;
#pragma unroll
    for (int i = 0; i < 16; i += 4) {
        float4 tv = *(const float4*)(tmr + i);
        m = fmaxf(m, fmaxf(fmaxf(tv.x, tv.y), fmaxf(tv.z, tv.w)));
    }

    const int tg = t >> 6;   // this thread's tile within each i-group
    float e[4][2];
    float sum = 0.f;
#pragma unroll
    for (int i = 0; i < 4; i++) {
        float adj = tmr[tg + 4 * i] - m;
        __half2 sv = srow[t + i * 256];
        float s0 = __low2float(sv)  + adj;
        float s1 = __high2float(sv) + adj;
        e[i][0] = __expf(s0); e[i][1] = __expf(s1);
        sum += e[i][0] + e[i][1];
    }

    // block sum reduce: warp shuffle + smem
#pragma unroll
    for (int o = 16; o > 0; o >>= 1) sum += __shfl_xor_sync(0xFFFFFFFFu, sum, o);
    __shared__ float red[8];
    if ((t & 31) == 0) red[t >> 5] = sum;
    __syncthreads();
    float tot = 0.f;
#pragma unroll
    for (int w = 0; w < 8; w++) tot += red[w];
    const float inv = 1.0f / tot;

#pragma unroll
    for (int i = 0; i < 4; i++)
        prow[t + i * 256] = __floats2half2_rn(e[i][0] * inv, e[i][1] * inv);
}

// ---------------- launch ----------------
extern "C" void kernel_launch(void* const* d_in, const int* in_sizes, int n_in,
                              void* d_out, int out_size)
{
    const float* q    = (const float*)d_in[0];
    const float* k    = (const float*)d_in[1];
    const float* v    = (const float*)d_in[2];
    const void*  mask = d_in[3];
    const float* Wq   = (const float*)d_in[4];
    const float* bq   = (const float*)d_in[5];
    const float* Wk   = (const float*)d_in[6];
    const float* bk   = (const float*)d_in[7];
    const float* Wv   = (const float*)d_in[8];
    const float* bvp  = (const float*)d_in[9];
    float* out        = (float*)d_out;

    __half *q0, *q1, *k0, *k1, *v0;
    __half *Wq0, *Wq1, *Wk0, *Wk1, *Wv0, *Wv1;
    __half *Qp0, *Qp1, *Kp0, *Kp1, *Vp0, *P0, *S16;
    float *Tmax, *maskf;
    cudaGetSymbolAddress((void**)&q0, g_q0);   cudaGetSymbolAddress((void**)&q1, g_q1);
    cudaGetSymbolAddress((void**)&k0, g_k0);   cudaGetSymbolAddress((void**)&k1, g_k1);
    cudaGetSymbolAddress((void**)&v0, g_v0);
    cudaGetSymbolAddress((void**)&Wq0, g_Wq0); cudaGetSymbolAddress((void**)&Wq1, g_Wq1);
    cudaGetSymbolAddress((void**)&Wk0, g_Wk0); cudaGetSymbolAddress((void**)&Wk1, g_Wk1);
    cudaGetSymbolAddress((void**)&Wv0, g_Wv0); cudaGetSymbolAddress((void**)&Wv1, g_Wv1);
    cudaGetSymbolAddress((void**)&Qp0, g_Qp0); cudaGetSymbolAddress((void**)&Qp1, g_Qp1);
    cudaGetSymbolAddress((void**)&Kp0, g_Kp0); cudaGetSymbolAddress((void**)&Kp1, g_Kp1);
    cudaGetSymbolAddress((void**)&Vp0, g_Vp0);
    cudaGetSymbolAddress((void**)&P0, g_P0);
    cudaGetSymbolAddress((void**)&S16, g_S16); cudaGetSymbolAddress((void**)&Tmax, g_Tmax);
    cudaGetSymbolAddress((void**)&maskf, g_maskf);

    // mask -> float
    detect_mask_kernel<<<1, 256>>>((const unsigned int*)mask);
    convert_mask_kernel<<<(BATCH * SKL + 255) / 256, 256>>>(mask, BATCH * SKL);

    // split q,k into fp16 pairs; convert v to single fp16
    {
        int n4 = (int)(NELEM / 4);
        int nb = (n4 + 255) / 256;
        split_kernel<<<nb, 256>>>((const float4*)q, (__half2*)q0, (__half2*)q1, n4);
        split_kernel<<<nb, 256>>>((const float4*)k, (__half2*)k0, (__half2*)k1, n4);
        convert_half_kernel<<<nb, 256>>>((const float4*)v, (__half2*)v0, n4);
    }
    // transpose + split weights -> [N][K] fp16
    {
        dim3 g(DIM / 32, DIM / 32);
        transpose_split_kernel<<<g, 256>>>(Wq, Wq0, Wq1);
        transpose_split_kernel<<<g, 256>>>(Wk, Wk0, Wk1);
        transpose_split_kernel<<<g, 256>>>(Wv, Wv0, Wv1);
    }

    const int SMEM02 = 2 * 40960;   // modes 0,2: 81920 B -> 2 CTAs/SM
    const int SMEM1  = 2 * 30720;   // mode 1:   61440 B -> 2 CTAs/SM
    const int SMEM3  = 2 * 18944;   // mode 3:   37888 B -> 2 CTAs/SM
    cudaFuncSetAttribute(mma_gemm<0>, cudaFuncAttributeMaxDynamicSharedMemorySize, SMEM02);
    cudaFuncSetAttribute(mma_gemm<1>, cudaFuncAttributeMaxDynamicSharedMemorySize, SMEM1);
    cudaFuncSetAttribute(mma_gemm<2>, cudaFuncAttributeMaxDynamicSharedMemorySize, SMEM02);
    cudaFuncSetAttribute(mma_gemm<3>, cudaFuncAttributeMaxDynamicSharedMemorySize, SMEM3);

    // Q & K projections MERGED: grid z=2 selects problem instance via pointer-diff strides
    {
        dim3 grid(DIM / 128, (BATCH * SQL) / 128, 2);
        long long sAz   = (long long)(k0  - q0);
        long long sAlz  = (long long)(k1  - q1);
        long long sBz   = (long long)(Wk0 - Wq0);
        long long sBlz  = (long long)(Wk1 - Wq1);
        long long sAuxz = (long long)(bk  - bq);
        long long sOz   = (long long)(Kp0 - Qp0);
        long long sO1z  = (long long)(Kp1 - Qp1);
        mma_gemm<0><<<grid, 256, SMEM02>>>(q0, q1, Wq0, Wq1, bq, Qp0, Qp1,
                                           DIM, DIM,
                                           sAz, sAlz, sBz, sBlz, sAuxz,
                                           DIM, DIM, sOz, sO1z);
    }
    // V projection: A single (v0), B split, 2 products
    {
        dim3 grid(DIM / 128, (BATCH * SQL) / 128, 1);
        mma_gemm<1><<<grid, 256, SMEM1>>>(v0, v0, Wv0, Wv1, bvp, Vp0, nullptr,
                                          DIM, DIM, 0, 0, 0, 0, 0,
                                          DIM, DIM, 0, 0);
    }

    // S16 = tile-shifted fp16 (Qp @ Kp^T + mask), Tmax = per-row tile maxes
    {
        dim3 grid(SKL / 128, SQL / 128, BATCH);
        mma_gemm<2><<<grid, 256, SMEM02>>>(Qp0, Qp1, Kp0, Kp1, maskf, S16, Tmax,
                                           DIM, DIM,
                                           (long long)SQL * DIM, (long long)SQL * DIM,
                                           (long long)SKL * DIM, (long long)SKL * DIM,
                                           SKL,
                                           DIM, SKL, (long long)SQL * SKL, 0);
    }

    // softmax rows -> single fp16 P
    softmax_rows<<<BATCH * SQL, 256>>>(S16, Tmax, P0);

    // out = P0 @ Vp0  (batched, single product)
    {
        dim3 grid(DIM / 128, SQL / 128, BATCH);
        mma_gemm<3><<<grid, 256, SMEM3>>>(P0, P0, Vp0, Vp0, nullptr, out, nullptr,
                                          SKL, DIM,
                                          (long long)SQL * SKL, (long long)SQL * SKL,
                                          (long long)SKL * DIM, (long long)SKL * DIM,
                                          0,
                                          SKL, DIM, (long long)SQL * DIM, 0);
    }
}

// round 13
// speedup vs baseline: 2.2696x; 1.0412x over previous
#include <cuda_runtime.h>
#include <cuda_fp16.h>
#include <cstdint>
#include <math.h>

// Problem dims
#define BATCH 8
#define SQL   2048
#define SKL   2048
#define DIM   1024

#define NELEM ((size_t)BATCH * SQL * DIM)      // 16.8M elements

// ---------------- device scratch (static) ----------------
__device__ __half g_q0[NELEM], g_q1[NELEM];
__device__ __half g_k0[NELEM], g_k1[NELEM];
__device__ __half g_v0[NELEM];                      // V input single fp16
__device__ __half g_Wq0[DIM*DIM], g_Wq1[DIM*DIM];   // transposed [N][K]
__device__ __half g_Wk0[DIM*DIM], g_Wk1[DIM*DIM];
__device__ __half g_Wv0[DIM*DIM], g_Wv1[DIM*DIM];   // Wv1 unused by GEMM now (kept for layout)
__device__ __half g_Qp0[NELEM], g_Qp1[NELEM];
__device__ __half g_Kp0[NELEM], g_Kp1[NELEM];
__device__ __half g_Vp0[NELEM];                     // single fp16 V
__device__ __half g_S16[(size_t)BATCH * SQL * SKL]; // tile-shifted scores (fp16)
__device__ float  g_Tmax[(size_t)BATCH * SQL * 16]; // per-row per-tile max (f32)
__device__ __half g_P0[(size_t)BATCH * SQL * SKL];  // softmax P (single fp16)
__device__ float  g_maskf[BATCH * SKL];
__device__ int    g_mask_mode;

// ---------------- small helpers ----------------
__device__ __forceinline__ uint32_t smem_u32(const void* p) {
    uint32_t a;
    asm("{ .reg .u64 t; cvta.to.shared.u64 t, %1; cvt.u32.u64 %0, t; }" : "=r"(a) : "l"(p));
    return a;
}
__device__ __forceinline__ void cp16(uint32_t dst, const void* src) {
    asm volatile("cp.async.cg.shared.global [%0], [%1], 16;" :: "r"(dst), "l"(src) : "memory");
}
__device__ __forceinline__ void cp_commit() {
    asm volatile("cp.async.commit_group;" ::: "memory");
}
template<int N> __device__ __forceinline__ void cp_wait() {
    asm volatile("cp.async.wait_group %0;" :: "n"(N) : "memory");
}
// mma.sync m16n8k16 f16 -> f32 accum
__device__ __forceinline__ void mma16(float* c, const uint32_t* a, const uint32_t* b) {
    asm volatile(
        "mma.sync.aligned.m16n8k16.row.col.f32.f16.f16.f32 "
        "{%0,%1,%2,%3}, {%4,%5,%6,%7}, {%8,%9}, {%0,%1,%2,%3};"
        : "+f"(c[0]), "+f"(c[1]), "+f"(c[2]), "+f"(c[3])
        : "r"(a[0]), "r"(a[1]), "r"(a[2]), "r"(a[3]), "r"(b[0]), "r"(b[1]));
}
__device__ __forceinline__ uint32_t lds32(const char* smem, int off) {
    return *(const uint32_t*)(smem + off);
}
__device__ __forceinline__ uint32_t lds16x2(const char* smem, int off_lo, int off_hi) {
    uint32_t lo = *(const uint16_t*)(smem + off_lo);
    uint32_t hi = *(const uint16_t*)(smem + off_hi);
    return lo | (hi << 16);
}
// float <-> monotonic unsigned encoding (for atomicMax on floats incl. negatives)
__device__ __forceinline__ unsigned f2o(float f) {
    unsigned u = __float_as_uint(f);
    return (u & 0x80000000u) ? ~u : (u | 0x80000000u);
}
__device__ __forceinline__ float o2f(unsigned u) {
    return (u & 0x80000000u) ? __uint_as_float(u & 0x7FFFFFFFu) : __uint_as_float(~u);
}

// ---------------- mask dtype sniffing (verified R1) ----------------
__global__ void detect_mask_kernel(const unsigned int* __restrict__ w)
{
    __shared__ unsigned int f;
    if (threadIdx.x == 0) f = 0u;
    __syncthreads();
    unsigned int loc = 0u;
    for (int i = threadIdx.x; i < 4096; i += 256) {
        unsigned int x = w[i];
        if (x == 0x3F803F80u || x == 0x00003F80u) loc |= 8u;
        if (x == 0x3F800000u)                     loc |= 4u;
        if (x > 1u)                               loc |= 2u;
    }
    atomicOr(&f, loc);
    __syncthreads();
    if (threadIdx.x == 0) {
        unsigned int ff = f;
        g_mask_mode = (ff & 8u) ? 3 : (ff & 4u) ? 2 : (ff & 2u) ? 1 : 0;
    }
}
__global__ void convert_mask_kernel(const void* __restrict__ m, int n)
{
    int i = blockIdx.x * blockDim.x + threadIdx.x;
    if (i >= n) return;
    int mode = g_mask_mode;
    float v;
    if (mode == 0)      v = (float)((const int*)m)[i];
    else if (mode == 1) v = (float)((const unsigned char*)m)[i];
    else if (mode == 2) v = ((const float*)m)[i];
    else {
        unsigned short h = ((const unsigned short*)m)[i];
        v = __uint_as_float(((unsigned int)h) << 16);
    }
    g_maskf[i] = v;
}

// ---------------- fp16 double-half split: q and k in ONE launch (z selects) -----
__global__ __launch_bounds__(256)
void split2_kernel(const float4* __restrict__ sq, const float4* __restrict__ sk,
                   __half2* __restrict__ q0, __half2* __restrict__ q1,
                   __half2* __restrict__ k0, __half2* __restrict__ k1, int n4)
{
    int i = blockIdx.x * blockDim.x + threadIdx.x;
    if (i >= n4) return;
    const float4* src = blockIdx.y ? sk : sq;
    __half2* h0 = blockIdx.y ? k0 : q0;
    __half2* h1 = blockIdx.y ? k1 : q1;
    float4 x = src[i];
    __half a0 = __float2half_rn(x.x); __half b0 = __float2half_rn(x.x - __half2float(a0));
    __half a1 = __float2half_rn(x.y); __half b1 = __float2half_rn(x.y - __half2float(a1));
    __half a2 = __float2half_rn(x.z); __half b2 = __float2half_rn(x.z - __half2float(a2));
    __half a3 = __float2half_rn(x.w); __half b3 = __float2half_rn(x.w - __half2float(a3));
    h0[2*i]   = __halves2half2(a0, a1);
    h0[2*i+1] = __halves2half2(a2, a3);
    h1[2*i]   = __halves2half2(b0, b1);
    h1[2*i+1] = __halves2half2(b2, b3);
}

// single fp16 convert (for V input)
__global__ __launch_bounds__(256)
void convert_half_kernel(const float4* __restrict__ src, __half2* __restrict__ h0, int n4)
{
    int i = blockIdx.x * blockDim.x + threadIdx.x;
    if (i >= n4) return;
    float4 x = src[i];
    h0[2*i]   = __halves2half2(__float2half_rn(x.x), __float2half_rn(x.y));
    h0[2*i+1] = __halves2half2(__float2half_rn(x.z), __float2half_rn(x.w));
}

// W [K,N] -> WT_h0/h1 [N,K] fp16; all three weights in ONE launch (z selects)
__global__ __launch_bounds__(256)
void transpose_split3_kernel(const float* __restrict__ Wa, const float* __restrict__ Wb,
                             const float* __restrict__ Wc,
                             __half* __restrict__ A0, __half* __restrict__ A1,
                             __half* __restrict__ B0, __half* __restrict__ B1,
                             __half* __restrict__ C0, __half* __restrict__ C1)
{
    const float* W = (blockIdx.z == 0) ? Wa : (blockIdx.z == 1) ? Wb : Wc;
    __half* T0 = (blockIdx.z == 0) ? A0 : (blockIdx.z == 1) ? B0 : C0;
    __half* T1 = (blockIdx.z == 0) ? A1 : (blockIdx.z == 1) ? B1 : C1;
    __shared__ float t[32][33];
    int n0 = blockIdx.x * 32, k0 = blockIdx.y * 32;
    int tx = threadIdx.x & 31, ty = threadIdx.x >> 5;
    for (int r = ty; r < 32; r += 8)
        t[r][tx] = W[(size_t)(k0 + r) * DIM + n0 + tx];
    __syncthreads();
    for (int r = ty; r < 32; r += 8) {
        float x = t[tx][r];
        __half h = __float2half_rn(x);
        size_t o = (size_t)(n0 + r) * DIM + k0 + tx;
        T0[o] = h; T1[o] = __float2half_rn(x - __half2float(h));
    }
}

// ------------- fp16 mma GEMM: 128x128 tile, Kc=32, 2-stage cp.async, 2 CTAs/SM ----
// MODE 0: C = A@B^T + bias      -> fp16 split write   (Q&K proj MERGED via z, 3 prod)
// MODE 1: C = tanh(A@B^T+bias)  -> fp16 write         (V proj, SINGLE product)
// MODE 2: C = A@B^T + mask      -> tile-shifted fp16 S + f32 tile max (QK^T, 3 prod)
// MODE 3: C = A0@B0 (B=[K][N])  -> f32 write          (P@V, single product)
template<int MODE>
__global__ __launch_bounds__(256, 2)
void mma_gemm(const __half* __restrict__ Ah, const __half* __restrict__ Al,
              const __half* __restrict__ Bh, const __half* __restrict__ Bl,
              const float* __restrict__ aux,
              void* __restrict__ out0v, void* __restrict__ out1v,
              int ldA, int ldB,
              long long sAz, long long sAlz, long long sBz, long long sBlz,
              long long sAuxz,
              int nK, int ldO, long long sOz, long long sO1z)
{
    constexpr bool BK     = (MODE == 3);                 // B is [K][N]
    constexpr bool SPLITA = (MODE == 0 || MODE == 2);
    constexpr bool SPLITB = (MODE == 0 || MODE == 2);
    constexpr int  OFF_B0 = SPLITA ? 20480 : 10240;
    constexpr int  STG    = BK ? (10240 + 8704)
                               : (OFF_B0 + (SPLITB ? 20480 : 10240));

    extern __shared__ char sm[];
    const uint32_t sb = smem_u32(sm);
    const int tid = threadIdx.x;
    const int lid = tid & 31, wid = tid >> 5;
    const int wm = wid >> 2, wn = wid & 3;      // 2 x 4 warp grid, warp tile 64x32
    const int lx = lid & 3,  ly = lid >> 2;
    const int m0 = blockIdx.y * 128, n0 = blockIdx.x * 128, z = blockIdx.z;
    const int nst = nK / 32;

    const __half* Agh = Ah + (size_t)z * sAz;
    const __half* Agl = Al + (size_t)z * sAlz;
    const __half* Bgh = Bh + (size_t)z * sBz;
    const __half* Bgl = Bl + (size_t)z * sBlz;
    const float*  auxz = aux + (size_t)z * sAuxz;

    float acc[4][4][4];
#pragma unroll
    for (int a = 0; a < 4; a++)
#pragma unroll
        for (int b = 0; b < 4; b++)
#pragma unroll
            for (int c = 0; c < 4; c++) acc[a][b][c] = 0.f;

    // ---- producer: fill stage SLOT st with k-chunk kt (32 k) ----
    auto issue = [&](int st, int kt) {
        uint32_t base = sb + (uint32_t)st * STG;
        // A tile(s): 128 rows x 4 chunks (16B = 8 halfs), row stride 80 B
#pragma unroll
        for (int i = 0; i < 2; i++) {
            int q = i * 256 + tid; int r = q >> 2, c = q & 3;
            uint32_t d = (uint32_t)(r * 80 + c * 16);
            cp16(base + d, Agh + (size_t)(m0 + r) * ldA + kt + c * 8);
            if (SPLITA) cp16(base + 10240 + d, Agl + (size_t)(m0 + r) * ldA + kt + c * 8);
        }
        uint32_t bb = base + OFF_B0;
        if (!BK) {
#pragma unroll
            for (int i = 0; i < 2; i++) {
                int q = i * 256 + tid; int r = q >> 2, c = q & 3;
                uint32_t d = (uint32_t)(r * 80 + c * 16);
                cp16(bb + d, Bgh + (size_t)(n0 + r) * ldB + kt + c * 8);
                if (SPLITB) cp16(bb + 10240 + d, Bgl + (size_t)(n0 + r) * ldB + kt + c * 8);
            }
        } else {
            // single B tile: 32 k-rows x 16 chunks, row stride 272 B
#pragma unroll
            for (int i = 0; i < 2; i++) {
                int q = i * 256 + tid; int r = q >> 4, c = q & 15;
                uint32_t d = (uint32_t)(r * 272 + c * 16);
                cp16(bb + d, Bgh + (size_t)(kt + r) * ldB + n0 + c * 8);
            }
        }
        cp_commit();
    };

    issue(0, 0); issue(1, 32);

    // per-thread A row byte bases
    int rowA[4];
#pragma unroll
    for (int mt = 0; mt < 4; mt++) rowA[mt] = (wm * 64 + mt * 16 + ly) * 80 + 4 * lx;
    int rowB[4];
#pragma unroll
    for (int nt = 0; nt < 4; nt++) {
        if (!BK) rowB[nt] = (wn * 32 + nt * 8 + ly) * 80 + 4 * lx;
        else     rowB[nt] = wn * 32 + nt * 8 + ly;   // column index
    }

#pragma unroll 1
    for (int it = 0; it < nst; it++) {
        if (it + 1 < nst) cp_wait<1>();
        else              cp_wait<0>();
        __syncthreads();
        const char* S0 = sm + (it & 1) * STG;
        const char* A0t = S0;
        const char* A1t = S0 + 10240;                  // SPLITA only
        const char* B0t = S0 + OFF_B0;
        const char* B1t = S0 + OFF_B0 + 10240;         // SPLITB only

#pragma unroll
        for (int ks = 0; ks < 2; ks++) {
            const int kb = ks * 32;                 // byte offset of k16 slice (16 halfs)
            uint32_t a0[4][4], a1[4][4];
#pragma unroll
            for (int mt = 0; mt < 4; mt++) {
                int o = rowA[mt] + kb;
                a0[mt][0] = lds32(A0t, o);        a0[mt][1] = lds32(A0t, o + 640);
                a0[mt][2] = lds32(A0t, o + 16);   a0[mt][3] = lds32(A0t, o + 656);
                if (SPLITA) {
                    a1[mt][0] = lds32(A1t, o);        a1[mt][1] = lds32(A1t, o + 640);
                    a1[mt][2] = lds32(A1t, o + 16);   a1[mt][3] = lds32(A1t, o + 656);
                }
            }
            uint32_t b0[4][2], b1[4][2];
#pragma unroll
            for (int nt = 0; nt < 4; nt++) {
                if (!BK) {
                    int o = rowB[nt] + kb;
                    b0[nt][0] = lds32(B0t, o); b0[nt][1] = lds32(B0t, o + 16);
                    if (SPLITB) {
                        b1[nt][0] = lds32(B1t, o); b1[nt][1] = lds32(B1t, o + 16);
                    }
                } else {
                    int krow = (kb >> 1) + 2 * lx;        // k index = ks*16 + 2lx
                    int base0 = krow * 272 + rowB[nt] * 2;
                    b0[nt][0] = lds16x2(B0t, base0,        base0 + 272);
                    b0[nt][1] = lds16x2(B0t, base0 + 2176, base0 + 2448);
                }
            }
#pragma unroll
            for (int mt = 0; mt < 4; mt++)
#pragma unroll
                for (int nt = 0; nt < 4; nt++) {
                    mma16(acc[mt][nt], a0[mt], b0[nt]);
                    if (SPLITB) mma16(acc[mt][nt], a0[mt], b1[nt]);
                    if (SPLITA) mma16(acc[mt][nt], a1[mt], b0[nt]);
                }
        }
        __syncthreads();
        if (it + 2 < nst) issue(it & 1, (it + 2) * 32);
    }

    // ---- epilogue ----
    if (MODE == 2) {
        // per-row (within CTA) tile max via smem atomicMax, then shifted fp16 store
        __syncthreads();
        unsigned* rmax = (unsigned*)sm;
        if (tid < 128) rmax[tid] = 0u;     // f2o-encoded -inf lower bound
        __syncthreads();
#pragma unroll
        for (int mt = 0; mt < 4; mt++) {
#pragma unroll
            for (int hf = 0; hf < 2; hf++) {
                const int rl = wm * 64 + mt * 16 + ly + hf * 8;
                float mx = -INFINITY;
#pragma unroll
                for (int nt = 0; nt < 4; nt++) {
                    const int col = n0 + wn * 32 + nt * 8 + 2 * lx;
                    float x0 = acc[mt][nt][hf * 2 + 0] + auxz[col];
                    float x1 = acc[mt][nt][hf * 2 + 1] + auxz[col + 1];
                    mx = fmaxf(mx, fmaxf(x0, x1));
                }
                atomicMax(&rmax[rl], f2o(mx));
            }
        }
        __syncthreads();
        __half* S16o = (__half*)out0v;
        float*  Tmxo = (float*)out1v;
#pragma unroll
        for (int mt = 0; mt < 4; mt++) {
#pragma unroll
            for (int hf = 0; hf < 2; hf++) {
                const int rl = wm * 64 + mt * 16 + ly + hf * 8;
                const float m = o2f(rmax[rl]);
                const int gm = m0 + rl;
#pragma unroll
                for (int nt = 0; nt < 4; nt++) {
                    const int col = n0 + wn * 32 + nt * 8 + 2 * lx;
                    float x0 = acc[mt][nt][hf * 2 + 0] + auxz[col];
                    float x1 = acc[mt][nt][hf * 2 + 1] + auxz[col + 1];
                    *(__half2*)(S16o + (size_t)z * sOz + (size_t)gm * ldO + col) =
                        __floats2half2_rn(x0 - m, x1 - m);
                }
                if (wn == 0 && lx == 0)
                    Tmxo[((size_t)z * SQL + gm) * 16 + (n0 >> 7)] = m;
            }
        }
        return;
    }

#pragma unroll
    for (int mt = 0; mt < 4; mt++) {
#pragma unroll
        for (int hf = 0; hf < 2; hf++) {
            const int gm = m0 + wm * 64 + mt * 16 + ly + hf * 8;
#pragma unroll
            for (int nt = 0; nt < 4; nt++) {
                const int col = n0 + wn * 32 + nt * 8 + 2 * lx;
                float c0 = acc[mt][nt][hf * 2 + 0];
                float c1 = acc[mt][nt][hf * 2 + 1];
                if (MODE == 0) {
                    float x0 = c0 + auxz[col], x1 = c1 + auxz[col + 1];
                    __half h0 = __float2half_rn(x0), h1 = __float2half_rn(x1);
                    __half l0 = __float2half_rn(x0 - __half2float(h0));
                    __half l1 = __float2half_rn(x1 - __half2float(h1));
                    *(__half2*)((__half*)out0v + (size_t)z * sOz + (size_t)gm * ldO + col) =
                        __halves2half2(h0, h1);
                    *(__half2*)((__half*)out1v + (size_t)z * sO1z + (size_t)gm * ldO + col) =
                        __halves2half2(l0, l1);
                } else if (MODE == 1) {
                    float x0 = tanhf(c0 + auxz[col]), x1 = tanhf(c1 + auxz[col + 1]);
                    *(__half2*)((__half*)out0v + (size_t)gm * ldO + col) =
                        __halves2half2(__float2half_rn(x0), __float2half_rn(x1));
                } else {
                    *(float2*)((float*)out0v + (size_t)z * sOz + (size_t)gm * ldO + col) =
                        make_float2(c0, c1);
                }
            }
        }
    }
}

// ------------- softmax: read fp16 tile-shifted S + f32 tile max, write fp16 P -------------
__global__ __launch_bounds__(256)
void softmax_rows(const __half* __restrict__ S16, const float* __restrict__ Tmax,
                  __half* __restrict__ P0)
{
    const size_t row = blockIdx.x;
    const __half2* srow = (const __half2*)(S16 + row * SKL);
    __half2* prow = (__half2*)(P0 + row * SKL);
    const float* tmr = Tmax + row * 16;
    const int t = threadIdx.x;

    // global row max from the 16 tile maxes
    float m = -INFINITY;
#pragma unroll
    for (int i = 0; i < 16; i += 4) {
        float4 tv = *(const float4*)(tmr + i);
        m = fmaxf(m, fmaxf(fmaxf(tv.x, tv.y), fmaxf(tv.z, tv.w)));
    }

    const int tg = t >> 6;   // this thread's tile within each i-group
    float e[4][2];
    float sum = 0.f;
#pragma unroll
    for (int i = 0; i < 4; i++) {
        float adj = tmr[tg + 4 * i] - m;
        __half2 sv = srow[t + i * 256];
        float s0 = __low2float(sv)  + adj;
        float s1 = __high2float(sv) + adj;
        e[i][0] = __expf(s0); e[i][1] = __expf(s1);
        sum += e[i][0] + e[i][1];
    }

    // block sum reduce: warp shuffle + smem
#pragma unroll
    for (int o = 16; o > 0; o >>= 1) sum += __shfl_xor_sync(0xFFFFFFFFu, sum, o);
    __shared__ float red[8];
    if ((t & 31) == 0) red[t >> 5] = sum;
    __syncthreads();
    float tot = 0.f;
#pragma unroll
    for (int w = 0; w < 8; w++) tot += red[w];
    const float inv = 1.0f / tot;

#pragma unroll
    for (int i = 0; i < 4; i++)
        prow[t + i * 256] = __floats2half2_rn(e[i][0] * inv, e[i][1] * inv);
}

// ---------------- launch ----------------
extern "C" void kernel_launch(void* const* d_in, const int* in_sizes, int n_in,
                              void* d_out, int out_size)
{
    const float* q    = (const float*)d_in[0];
    const float* k    = (const float*)d_in[1];
    const float* v    = (const float*)d_in[2];
    const void*  mask = d_in[3];
    const float* Wq   = (const float*)d_in[4];
    const float* bq   = (const float*)d_in[5];
    const float* Wk   = (const float*)d_in[6];
    const float* bk   = (const float*)d_in[7];
    const float* Wv   = (const float*)d_in[8];
    const float* bvp  = (const float*)d_in[9];
    float* out        = (float*)d_out;

    __half *q0, *q1, *k0, *k1, *v0;
    __half *Wq0, *Wq1, *Wk0, *Wk1, *Wv0, *Wv1;
    __half *Qp0, *Qp1, *Kp0, *Kp1, *Vp0, *P0, *S16;
    float *Tmax, *maskf;
    cudaGetSymbolAddress((void**)&q0, g_q0);   cudaGetSymbolAddress((void**)&q1, g_q1);
    cudaGetSymbolAddress((void**)&k0, g_k0);   cudaGetSymbolAddress((void**)&k1, g_k1);
    cudaGetSymbolAddress((void**)&v0, g_v0);
    cudaGetSymbolAddress((void**)&Wq0, g_Wq0); cudaGetSymbolAddress((void**)&Wq1, g_Wq1);
    cudaGetSymbolAddress((void**)&Wk0, g_Wk0); cudaGetSymbolAddress((void**)&Wk1, g_Wk1);
    cudaGetSymbolAddress((void**)&Wv0, g_Wv0); cudaGetSymbolAddress((void**)&Wv1, g_Wv1);
    cudaGetSymbolAddress((void**)&Qp0, g_Qp0); cudaGetSymbolAddress((void**)&Qp1, g_Qp1);
    cudaGetSymbolAddress((void**)&Kp0, g_Kp0); cudaGetSymbolAddress((void**)&Kp1, g_Kp1);
    cudaGetSymbolAddress((void**)&Vp0, g_Vp0);
    cudaGetSymbolAddress((void**)&P0, g_P0);
    cudaGetSymbolAddress((void**)&S16, g_S16); cudaGetSymbolAddress((void**)&Tmax, g_Tmax);
    cudaGetSymbolAddress((void**)&maskf, g_maskf);

    // mask -> float
    detect_mask_kernel<<<1, 256>>>((const unsigned int*)mask);
    convert_mask_kernel<<<(BATCH * SKL + 255) / 256, 256>>>(mask, BATCH * SKL);

    // split q,k (one launch) + convert v
    {
        int n4 = (int)(NELEM / 4);
        int nb = (n4 + 255) / 256;
        dim3 g2(nb, 2);
        split2_kernel<<<g2, 256>>>((const float4*)q, (const float4*)k,
                                   (__half2*)q0, (__half2*)q1,
                                   (__half2*)k0, (__half2*)k1, n4);
        convert_half_kernel<<<nb, 256>>>((const float4*)v, (__half2*)v0, n4);
    }
    // transpose + split all three weights in one launch
    {
        dim3 g(DIM / 32, DIM / 32, 3);
        transpose_split3_kernel<<<g, 256>>>(Wq, Wk, Wv, Wq0, Wq1, Wk0, Wk1, Wv0, Wv1);
    }

    const int SMEM02 = 2 * 40960;   // modes 0,2: 81920 B -> 2 CTAs/SM
    const int SMEM1  = 2 * 20480;   // mode 1:   40960 B
    const int SMEM3  = 2 * 18944;   // mode 3:   37888 B
    cudaFuncSetAttribute(mma_gemm<0>, cudaFuncAttributeMaxDynamicSharedMemorySize, SMEM02);
    cudaFuncSetAttribute(mma_gemm<1>, cudaFuncAttributeMaxDynamicSharedMemorySize, SMEM1);
    cudaFuncSetAttribute(mma_gemm<2>, cudaFuncAttributeMaxDynamicSharedMemorySize, SMEM02);
    cudaFuncSetAttribute(mma_gemm<3>, cudaFuncAttributeMaxDynamicSharedMemorySize, SMEM3);

    // Q & K projections MERGED: grid z=2 selects problem instance via pointer-diff strides
    {
        dim3 grid(DIM / 128, (BATCH * SQL) / 128, 2);
        long long sAz   = (long long)(k0  - q0);
        long long sAlz  = (long long)(k1  - q1);
        long long sBz   = (long long)(Wk0 - Wq0);
        long long sBlz  = (long long)(Wk1 - Wq1);
        long long sAuxz = (long long)(bk  - bq);
        long long sOz   = (long long)(Kp0 - Qp0);
        long long sO1z  = (long long)(Kp1 - Qp1);
        mma_gemm<0><<<grid, 256, SMEM02>>>(q0, q1, Wq0, Wq1, bq, Qp0, Qp1,
                                           DIM, DIM,
                                           sAz, sAlz, sBz, sBlz, sAuxz,
                                           DIM, DIM, sOz, sO1z);
    }
    // V projection: single product v0 @ Wv0^T
    {
        dim3 grid(DIM / 128, (BATCH * SQL) / 128, 1);
        mma_gemm<1><<<grid, 256, SMEM1>>>(v0, v0, Wv0, Wv0, bvp, Vp0, nullptr,
                                          DIM, DIM, 0, 0, 0, 0, 0,
                                          DIM, DIM, 0, 0);
    }

    // S16 = tile-shifted fp16 (Qp @ Kp^T + mask), Tmax = per-row tile maxes
    {
        dim3 grid(SKL / 128, SQL / 128, BATCH);
        mma_gemm<2><<<grid, 256, SMEM02>>>(Qp0, Qp1, Kp0, Kp1, maskf, S16, Tmax,
                                           DIM, DIM,
                                           (long long)SQL * DIM, (long long)SQL * DIM,
                                           (long long)SKL * DIM, (long long)SKL * DIM,
                                           SKL,
                                           DIM, SKL, (long long)SQL * SKL, 0);
    }

    // softmax rows -> single fp16 P
    softmax_rows<<<BATCH * SQL, 256>>>(S16, Tmax, P0);

    // out = P0 @ Vp0  (batched, single product)
    {
        dim3 grid(DIM / 128, SQL / 128, BATCH);
        mma_gemm<3><<<grid, 256, SMEM3>>>(P0, P0, Vp0, Vp0, nullptr, out, nullptr,
                                          SKL, DIM,
                                          (long long)SQL * SKL, (long long)SQL * SKL,
                                          (long long)SKL * DIM, (long long)SKL * DIM,
                                          0,
                                          SKL, DIM, (long long)SQL * DIM, 0);
    }
}